// round 12
// baseline (speedup 1.0000x reference)
#include <cuda_runtime.h>
#include <cuda_fp16.h>
#include <math.h>
#include <stdint.h>

// Problem constants
#define LAYERS 6
#define NHEAD  16
#define DMODEL 1024
#define HDIM   64
#define BATCH  2
#define SEQ    1024
#define NTOK   (BATCH*SEQ)     // 2048
#define VOCAB  50257
#define NVTILE ((VOCAB+127)/128)     // 393
#define PCOLS  (NVTILE*4)            // 1572 loss partials per row

// ---------------- scratch ----------------------------------------------------
__device__ float  g_x   [NTOK*DMODEL];
__device__ __half g_h   [NTOK*DMODEL];
__device__ float  g_qkv [NTOK*3*DMODEL];
__device__ __half g_att [NTOK*DMODEL];
__device__ __half g_ffn [NTOK*4*DMODEL];
__device__ float  g_part[2*(size_t)NTOK*DMODEL];    // split-K partials (proj/fcp)
__device__ float  g_logits_fallback[(size_t)NTOK*VOCAB];
__device__ float  g_rowloss[NTOK];
__device__ float  g_pm[(size_t)NTOK*PCOLS];
__device__ float  g_ps[(size_t)NTOK*PCOLS];
// fp16 weight copies (converted once per launch)
__device__ __half g_wq [(size_t)LAYERS*3*DMODEL*DMODEL];
__device__ __half g_wp [(size_t)LAYERS*DMODEL*DMODEL];
__device__ __half g_wf [(size_t)LAYERS*4*DMODEL*DMODEL];
__device__ __half g_wf2[(size_t)LAYERS*DMODEL*4*DMODEL];
__device__ __half g_wv [(size_t)VOCAB*DMODEL];

// ---------------- PTX helpers (sm_80-portable only) --------------------------
__device__ __forceinline__ uint32_t smem_to_u32(const void* p) {
    uint32_t a;
    asm("{ .reg .u64 t; cvta.to.shared.u64 t, %1; cvt.u32.u64 %0, t; }" : "=r"(a) : "l"(p));
    return a;
}
__device__ __forceinline__ void cp_async16(uint32_t dst, const void* src, int srcsize) {
    asm volatile("cp.async.cg.shared.global [%0], [%1], 16, %2;\n"
                 :: "r"(dst), "l"(src), "r"(srcsize) : "memory");
}
#define CP_COMMIT() asm volatile("cp.async.commit_group;" ::: "memory")

#define LDSM_X4(r, a) \
    asm volatile("ldmatrix.sync.aligned.m8n8.x4.shared.b16 {%0,%1,%2,%3}, [%4];" \
        : "=r"((r)[0]), "=r"((r)[1]), "=r"((r)[2]), "=r"((r)[3]) : "r"(a))

// fp16 MMA: m16n8k16, fp32 accumulate
#define MMA_F16(d, a, b) \
    asm volatile("mma.sync.aligned.m16n8k16.row.col.f32.f16.f16.f32 " \
        "{%0,%1,%2,%3}, {%4,%5,%6,%7}, {%8,%9}, {%0,%1,%2,%3};" \
        : "+f"((d)[0]), "+f"((d)[1]), "+f"((d)[2]), "+f"((d)[3]) \
        : "r"((a)[0]), "r"((a)[1]), "r"((a)[2]), "r"((a)[3]), "r"((b)[0]), "r"((b)[1]))

// tf32 MMA (attention keeps this path)
#define MMA_TF32(d, a, b) \
    asm volatile("mma.sync.aligned.m16n8k8.row.col.f32.tf32.tf32.f32 " \
        "{%0,%1,%2,%3}, {%4,%5,%6,%7}, {%8,%9}, {%0,%1,%2,%3};" \
        : "+f"((d)[0]), "+f"((d)[1]), "+f"((d)[2]), "+f"((d)[3]) \
        : "r"((a)[0]), "r"((a)[1]), "r"((a)[2]), "r"((a)[3]), "r"((b)[0]), "r"((b)[1]))

__device__ __forceinline__ float tf32r(float x) {
    uint32_t y;
    asm("cvt.rna.tf32.f32 %0, %1;" : "=r"(y) : "f"(x));
    return __uint_as_float(y);
}

// MUFU-free exp: magic-number 2^n split + deg-5 poly (all FMA pipe).
__device__ __forceinline__ float fast_exp(float x) {
    x = fmaxf(x, -87.0f);
    float f = fminf(x * 1.44269504088896341f, 126.0f);
    float t = f + 12582912.0f;
    int bits = __float_as_int(t);
    int n = (bits & 0x007FFFFF) - 0x00400000;
    float r = f - (t - 12582912.0f);
    float p = 1.33335581e-3f;
    p = p * r + 9.61812911e-3f;
    p = p * r + 5.55041087e-2f;
    p = p * r + 2.40226507e-1f;
    p = p * r + 6.93147181e-1f;
    p = p * r + 1.0f;
    return p * __int_as_float((n + 127) << 23);
}

// ---------------- fp16 mma.sync NT GEMM: C[M,N] = A[M,K]*B[N,K]^T (+epi) -----
// CTA tile 128x128, 8 warps 2x4, warp tile 64x32, BK=64 halfs, 3-stage cp.async.
// A,B fp16; accumulate fp32. SWAP=1: x=M-tiles, y=N-tiles.
// gridDim.z>1: split-K; EPI_PART writes raw fp32 partials at C + z*M*N.
enum { EPI_NONE = 0, EPI_GELU = 1, EPI_LOSS = 3, EPI_PART = 4 };

#define GBM 128
#define GBK 64
#define GSTAGES 3
#define GSTAGE_BYTES (GBM*GBK*2)                 // 16384
#define GT_SMEM (1024 + 2*GSTAGES*GSTAGE_BYTES)  // 99328

__device__ __forceinline__ uint32_t sw_off(int r, int c /*16B chunk 0..7*/) {
    return (uint32_t)(r * 128 + ((c ^ (r & 7)) << 4));
}

template<int EPI, int SWAP>
__global__ void __launch_bounds__(256, 2) gemm_tc(
    const __half* __restrict__ A, const __half* __restrict__ B,
    const float* __restrict__ bias,
    float* __restrict__ C, int M, int N, int K,
    float* __restrict__ Pm, float* __restrict__ Psum)
{
    extern __shared__ char dsm[];
    const int tid  = threadIdx.x;
    const int wid  = tid >> 5;
    const int lane = tid & 31;
    const int wm = wid >> 2;
    const int wn = wid & 3;
    const int bm = (SWAP ? blockIdx.x : blockIdx.y) * 128;
    const int bn = (SWAP ? blockIdx.y : blockIdx.x) * 128;
    const int ntile = SWAP ? blockIdx.y : blockIdx.x;

    uint32_t sbase = (smem_to_u32(dsm) + 1023u) & ~1023u;
    uint32_t aStage0 = sbase;
    uint32_t bStage0 = sbase + GSTAGES * GSTAGE_BYTES;

    const int T = K / (GBK * gridDim.z);
    const int koff = blockIdx.z * T * GBK;

    auto load_tile = [&](int kt, int slot) {
        int k0 = koff + kt * GBK;
        uint32_t aB = aStage0 + slot * GSTAGE_BYTES;
        uint32_t bB = bStage0 + slot * GSTAGE_BYTES;
        #pragma unroll
        for (int u = 0; u < 4; u++) {
            int f = tid + u * 256;
            int r = f >> 3, c = f & 7;
            cp_async16(aB + sw_off(r, c), A + (size_t)(bm + r) * K + k0 + c * 8, 16);
            int gb = bn + r;
            const __half* bsrc = B + (size_t)(gb < N ? gb : 0) * K + k0 + c * 8;
            cp_async16(bB + sw_off(r, c), bsrc, gb < N ? 16 : 0);
        }
        CP_COMMIT();
    };

    float acc[4][4][4];
    #pragma unroll
    for (int i = 0; i < 4; i++)
        #pragma unroll
        for (int j = 0; j < 4; j++)
            #pragma unroll
            for (int v = 0; v < 4; v++) acc[i][j][v] = 0.f;

    load_tile(0, 0);
    load_tile(1, 1);
    load_tile(2, 2);

    for (int kt = 0; kt < T; kt++) {
        if (kt < T - 2)       asm volatile("cp.async.wait_group 2;" ::: "memory");
        else if (kt == T - 2) asm volatile("cp.async.wait_group 1;" ::: "memory");
        else                  asm volatile("cp.async.wait_group 0;" ::: "memory");
        __syncthreads();

        int slot = kt % GSTAGES;
        uint32_t aS = aStage0 + slot * GSTAGE_BYTES;
        uint32_t bS = bStage0 + slot * GSTAGE_BYTES;

        #pragma unroll
        for (int kk = 0; kk < 4; kk++) {       // 4 x k16 per BK=64
            uint32_t af[4][4];
            uint32_t bf[4][2];
            #pragma unroll
            for (int mb = 0; mb < 4; mb++) {
                int row = wm * 64 + mb * 16 + (lane & 15);
                int chunk = kk * 2 + (lane >> 4);
                LDSM_X4(af[mb], aS + sw_off(row, chunk));
            }
            #pragma unroll
            for (int p = 0; p < 2; p++) {
                uint32_t r4[4];
                int n = wn * 32 + p * 16 + (lane & 7) + ((lane >> 4) << 3);
                int chunk = kk * 2 + ((lane >> 3) & 1);
                LDSM_X4(r4, bS + sw_off(n, chunk));
                bf[p*2  ][0] = r4[0]; bf[p*2  ][1] = r4[1];
                bf[p*2+1][0] = r4[2]; bf[p*2+1][1] = r4[3];
            }
            #pragma unroll
            for (int mb = 0; mb < 4; mb++)
                #pragma unroll
                for (int nb = 0; nb < 4; nb++)
                    MMA_F16(acc[mb][nb], af[mb], bf[nb]);
        }
        __syncthreads();
        if (kt + GSTAGES < T) load_tile(kt + GSTAGES, slot);
    }

    if (EPI == EPI_PART) {
        float* Cp = C + (size_t)blockIdx.z * M * (size_t)N;
        #pragma unroll
        for (int mb = 0; mb < 4; mb++) {
            int r0 = bm + wm * 64 + mb * 16 + (lane >> 2);
            #pragma unroll
            for (int nb = 0; nb < 4; nb++) {
                int col = bn + wn * 32 + nb * 8 + (lane & 3) * 2;
                #pragma unroll
                for (int half = 0; half < 2; half++) {
                    size_t row = (size_t)(r0 + half * 8);
                    *(float2*)(Cp + row * (size_t)N + col) =
                        make_float2(acc[mb][nb][half*2], acc[mb][nb][half*2 + 1]);
                }
            }
        }
        return;
    }

    if (EPI == EPI_LOSS) {
        #pragma unroll
        for (int mb = 0; mb < 4; mb++) {
            #pragma unroll
            for (int half = 0; half < 2; half++) {
                int rrow = bm + wm * 64 + mb * 16 + (lane >> 2) + half * 8;
                float vals[8];
                float vmax = -1e30f;
                #pragma unroll
                for (int nb = 0; nb < 4; nb++) {
                    int col = bn + wn * 32 + nb * 8 + (lane & 3) * 2;
                    float v0 = acc[mb][nb][half*2 + 0];
                    float v1 = acc[mb][nb][half*2 + 1];
                    size_t base = (size_t)rrow * N + col;
                    if (col + 1 < N) {
                        if ((base & 1) == 0) *(float2*)(C + base) = make_float2(v0, v1);
                        else { C[base] = v0; C[base + 1] = v1; }
                    } else if (col < N) {
                        C[base] = v0;
                    }
                    vals[nb*2    ] = (col     < N) ? v0 : -1e30f;
                    vals[nb*2 + 1] = (col + 1 < N) ? v1 : -1e30f;
                    vmax = fmaxf(vmax, fmaxf(vals[nb*2], vals[nb*2+1]));
                }
                vmax = fmaxf(vmax, __shfl_xor_sync(0xffffffffu, vmax, 1));
                vmax = fmaxf(vmax, __shfl_xor_sync(0xffffffffu, vmax, 2));
                float s = 0.f;
                #pragma unroll
                for (int j = 0; j < 8; j++) s += fast_exp(vals[j] - vmax);
                s += __shfl_xor_sync(0xffffffffu, s, 1);
                s += __shfl_xor_sync(0xffffffffu, s, 2);
                if ((lane & 3) == 0) {
                    size_t po = (size_t)rrow * PCOLS + ntile * 4 + wn;
                    Pm[po] = vmax;
                    Psum[po] = s;
                }
            }
        }
        return;
    }

    // EPI_NONE (fp32 out + bias) / EPI_GELU (fp16 out + bias)
    #pragma unroll
    for (int mb = 0; mb < 4; mb++) {
        int r0 = bm + wm * 64 + mb * 16 + (lane >> 2);
        #pragma unroll
        for (int nb = 0; nb < 4; nb++) {
            int col = bn + wn * 32 + nb * 8 + (lane & 3) * 2;
            #pragma unroll
            for (int half = 0; half < 2; half++) {
                size_t row = (size_t)(r0 + half * 8);
                float v0 = acc[mb][nb][half*2 + 0];
                float v1 = acc[mb][nb][half*2 + 1];
                size_t base = row * (size_t)N + col;
                if (col + 1 < N) {
                    if (bias) { v0 += bias[col]; v1 += bias[col+1]; }
                    if (EPI == EPI_GELU) {
                        v0 = 0.5f*v0*(1.0f + erff(v0*0.70710678118654752f));
                        v1 = 0.5f*v1*(1.0f + erff(v1*0.70710678118654752f));
                        *(__half2*)((__half*)C + base) = __floats2half2_rn(v0, v1);
                    } else {
                        if ((base & 1) == 0) {
                            *(float2*)(C + base) = make_float2(v0, v1);
                        } else {
                            C[base] = v0; C[base + 1] = v1;
                        }
                    }
                } else if (col < N) {
                    if (bias) v0 += bias[col];
                    if (EPI == EPI_GELU) {
                        v0 = 0.5f*v0*(1.0f + erff(v0*0.70710678118654752f));
                        ((__half*)C)[base] = __float2half_rn(v0);
                    } else {
                        C[base] = v0;
                    }
                }
            }
        }
    }
}

// ---------------- fp32 -> fp16 weight conversion ------------------------------
__global__ void __launch_bounds__(256) cvt_half_k(const float* __restrict__ src,
                                                  __half* __restrict__ dst, int n4)
{
    int i = blockIdx.x * 256 + threadIdx.x;
    if (i < n4) {
        float4 v = ((const float4*)src)[i];
        ((__half2*)dst)[i*2    ] = __floats2half2_rn(v.x, v.y);
        ((__half2*)dst)[i*2 + 1] = __floats2half2_rn(v.z, v.w);
    }
}

// ---------------- fused split-K reduce + residual + LayerNorm ----------------
// x += p0 + p1 + bias; h = fp16(LN(x) * w + b)
__global__ void __launch_bounds__(256) splitk_ln_k(
    const float* __restrict__ part, const float* __restrict__ bias,
    float* __restrict__ x,
    const float* __restrict__ lw, const float* __restrict__ lb,
    __half* __restrict__ h)
{
    int n = blockIdx.x;
    int i = threadIdx.x;
    float4 a = ((const float4*)(part + (size_t)n * DMODEL))[i];
    float4 b = ((const float4*)(part + (size_t)NTOK * DMODEL + (size_t)n * DMODEL))[i];
    float4 c = ((const float4*)bias)[i];
    float4 r = ((float4*)(x + (size_t)n * DMODEL))[i];
    float4 v = make_float4(a.x + b.x + c.x + r.x, a.y + b.y + c.y + r.y,
                           a.z + b.z + c.z + r.z, a.w + b.w + c.w + r.w);
    ((float4*)(x + (size_t)n * DMODEL))[i] = v;

    float s  = v.x + v.y + v.z + v.w;
    float ss = v.x*v.x + v.y*v.y + v.z*v.z + v.w*v.w;
    #pragma unroll
    for (int o = 16; o; o >>= 1) {
        s  += __shfl_xor_sync(0xffffffffu, s,  o);
        ss += __shfl_xor_sync(0xffffffffu, ss, o);
    }
    __shared__ float sm[8], sm2[8];
    int wid = i >> 5;
    if ((i & 31) == 0) { sm[wid] = s; sm2[wid] = ss; }
    __syncthreads();
    if (i < 32) {
        s  = (i < 8) ? sm [i] : 0.f;
        ss = (i < 8) ? sm2[i] : 0.f;
        #pragma unroll
        for (int o = 4; o; o >>= 1) {
            s  += __shfl_xor_sync(0xffffffffu, s,  o);
            ss += __shfl_xor_sync(0xffffffffu, ss, o);
        }
        if (i == 0) { sm[0] = s; sm2[0] = ss; }
    }
    __syncthreads();
    float mean = sm[0] * (1.0f/DMODEL);
    float var  = sm2[0] * (1.0f/DMODEL) - mean*mean;
    float inv  = rsqrtf(var + 1e-5f);
    float4 gw = ((const float4*)lw)[i];
    float4 gb = ((const float4*)lb)[i];
    __half* hrow = h + (size_t)n * DMODEL + i * 4;
    *(__half2*)(hrow    ) = __floats2half2_rn((v.x - mean)*inv*gw.x + gb.x,
                                              (v.y - mean)*inv*gw.y + gb.y);
    *(__half2*)(hrow + 2) = __floats2half2_rn((v.z - mean)*inv*gw.z + gb.z,
                                              (v.w - mean)*inv*gw.w + gb.w);
}

// ---------------- embedding --------------------------------------------------
__global__ void embed_k(const int* __restrict__ idx,
                        const float* __restrict__ wte,
                        const float* __restrict__ wpe,
                        float* __restrict__ x)
{
    int n = blockIdx.x;
    int tok = idx[n];
    int t = n % SEQ;
    const float4* a = (const float4*)(wte + (size_t)tok * DMODEL);
    const float4* p = (const float4*)(wpe + (size_t)t   * DMODEL);
    float4* o = (float4*)(x + (size_t)n * DMODEL);
    for (int i = threadIdx.x; i < DMODEL/4; i += blockDim.x) {
        float4 u = a[i], v = p[i];
        o[i] = make_float4(u.x+v.x, u.y+v.y, u.z+v.z, u.w+v.w);
    }
}

// ---------------- standalone layernorm (first ln1 only), fp16 out ------------
__global__ void __launch_bounds__(256) ln_k(const float* __restrict__ x,
                                            const float* __restrict__ w,
                                            const float* __restrict__ b,
                                            __half* __restrict__ out)
{
    int n = blockIdx.x;
    const float* row = x + (size_t)n * DMODEL;
    int i = threadIdx.x;
    float4 v = ((const float4*)row)[i];
    float s  = v.x + v.y + v.z + v.w;
    float ss = v.x*v.x + v.y*v.y + v.z*v.z + v.w*v.w;
    #pragma unroll
    for (int o = 16; o; o >>= 1) {
        s  += __shfl_xor_sync(0xffffffffu, s,  o);
        ss += __shfl_xor_sync(0xffffffffu, ss, o);
    }
    __shared__ float sm[8], sm2[8];
    int wid = i >> 5;
    if ((i & 31) == 0) { sm[wid] = s; sm2[wid] = ss; }
    __syncthreads();
    if (i < 32) {
        s  = (i < 8) ? sm [i] : 0.f;
        ss = (i < 8) ? sm2[i] : 0.f;
        #pragma unroll
        for (int o = 4; o; o >>= 1) {
            s  += __shfl_xor_sync(0xffffffffu, s,  o);
            ss += __shfl_xor_sync(0xffffffffu, ss, o);
        }
        if (i == 0) { sm[0] = s; sm2[0] = ss; }
    }
    __syncthreads();
    float mean = sm[0] * (1.0f/DMODEL);
    float var  = sm2[0] * (1.0f/DMODEL) - mean*mean;
    float inv  = rsqrtf(var + 1e-5f);
    float4 gw = ((const float4*)w)[i];
    float4 gb = ((const float4*)b)[i];
    __half* orow = out + (size_t)n * DMODEL + i * 4;
    *(__half2*)(orow    ) = __floats2half2_rn((v.x - mean)*inv*gw.x + gb.x,
                                              (v.y - mean)*inv*gw.y + gb.y);
    *(__half2*)(orow + 2) = __floats2half2_rn((v.z - mean)*inv*gw.z + gb.z,
                                              (v.w - mean)*inv*gw.w + gb.w);
}

// ---------------- tensor-core flash attention (tf32, fp32 qkv in, fp16 out) --
#define AT_KT 64
#define AT_SMEM 66560
#define PS_STRIDE 68

__device__ __forceinline__ uint32_t att_off(int r, int c /*16B chunk 0..15*/) {
    return (uint32_t)(r * 256 + ((c & 8) << 4) + (((c & 7) ^ (r & 7)) << 4));
}

__global__ void __launch_bounds__(128) attn_k(const float* __restrict__ qkv,
                                              __half* __restrict__ y)
{
    extern __shared__ float smf[];
    uint32_t qsB = smem_to_u32(smf);
    uint32_t ksB = qsB + 16384;
    uint32_t vtB = qsB + 32768;
    float* Ps = smf + 12288;

    const int bh = blockIdx.y;
    const int b = bh >> 4, h = bh & 15;
    const int q0 = (gridDim.x - 1 - blockIdx.x) * 64;
    const int tid = threadIdx.x, wid = tid >> 5, lane = tid & 31;
    const int wq = wid * 16;
    const int qtr = lane >> 2;
    const int qlc = lane & 3;

    #pragma unroll
    for (int u = 0; u < 8; u++) {
        int f = tid + u * 128;
        int r = f >> 4, c = f & 15;
        float4 v = *(const float4*)(qkv + (size_t)(b*SEQ + q0 + r)*3*DMODEL + h*HDIM + c*4);
        float4 w;
        w.x = tf32r(v.x * 0.125f); w.y = tf32r(v.y * 0.125f);
        w.z = tf32r(v.z * 0.125f); w.w = tf32r(v.w * 0.125f);
        *(float4*)((char*)smf + att_off(r, c)) = w;
    }

    float m0 = -1e30f, m1 = -1e30f, l0 = 0.f, l1 = 0.f;
    float o[8][4];
    #pragma unroll
    for (int nb = 0; nb < 8; nb++)
        #pragma unroll
        for (int v = 0; v < 4; v++) o[nb][v] = 0.f;

    const int row0 = q0 + wq + qtr;

    for (int k0 = 0; k0 < q0 + 64; k0 += AT_KT) {
        __syncthreads();
        #pragma unroll
        for (int u = 0; u < 8; u++) {
            int f = tid + u * 128;
            int r = f >> 4, c = f & 15;
            float4 v = *(const float4*)(qkv + (size_t)(b*SEQ + k0 + r)*3*DMODEL + DMODEL + h*HDIM + c*4);
            float4 w;
            w.x = tf32r(v.x); w.y = tf32r(v.y); w.z = tf32r(v.z); w.w = tf32r(v.w);
            *(float4*)((char*)smf + 16384 + att_off(r, c)) = w;
        }
        #pragma unroll
        for (int u = 0; u < 8; u++) {
            int f = tid + u * 128;
            int kt = f >> 4, c = f & 15;
            float4 v = *(const float4*)(qkv + (size_t)(b*SEQ + k0 + kt)*3*DMODEL + 2*DMODEL + h*HDIM + c*4);
            float vv[4] = {v.x, v.y, v.z, v.w};
            #pragma unroll
            for (int j = 0; j < 4; j++) {
                int d = c * 4 + j;
                *(float*)((char*)smf + 32768 + att_off(d, kt >> 2) + (kt & 3) * 4) = tf32r(vv[j]);
            }
        }
        __syncthreads();

        float sc[8][4];
        #pragma unroll
        for (int nb = 0; nb < 8; nb++)
            #pragma unroll
            for (int v = 0; v < 4; v++) sc[nb][v] = 0.f;

        #pragma unroll
        for (int ks8 = 0; ks8 < 8; ks8++) {
            uint32_t af[4];
            LDSM_X4(af, qsB + att_off(wq + (lane & 15), 2*ks8 + (lane >> 4)));
            #pragma unroll
            for (int g = 0; g < 4; g++) {
                uint32_t r4[4];
                int n = g * 16 + (lane & 7) + ((lane >> 4) << 3);
                int ch = 2*ks8 + ((lane >> 3) & 1);
                LDSM_X4(r4, ksB + att_off(n, ch));
                uint32_t b0[2] = {r4[0], r4[1]};
                uint32_t b1[2] = {r4[2], r4[3]};
                MMA_TF32(sc[g*2    ], af, b0);
                MMA_TF32(sc[g*2 + 1], af, b1);
            }
        }

        if (k0 + AT_KT - 1 > q0 + wq) {
            #pragma unroll
            for (int nb = 0; nb < 8; nb++) {
                int c0 = k0 + nb*8 + qlc*2;
                if (c0     > row0    ) sc[nb][0] = -1e30f;
                if (c0 + 1 > row0    ) sc[nb][1] = -1e30f;
                if (c0     > row0 + 8) sc[nb][2] = -1e30f;
                if (c0 + 1 > row0 + 8) sc[nb][3] = -1e30f;
            }
        }

        float mx0 = sc[0][0], mx1 = sc[0][2];
        #pragma unroll
        for (int nb = 0; nb < 8; nb++) {
            mx0 = fmaxf(mx0, fmaxf(sc[nb][0], sc[nb][1]));
            mx1 = fmaxf(mx1, fmaxf(sc[nb][2], sc[nb][3]));
        }
        mx0 = fmaxf(mx0, __shfl_xor_sync(0xffffffffu, mx0, 1));
        mx0 = fmaxf(mx0, __shfl_xor_sync(0xffffffffu, mx0, 2));
        mx1 = fmaxf(mx1, __shfl_xor_sync(0xffffffffu, mx1, 1));
        mx1 = fmaxf(mx1, __shfl_xor_sync(0xffffffffu, mx1, 2));
        float nm0 = fmaxf(m0, mx0), nm1 = fmaxf(m1, mx1);
        float corr0 = fast_exp(m0 - nm0), corr1 = fast_exp(m1 - nm1);
        float s0 = 0.f, s1 = 0.f;
        #pragma unroll
        for (int nb = 0; nb < 8; nb++) {
            sc[nb][0] = fast_exp(sc[nb][0] - nm0);
            sc[nb][1] = fast_exp(sc[nb][1] - nm0);
            sc[nb][2] = fast_exp(sc[nb][2] - nm1);
            sc[nb][3] = fast_exp(sc[nb][3] - nm1);
            s0 += sc[nb][0] + sc[nb][1];
            s1 += sc[nb][2] + sc[nb][3];
        }
        s0 += __shfl_xor_sync(0xffffffffu, s0, 1);
        s0 += __shfl_xor_sync(0xffffffffu, s0, 2);
        s1 += __shfl_xor_sync(0xffffffffu, s1, 1);
        s1 += __shfl_xor_sync(0xffffffffu, s1, 2);
        l0 = l0 * corr0 + s0;  m0 = nm0;
        l1 = l1 * corr1 + s1;  m1 = nm1;
        #pragma unroll
        for (int nb = 0; nb < 8; nb++) {
            o[nb][0] *= corr0; o[nb][1] *= corr0;
            o[nb][2] *= corr1; o[nb][3] *= corr1;
        }

        int pr = wq + qtr;
        #pragma unroll
        for (int nb = 0; nb < 8; nb++) {
            int pc = nb*8 + qlc*2;
            Ps[pr*PS_STRIDE + pc    ] = tf32r(sc[nb][0]);
            Ps[pr*PS_STRIDE + pc + 1] = tf32r(sc[nb][1]);
            Ps[(pr+8)*PS_STRIDE + pc    ] = tf32r(sc[nb][2]);
            Ps[(pr+8)*PS_STRIDE + pc + 1] = tf32r(sc[nb][3]);
        }
        __syncwarp();

        #pragma unroll
        for (int ks8 = 0; ks8 < 8; ks8++) {
            uint32_t pa[4];
            int pk = ks8*8 + qlc;
            pa[0] = __float_as_uint(Ps[(wq + qtr    )*PS_STRIDE + pk    ]);
            pa[1] = __float_as_uint(Ps[(wq + qtr + 8)*PS_STRIDE + pk    ]);
            pa[2] = __float_as_uint(Ps[(wq + qtr    )*PS_STRIDE + pk + 4]);
            pa[3] = __float_as_uint(Ps[(wq + qtr + 8)*PS_STRIDE + pk + 4]);
            #pragma unroll
            for (int g = 0; g < 4; g++) {
                uint32_t r4[4];
                int n = g * 16 + (lane & 7) + ((lane >> 4) << 3);
                int ch = 2*ks8 + ((lane >> 3) & 1);
                LDSM_X4(r4, vtB + att_off(n, ch));
                uint32_t b0[2] = {r4[0], r4[1]};
                uint32_t b1[2] = {r4[2], r4[3]};
                MMA_TF32(o[g*2    ], pa, b0);
                MMA_TF32(o[g*2 + 1], pa, b1);
            }
        }
        __syncwarp();
    }

    // fp16 output (feeds proj GEMM A)
    float inv0 = 1.0f / l0, inv1 = 1.0f / l1;
    size_t g0 = (size_t)(b*SEQ + q0 + wq + qtr) * DMODEL + h*HDIM;
    size_t g1 = g0 + 8 * DMODEL;
    #pragma unroll
    for (int nb = 0; nb < 8; nb++) {
        int d0 = nb*8 + qlc*2;
        *(__half2*)(y + g0 + d0) = __floats2half2_rn(o[nb][0]*inv0, o[nb][1]*inv0);
        *(__half2*)(y + g1 + d0) = __floats2half2_rn(o[nb][2]*inv1, o[nb][3]*inv1);
    }
}

// ---------------- loss reduce over fused partials ----------------------------
__global__ void __launch_bounds__(256) rowloss2_k(const float* __restrict__ pm,
                                                  const float* __restrict__ ps,
                                                  const float* __restrict__ logits,
                                                  const int* __restrict__ tgt,
                                                  float* __restrict__ rowloss)
{
    int n = blockIdx.x;
    const float* rm = pm + (size_t)n * PCOLS;
    const float* rs = ps + (size_t)n * PCOLS;
    float m = -1e30f, ssum = 0.f;
    for (int i = threadIdx.x; i < PCOLS; i += 256) {
        float m2 = rm[i], s2 = rs[i];
        float M = fmaxf(m, m2);
        ssum = ssum*fast_exp(m - M) + s2*fast_exp(m2 - M);
        m = M;
    }
    #pragma unroll
    for (int o = 16; o; o >>= 1) {
        float m2 = __shfl_xor_sync(0xffffffffu, m, o);
        float s2 = __shfl_xor_sync(0xffffffffu, ssum, o);
        float M  = fmaxf(m, m2);
        ssum = ssum*fast_exp(m - M) + s2*fast_exp(m2 - M);
        m = M;
    }
    __shared__ float smm[8], sms[8];
    int wid = threadIdx.x >> 5;
    if ((threadIdx.x & 31) == 0) { smm[wid] = m; sms[wid] = ssum; }
    __syncthreads();
    if (threadIdx.x == 0) {
        float M = smm[0], S = sms[0];
        for (int i = 1; i < 8; i++) {
            float M2 = fmaxf(M, smm[i]);
            S = S*fast_exp(M - M2) + sms[i]*fast_exp(smm[i] - M2);
            M = M2;
        }
        float lse = M + logf(S);
        rowloss[n] = lse - logits[(size_t)n * VOCAB + tgt[n]];
    }
}

__global__ void finalize_k(const float* __restrict__ rowloss, float* __restrict__ out_loss)
{
    float s = 0.f;
    for (int i = threadIdx.x; i < NTOK; i += 256) s += rowloss[i];
    #pragma unroll
    for (int o = 16; o; o >>= 1) s += __shfl_xor_sync(0xffffffffu, s, o);
    __shared__ float sm[8];
    int wid = threadIdx.x >> 5;
    if ((threadIdx.x & 31) == 0) sm[wid] = s;
    __syncthreads();
    if (threadIdx.x == 0) {
        float t = 0.f;
        for (int i = 0; i < 8; i++) t += sm[i];
        *out_loss = t * (1.0f/NTOK);
    }
}

// ---------------- launch -----------------------------------------------------
extern "C" void kernel_launch(void* const* d_in, const int* in_sizes, int n_in,
                              void* d_out, int out_size)
{
    const int*   idx     = (const int*)  d_in[0];
    const int*   targets = (const int*)  d_in[1];
    const float* wte     = (const float*)d_in[2];
    const float* wpe     = (const float*)d_in[3];
    const float* ln1_w   = (const float*)d_in[4];
    const float* ln1_b   = (const float*)d_in[5];
    const float* attn_w  = (const float*)d_in[6];
    const float* attn_b  = (const float*)d_in[7];
    const float* proj_w  = (const float*)d_in[8];
    const float* proj_b  = (const float*)d_in[9];
    const float* ln2_w   = (const float*)d_in[10];
    const float* ln2_b   = (const float*)d_in[11];
    const float* fc_w    = (const float*)d_in[12];
    const float* fc_b    = (const float*)d_in[13];
    const float* fcp_w   = (const float*)d_in[14];
    const float* fcp_b   = (const float*)d_in[15];
    const float* lnf_w   = (const float*)d_in[16];
    const float* lnf_b   = (const float*)d_in[17];

    float *px, *pqkv, *ppart, *plogfb, *prl, *ppm, *pps;
    __half *ph, *patt, *pffn, *pwq, *pwp, *pwf, *pwf2, *pwv;
    cudaGetSymbolAddress((void**)&px,    g_x);
    cudaGetSymbolAddress((void**)&ph,    g_h);
    cudaGetSymbolAddress((void**)&pqkv,  g_qkv);
    cudaGetSymbolAddress((void**)&patt,  g_att);
    cudaGetSymbolAddress((void**)&pffn,  g_ffn);
    cudaGetSymbolAddress((void**)&ppart, g_part);
    cudaGetSymbolAddress((void**)&plogfb,g_logits_fallback);
    cudaGetSymbolAddress((void**)&prl,   g_rowloss);
    cudaGetSymbolAddress((void**)&ppm,   g_pm);
    cudaGetSymbolAddress((void**)&pps,   g_ps);
    cudaGetSymbolAddress((void**)&pwq,   g_wq);
    cudaGetSymbolAddress((void**)&pwp,   g_wp);
    cudaGetSymbolAddress((void**)&pwf,   g_wf);
    cudaGetSymbolAddress((void**)&pwf2,  g_wf2);
    cudaGetSymbolAddress((void**)&pwv,   g_wv);

    static bool attr_done = false;
    if (!attr_done) {
        cudaFuncSetAttribute((const void*)gemm_tc<EPI_NONE,0>,  cudaFuncAttributeMaxDynamicSharedMemorySize, GT_SMEM);
        cudaFuncSetAttribute((const void*)gemm_tc<EPI_GELU,0>,  cudaFuncAttributeMaxDynamicSharedMemorySize, GT_SMEM);
        cudaFuncSetAttribute((const void*)gemm_tc<EPI_PART,0>,  cudaFuncAttributeMaxDynamicSharedMemorySize, GT_SMEM);
        cudaFuncSetAttribute((const void*)gemm_tc<EPI_LOSS,1>,  cudaFuncAttributeMaxDynamicSharedMemorySize, GT_SMEM);
        cudaFuncSetAttribute((const void*)attn_k, cudaFuncAttributeMaxDynamicSharedMemorySize, AT_SMEM);
        attr_done = true;
    }

    const long long LOGN = (long long)NTOK * VOCAB;
    float* logits_ptr;
    float* loss_ptr = nullptr;
    if ((long long)out_size >= LOGN) {
        logits_ptr = (float*)d_out;
        if ((long long)out_size > LOGN) loss_ptr = (float*)d_out + LOGN;
    } else {
        logits_ptr = plogfb;
        loss_ptr = (float*)d_out;
    }

    // weight fp32->fp16 conversion (per launch; ~130us at HBM)
    {
        long long nq  = (long long)LAYERS*3*DMODEL*DMODEL/4;
        long long np  = (long long)LAYERS*DMODEL*DMODEL/4;
        long long nf  = (long long)LAYERS*4*DMODEL*DMODEL/4;
        long long nv  = (long long)VOCAB*DMODEL/4;
        cvt_half_k<<<(int)((nq+255)/256), 256>>>(attn_w, pwq, (int)nq);
        cvt_half_k<<<(int)((np+255)/256), 256>>>(proj_w, pwp, (int)np);
        cvt_half_k<<<(int)((nf+255)/256), 256>>>(fc_w,  pwf,  (int)nf);
        cvt_half_k<<<(int)((nf+255)/256), 256>>>(fcp_w, pwf2, (int)nf);
        cvt_half_k<<<(int)((nv+255)/256), 256>>>(wte,   pwv,  (int)nv);
    }

    embed_k<<<NTOK, 256>>>(idx, wte, wpe, px);
    ln_k<<<NTOK, 256>>>(px, ln1_w, ln1_b, ph);

    dim3 gq (3*DMODEL/128, NTOK/128);       // 24 x 16
    dim3 gp2(DMODEL/128,   NTOK/128, 2);    //  8 x 16 x 2 (split-K)
    dim3 gf (4*DMODEL/128, NTOK/128);       // 32 x 16
    dim3 gv (NTOK/128, NVTILE);             // SWAP: x=M-tiles, y=N-tiles
    dim3 ga (SEQ/64, BATCH*NHEAD);

    for (int l = 0; l < LAYERS; l++) {
        gemm_tc<EPI_NONE,0><<<gq, 256, GT_SMEM>>>(ph, pwq + (size_t)l*3*DMODEL*DMODEL,
                                       attn_b + (size_t)l*3*DMODEL,
                                       pqkv, NTOK, 3*DMODEL, DMODEL, nullptr, nullptr);
        attn_k<<<ga, 128, AT_SMEM>>>(pqkv, patt);
        gemm_tc<EPI_PART,0><<<gp2, 256, GT_SMEM>>>(patt, pwp + (size_t)l*DMODEL*DMODEL,
                                        nullptr,
                                        ppart, NTOK, DMODEL, DMODEL, nullptr, nullptr);
        splitk_ln_k<<<NTOK, 256>>>(ppart, proj_b + (size_t)l*DMODEL, px,
                                   ln2_w + (size_t)l*DMODEL, ln2_b + (size_t)l*DMODEL, ph);
        gemm_tc<EPI_GELU,0><<<gf, 256, GT_SMEM>>>(ph, pwf + (size_t)l*4*DMODEL*DMODEL,
                                       fc_b + (size_t)l*4*DMODEL,
                                       (float*)pffn, NTOK, 4*DMODEL, DMODEL, nullptr, nullptr);
        gemm_tc<EPI_PART,0><<<gp2, 256, GT_SMEM>>>(pffn, pwf2 + (size_t)l*DMODEL*4*DMODEL,
                                        nullptr,
                                        ppart, NTOK, DMODEL, 4*DMODEL, nullptr, nullptr);
        const float* nw = (l + 1 < LAYERS) ? ln1_w + (size_t)(l+1)*DMODEL : lnf_w;
        const float* nb = (l + 1 < LAYERS) ? ln1_b + (size_t)(l+1)*DMODEL : lnf_b;
        splitk_ln_k<<<NTOK, 256>>>(ppart, fcp_b + (size_t)l*DMODEL, px, nw, nb, ph);
    }

    gemm_tc<EPI_LOSS,1><<<gv, 256, GT_SMEM>>>(ph, pwv, nullptr,
                                   logits_ptr, NTOK, VOCAB, DMODEL, ppm, pps);

    if (loss_ptr) {
        rowloss2_k<<<NTOK, 256>>>(ppm, pps, logits_ptr, targets, prl);
        finalize_k<<<1, 256>>>(prl, loss_ptr);
    }
}

// round 13
// speedup vs baseline: 1.0015x; 1.0015x over previous
#include <cuda_runtime.h>
#include <cuda_fp16.h>
#include <math.h>
#include <stdint.h>

// Problem constants
#define LAYERS 6
#define NHEAD  16
#define DMODEL 1024
#define HDIM   64
#define BATCH  2
#define SEQ    1024
#define NTOK   (BATCH*SEQ)     // 2048
#define VOCAB  50257
#define NVTILE ((VOCAB+127)/128)     // 393
#define PCOLS  (NVTILE*4)            // 1572 loss partials per row

// ---------------- scratch ----------------------------------------------------
__device__ float  g_x   [NTOK*DMODEL];
__device__ __half g_h   [NTOK*DMODEL];
__device__ float  g_qkv [NTOK*3*DMODEL];
__device__ __half g_att [NTOK*DMODEL];
__device__ __half g_ffn [NTOK*4*DMODEL];
__device__ float  g_part[2*(size_t)NTOK*DMODEL];    // split-K partials (proj/fcp)
__device__ float  g_logits_fallback[(size_t)NTOK*VOCAB];
__device__ float  g_rowloss[NTOK];
__device__ float  g_pm[(size_t)NTOK*PCOLS];
__device__ float  g_ps[(size_t)NTOK*PCOLS];
// fp16 weight copies (converted once per launch)
__device__ __half g_wq [(size_t)LAYERS*3*DMODEL*DMODEL];
__device__ __half g_wp [(size_t)LAYERS*DMODEL*DMODEL];
__device__ __half g_wf [(size_t)LAYERS*4*DMODEL*DMODEL];
__device__ __half g_wf2[(size_t)LAYERS*DMODEL*4*DMODEL];
__device__ __half g_wv [(size_t)VOCAB*DMODEL];

// ---------------- PTX helpers (sm_80-portable only) --------------------------
__device__ __forceinline__ uint32_t smem_to_u32(const void* p) {
    uint32_t a;
    asm("{ .reg .u64 t; cvta.to.shared.u64 t, %1; cvt.u32.u64 %0, t; }" : "=r"(a) : "l"(p));
    return a;
}
__device__ __forceinline__ void cp_async16(uint32_t dst, const void* src, int srcsize) {
    asm volatile("cp.async.cg.shared.global [%0], [%1], 16, %2;\n"
                 :: "r"(dst), "l"(src), "r"(srcsize) : "memory");
}
#define CP_COMMIT() asm volatile("cp.async.commit_group;" ::: "memory")

#define LDSM_X4(r, a) \
    asm volatile("ldmatrix.sync.aligned.m8n8.x4.shared.b16 {%0,%1,%2,%3}, [%4];" \
        : "=r"((r)[0]), "=r"((r)[1]), "=r"((r)[2]), "=r"((r)[3]) : "r"(a))

// fp16 MMA: m16n8k16, fp32 accumulate
#define MMA_F16(d, a, b) \
    asm volatile("mma.sync.aligned.m16n8k16.row.col.f32.f16.f16.f32 " \
        "{%0,%1,%2,%3}, {%4,%5,%6,%7}, {%8,%9}, {%0,%1,%2,%3};" \
        : "+f"((d)[0]), "+f"((d)[1]), "+f"((d)[2]), "+f"((d)[3]) \
        : "r"((a)[0]), "r"((a)[1]), "r"((a)[2]), "r"((a)[3]), "r"((b)[0]), "r"((b)[1]))

// tf32 MMA (attention keeps this path)
#define MMA_TF32(d, a, b) \
    asm volatile("mma.sync.aligned.m16n8k8.row.col.f32.tf32.tf32.f32 " \
        "{%0,%1,%2,%3}, {%4,%5,%6,%7}, {%8,%9}, {%0,%1,%2,%3};" \
        : "+f"((d)[0]), "+f"((d)[1]), "+f"((d)[2]), "+f"((d)[3]) \
        : "r"((a)[0]), "r"((a)[1]), "r"((a)[2]), "r"((a)[3]), "r"((b)[0]), "r"((b)[1]))

__device__ __forceinline__ float tf32r(float x) {
    uint32_t y;
    asm("cvt.rna.tf32.f32 %0, %1;" : "=r"(y) : "f"(x));
    return __uint_as_float(y);
}

// MUFU-free exp: magic-number 2^n split + deg-5 poly (all FMA pipe).
__device__ __forceinline__ float fast_exp(float x) {
    x = fmaxf(x, -87.0f);
    float f = fminf(x * 1.44269504088896341f, 126.0f);
    float t = f + 12582912.0f;
    int bits = __float_as_int(t);
    int n = (bits & 0x007FFFFF) - 0x00400000;
    float r = f - (t - 12582912.0f);
    float p = 1.33335581e-3f;
    p = p * r + 9.61812911e-3f;
    p = p * r + 5.55041087e-2f;
    p = p * r + 2.40226507e-1f;
    p = p * r + 6.93147181e-1f;
    p = p * r + 1.0f;
    return p * __int_as_float((n + 127) << 23);
}

// ---------------- fp16 mma.sync NT GEMM: C[M,N] = A[M,K]*B[N,K]^T (+epi) -----
// CTA tile 128x128, 8 warps 2x4, warp tile 64x32, BK=64 halfs, 3-stage cp.async.
// A,B fp16; accumulate fp32. SWAP=1: x=M-tiles, y=N-tiles.
// gridDim.z>1: split-K; EPI_PART writes raw fp32 partials at C + z*M*N.
enum { EPI_NONE = 0, EPI_GELU = 1, EPI_LOSS = 3, EPI_PART = 4 };

#define GBM 128
#define GBK 64
#define GSTAGES 3
#define GSTAGE_BYTES (GBM*GBK*2)                 // 16384
#define GT_SMEM (1024 + 2*GSTAGES*GSTAGE_BYTES)  // 99328

__device__ __forceinline__ uint32_t sw_off(int r, int c /*16B chunk 0..7*/) {
    return (uint32_t)(r * 128 + ((c ^ (r & 7)) << 4));
}

template<int EPI, int SWAP>
__global__ void __launch_bounds__(256, 2) gemm_tc(
    const __half* __restrict__ A, const __half* __restrict__ B,
    const float* __restrict__ bias,
    float* __restrict__ C, int M, int N, int K,
    float* __restrict__ Pm, float* __restrict__ Psum)
{
    extern __shared__ char dsm[];
    const int tid  = threadIdx.x;
    const int wid  = tid >> 5;
    const int lane = tid & 31;
    const int wm = wid >> 2;
    const int wn = wid & 3;
    const int bm = (SWAP ? blockIdx.x : blockIdx.y) * 128;
    const int bn = (SWAP ? blockIdx.y : blockIdx.x) * 128;
    const int ntile = SWAP ? blockIdx.y : blockIdx.x;

    uint32_t sbase = (smem_to_u32(dsm) + 1023u) & ~1023u;
    uint32_t aStage0 = sbase;
    uint32_t bStage0 = sbase + GSTAGES * GSTAGE_BYTES;

    const int T = K / (GBK * gridDim.z);
    const int koff = blockIdx.z * T * GBK;

    auto load_tile = [&](int kt, int slot) {
        int k0 = koff + kt * GBK;
        uint32_t aB = aStage0 + slot * GSTAGE_BYTES;
        uint32_t bB = bStage0 + slot * GSTAGE_BYTES;
        #pragma unroll
        for (int u = 0; u < 4; u++) {
            int f = tid + u * 256;
            int r = f >> 3, c = f & 7;
            cp_async16(aB + sw_off(r, c), A + (size_t)(bm + r) * K + k0 + c * 8, 16);
            int gb = bn + r;
            const __half* bsrc = B + (size_t)(gb < N ? gb : 0) * K + k0 + c * 8;
            cp_async16(bB + sw_off(r, c), bsrc, gb < N ? 16 : 0);
        }
        CP_COMMIT();
    };

    float acc[4][4][4];
    #pragma unroll
    for (int i = 0; i < 4; i++)
        #pragma unroll
        for (int j = 0; j < 4; j++)
            #pragma unroll
            for (int v = 0; v < 4; v++) acc[i][j][v] = 0.f;

    load_tile(0, 0);
    load_tile(1, 1);
    load_tile(2, 2);

    for (int kt = 0; kt < T; kt++) {
        if (kt < T - 2)       asm volatile("cp.async.wait_group 2;" ::: "memory");
        else if (kt == T - 2) asm volatile("cp.async.wait_group 1;" ::: "memory");
        else                  asm volatile("cp.async.wait_group 0;" ::: "memory");
        __syncthreads();

        int slot = kt % GSTAGES;
        uint32_t aS = aStage0 + slot * GSTAGE_BYTES;
        uint32_t bS = bStage0 + slot * GSTAGE_BYTES;

        #pragma unroll
        for (int kk = 0; kk < 4; kk++) {       // 4 x k16 per BK=64
            uint32_t af[4][4];
            uint32_t bf[4][2];
            #pragma unroll
            for (int mb = 0; mb < 4; mb++) {
                int row = wm * 64 + mb * 16 + (lane & 15);
                int chunk = kk * 2 + (lane >> 4);
                LDSM_X4(af[mb], aS + sw_off(row, chunk));
            }
            #pragma unroll
            for (int p = 0; p < 2; p++) {
                uint32_t r4[4];
                int n = wn * 32 + p * 16 + (lane & 7) + ((lane >> 4) << 3);
                int chunk = kk * 2 + ((lane >> 3) & 1);
                LDSM_X4(r4, bS + sw_off(n, chunk));
                bf[p*2  ][0] = r4[0]; bf[p*2  ][1] = r4[1];
                bf[p*2+1][0] = r4[2]; bf[p*2+1][1] = r4[3];
            }
            #pragma unroll
            for (int mb = 0; mb < 4; mb++)
                #pragma unroll
                for (int nb = 0; nb < 4; nb++)
                    MMA_F16(acc[mb][nb], af[mb], bf[nb]);
        }
        __syncthreads();
        if (kt + GSTAGES < T) load_tile(kt + GSTAGES, slot);
    }

    if (EPI == EPI_PART) {
        float* Cp = C + (size_t)blockIdx.z * M * (size_t)N;
        #pragma unroll
        for (int mb = 0; mb < 4; mb++) {
            int r0 = bm + wm * 64 + mb * 16 + (lane >> 2);
            #pragma unroll
            for (int nb = 0; nb < 4; nb++) {
                int col = bn + wn * 32 + nb * 8 + (lane & 3) * 2;
                #pragma unroll
                for (int half = 0; half < 2; half++) {
                    size_t row = (size_t)(r0 + half * 8);
                    *(float2*)(Cp + row * (size_t)N + col) =
                        make_float2(acc[mb][nb][half*2], acc[mb][nb][half*2 + 1]);
                }
            }
        }
        return;
    }

    if (EPI == EPI_LOSS) {
        #pragma unroll
        for (int mb = 0; mb < 4; mb++) {
            #pragma unroll
            for (int half = 0; half < 2; half++) {
                int rrow = bm + wm * 64 + mb * 16 + (lane >> 2) + half * 8;
                float vals[8];
                float vmax = -1e30f;
                #pragma unroll
                for (int nb = 0; nb < 4; nb++) {
                    int col = bn + wn * 32 + nb * 8 + (lane & 3) * 2;
                    float v0 = acc[mb][nb][half*2 + 0];
                    float v1 = acc[mb][nb][half*2 + 1];
                    size_t base = (size_t)rrow * N + col;
                    if (col + 1 < N) {
                        if ((base & 1) == 0) *(float2*)(C + base) = make_float2(v0, v1);
                        else { C[base] = v0; C[base + 1] = v1; }
                    } else if (col < N) {
                        C[base] = v0;
                    }
                    vals[nb*2    ] = (col     < N) ? v0 : -1e30f;
                    vals[nb*2 + 1] = (col + 1 < N) ? v1 : -1e30f;
                    vmax = fmaxf(vmax, fmaxf(vals[nb*2], vals[nb*2+1]));
                }
                vmax = fmaxf(vmax, __shfl_xor_sync(0xffffffffu, vmax, 1));
                vmax = fmaxf(vmax, __shfl_xor_sync(0xffffffffu, vmax, 2));
                float s = 0.f;
                #pragma unroll
                for (int j = 0; j < 8; j++) s += fast_exp(vals[j] - vmax);
                s += __shfl_xor_sync(0xffffffffu, s, 1);
                s += __shfl_xor_sync(0xffffffffu, s, 2);
                if ((lane & 3) == 0) {
                    size_t po = (size_t)rrow * PCOLS + ntile * 4 + wn;
                    Pm[po] = vmax;
                    Psum[po] = s;
                }
            }
        }
        return;
    }

    // EPI_NONE (fp32 out + bias) / EPI_GELU (fp16 out + bias)
    #pragma unroll
    for (int mb = 0; mb < 4; mb++) {
        int r0 = bm + wm * 64 + mb * 16 + (lane >> 2);
        #pragma unroll
        for (int nb = 0; nb < 4; nb++) {
            int col = bn + wn * 32 + nb * 8 + (lane & 3) * 2;
            #pragma unroll
            for (int half = 0; half < 2; half++) {
                size_t row = (size_t)(r0 + half * 8);
                float v0 = acc[mb][nb][half*2 + 0];
                float v1 = acc[mb][nb][half*2 + 1];
                size_t base = row * (size_t)N + col;
                if (col + 1 < N) {
                    if (bias) { v0 += bias[col]; v1 += bias[col+1]; }
                    if (EPI == EPI_GELU) {
                        v0 = 0.5f*v0*(1.0f + erff(v0*0.70710678118654752f));
                        v1 = 0.5f*v1*(1.0f + erff(v1*0.70710678118654752f));
                        *(__half2*)((__half*)C + base) = __floats2half2_rn(v0, v1);
                    } else {
                        if ((base & 1) == 0) {
                            *(float2*)(C + base) = make_float2(v0, v1);
                        } else {
                            C[base] = v0; C[base + 1] = v1;
                        }
                    }
                } else if (col < N) {
                    if (bias) v0 += bias[col];
                    if (EPI == EPI_GELU) {
                        v0 = 0.5f*v0*(1.0f + erff(v0*0.70710678118654752f));
                        ((__half*)C)[base] = __float2half_rn(v0);
                    } else {
                        C[base] = v0;
                    }
                }
            }
        }
    }
}

// ---------------- fp32 -> fp16 weight conversion ------------------------------
__global__ void __launch_bounds__(256) cvt_half_k(const float* __restrict__ src,
                                                  __half* __restrict__ dst, int n4)
{
    int i = blockIdx.x * 256 + threadIdx.x;
    if (i < n4) {
        float4 v = ((const float4*)src)[i];
        ((__half2*)dst)[i*2    ] = __floats2half2_rn(v.x, v.y);
        ((__half2*)dst)[i*2 + 1] = __floats2half2_rn(v.z, v.w);
    }
}

// ---------------- fused split-K reduce + residual + LayerNorm ----------------
// x += p0 + p1 + bias; h = fp16(LN(x) * w + b)
__global__ void __launch_bounds__(256) splitk_ln_k(
    const float* __restrict__ part, const float* __restrict__ bias,
    float* __restrict__ x,
    const float* __restrict__ lw, const float* __restrict__ lb,
    __half* __restrict__ h)
{
    int n = blockIdx.x;
    int i = threadIdx.x;
    float4 a = ((const float4*)(part + (size_t)n * DMODEL))[i];
    float4 b = ((const float4*)(part + (size_t)NTOK * DMODEL + (size_t)n * DMODEL))[i];
    float4 c = ((const float4*)bias)[i];
    float4 r = ((float4*)(x + (size_t)n * DMODEL))[i];
    float4 v = make_float4(a.x + b.x + c.x + r.x, a.y + b.y + c.y + r.y,
                           a.z + b.z + c.z + r.z, a.w + b.w + c.w + r.w);
    ((float4*)(x + (size_t)n * DMODEL))[i] = v;

    float s  = v.x + v.y + v.z + v.w;
    float ss = v.x*v.x + v.y*v.y + v.z*v.z + v.w*v.w;
    #pragma unroll
    for (int o = 16; o; o >>= 1) {
        s  += __shfl_xor_sync(0xffffffffu, s,  o);
        ss += __shfl_xor_sync(0xffffffffu, ss, o);
    }
    __shared__ float sm[8], sm2[8];
    int wid = i >> 5;
    if ((i & 31) == 0) { sm[wid] = s; sm2[wid] = ss; }
    __syncthreads();
    if (i < 32) {
        s  = (i < 8) ? sm [i] : 0.f;
        ss = (i < 8) ? sm2[i] : 0.f;
        #pragma unroll
        for (int o = 4; o; o >>= 1) {
            s  += __shfl_xor_sync(0xffffffffu, s,  o);
            ss += __shfl_xor_sync(0xffffffffu, ss, o);
        }
        if (i == 0) { sm[0] = s; sm2[0] = ss; }
    }
    __syncthreads();
    float mean = sm[0] * (1.0f/DMODEL);
    float var  = sm2[0] * (1.0f/DMODEL) - mean*mean;
    float inv  = rsqrtf(var + 1e-5f);
    float4 gw = ((const float4*)lw)[i];
    float4 gb = ((const float4*)lb)[i];
    __half* hrow = h + (size_t)n * DMODEL + i * 4;
    *(__half2*)(hrow    ) = __floats2half2_rn((v.x - mean)*inv*gw.x + gb.x,
                                              (v.y - mean)*inv*gw.y + gb.y);
    *(__half2*)(hrow + 2) = __floats2half2_rn((v.z - mean)*inv*gw.z + gb.z,
                                              (v.w - mean)*inv*gw.w + gb.w);
}

// ---------------- embedding --------------------------------------------------
__global__ void embed_k(const int* __restrict__ idx,
                        const float* __restrict__ wte,
                        const float* __restrict__ wpe,
                        float* __restrict__ x)
{
    int n = blockIdx.x;
    int tok = idx[n];
    int t = n % SEQ;
    const float4* a = (const float4*)(wte + (size_t)tok * DMODEL);
    const float4* p = (const float4*)(wpe + (size_t)t   * DMODEL);
    float4* o = (float4*)(x + (size_t)n * DMODEL);
    for (int i = threadIdx.x; i < DMODEL/4; i += blockDim.x) {
        float4 u = a[i], v = p[i];
        o[i] = make_float4(u.x+v.x, u.y+v.y, u.z+v.z, u.w+v.w);
    }
}

// ---------------- standalone layernorm (first ln1 only), fp16 out ------------
__global__ void __launch_bounds__(256) ln_k(const float* __restrict__ x,
                                            const float* __restrict__ w,
                                            const float* __restrict__ b,
                                            __half* __restrict__ out)
{
    int n = blockIdx.x;
    const float* row = x + (size_t)n * DMODEL;
    int i = threadIdx.x;
    float4 v = ((const float4*)row)[i];
    float s  = v.x + v.y + v.z + v.w;
    float ss = v.x*v.x + v.y*v.y + v.z*v.z + v.w*v.w;
    #pragma unroll
    for (int o = 16; o; o >>= 1) {
        s  += __shfl_xor_sync(0xffffffffu, s,  o);
        ss += __shfl_xor_sync(0xffffffffu, ss, o);
    }
    __shared__ float sm[8], sm2[8];
    int wid = i >> 5;
    if ((i & 31) == 0) { sm[wid] = s; sm2[wid] = ss; }
    __syncthreads();
    if (i < 32) {
        s  = (i < 8) ? sm [i] : 0.f;
        ss = (i < 8) ? sm2[i] : 0.f;
        #pragma unroll
        for (int o = 4; o; o >>= 1) {
            s  += __shfl_xor_sync(0xffffffffu, s,  o);
            ss += __shfl_xor_sync(0xffffffffu, ss, o);
        }
        if (i == 0) { sm[0] = s; sm2[0] = ss; }
    }
    __syncthreads();
    float mean = sm[0] * (1.0f/DMODEL);
    float var  = sm2[0] * (1.0f/DMODEL) - mean*mean;
    float inv  = rsqrtf(var + 1e-5f);
    float4 gw = ((const float4*)w)[i];
    float4 gb = ((const float4*)b)[i];
    __half* orow = out + (size_t)n * DMODEL + i * 4;
    *(__half2*)(orow    ) = __floats2half2_rn((v.x - mean)*inv*gw.x + gb.x,
                                              (v.y - mean)*inv*gw.y + gb.y);
    *(__half2*)(orow + 2) = __floats2half2_rn((v.z - mean)*inv*gw.z + gb.z,
                                              (v.w - mean)*inv*gw.w + gb.w);
}

// ---------------- tensor-core flash attention (tf32, fp32 qkv in, fp16 out) --
#define AT_KT 64
#define AT_SMEM 66560
#define PS_STRIDE 68

__device__ __forceinline__ uint32_t att_off(int r, int c /*16B chunk 0..15*/) {
    return (uint32_t)(r * 256 + ((c & 8) << 4) + (((c & 7) ^ (r & 7)) << 4));
}

__global__ void __launch_bounds__(128) attn_k(const float* __restrict__ qkv,
                                              __half* __restrict__ y)
{
    extern __shared__ float smf[];
    uint32_t qsB = smem_to_u32(smf);
    uint32_t ksB = qsB + 16384;
    uint32_t vtB = qsB + 32768;
    float* Ps = smf + 12288;

    const int bh = blockIdx.y;
    const int b = bh >> 4, h = bh & 15;
    const int q0 = (gridDim.x - 1 - blockIdx.x) * 64;
    const int tid = threadIdx.x, wid = tid >> 5, lane = tid & 31;
    const int wq = wid * 16;
    const int qtr = lane >> 2;
    const int qlc = lane & 3;

    #pragma unroll
    for (int u = 0; u < 8; u++) {
        int f = tid + u * 128;
        int r = f >> 4, c = f & 15;
        float4 v = *(const float4*)(qkv + (size_t)(b*SEQ + q0 + r)*3*DMODEL + h*HDIM + c*4);
        float4 w;
        w.x = tf32r(v.x * 0.125f); w.y = tf32r(v.y * 0.125f);
        w.z = tf32r(v.z * 0.125f); w.w = tf32r(v.w * 0.125f);
        *(float4*)((char*)smf + att_off(r, c)) = w;
    }

    float m0 = -1e30f, m1 = -1e30f, l0 = 0.f, l1 = 0.f;
    float o[8][4];
    #pragma unroll
    for (int nb = 0; nb < 8; nb++)
        #pragma unroll
        for (int v = 0; v < 4; v++) o[nb][v] = 0.f;

    const int row0 = q0 + wq + qtr;

    for (int k0 = 0; k0 < q0 + 64; k0 += AT_KT) {
        __syncthreads();
        #pragma unroll
        for (int u = 0; u < 8; u++) {
            int f = tid + u * 128;
            int r = f >> 4, c = f & 15;
            float4 v = *(const float4*)(qkv + (size_t)(b*SEQ + k0 + r)*3*DMODEL + DMODEL + h*HDIM + c*4);
            float4 w;
            w.x = tf32r(v.x); w.y = tf32r(v.y); w.z = tf32r(v.z); w.w = tf32r(v.w);
            *(float4*)((char*)smf + 16384 + att_off(r, c)) = w;
        }
        #pragma unroll
        for (int u = 0; u < 8; u++) {
            int f = tid + u * 128;
            int kt = f >> 4, c = f & 15;
            float4 v = *(const float4*)(qkv + (size_t)(b*SEQ + k0 + kt)*3*DMODEL + 2*DMODEL + h*HDIM + c*4);
            float vv[4] = {v.x, v.y, v.z, v.w};
            #pragma unroll
            for (int j = 0; j < 4; j++) {
                int d = c * 4 + j;
                *(float*)((char*)smf + 32768 + att_off(d, kt >> 2) + (kt & 3) * 4) = tf32r(vv[j]);
            }
        }
        __syncthreads();

        float sc[8][4];
        #pragma unroll
        for (int nb = 0; nb < 8; nb++)
            #pragma unroll
            for (int v = 0; v < 4; v++) sc[nb][v] = 0.f;

        #pragma unroll
        for (int ks8 = 0; ks8 < 8; ks8++) {
            uint32_t af[4];
            LDSM_X4(af, qsB + att_off(wq + (lane & 15), 2*ks8 + (lane >> 4)));
            #pragma unroll
            for (int g = 0; g < 4; g++) {
                uint32_t r4[4];
                int n = g * 16 + (lane & 7) + ((lane >> 4) << 3);
                int ch = 2*ks8 + ((lane >> 3) & 1);
                LDSM_X4(r4, ksB + att_off(n, ch));
                uint32_t b0[2] = {r4[0], r4[1]};
                uint32_t b1[2] = {r4[2], r4[3]};
                MMA_TF32(sc[g*2    ], af, b0);
                MMA_TF32(sc[g*2 + 1], af, b1);
            }
        }

        if (k0 + AT_KT - 1 > q0 + wq) {
            #pragma unroll
            for (int nb = 0; nb < 8; nb++) {
                int c0 = k0 + nb*8 + qlc*2;
                if (c0     > row0    ) sc[nb][0] = -1e30f;
                if (c0 + 1 > row0    ) sc[nb][1] = -1e30f;
                if (c0     > row0 + 8) sc[nb][2] = -1e30f;
                if (c0 + 1 > row0 + 8) sc[nb][3] = -1e30f;
            }
        }

        float mx0 = sc[0][0], mx1 = sc[0][2];
        #pragma unroll
        for (int nb = 0; nb < 8; nb++) {
            mx0 = fmaxf(mx0, fmaxf(sc[nb][0], sc[nb][1]));
            mx1 = fmaxf(mx1, fmaxf(sc[nb][2], sc[nb][3]));
        }
        mx0 = fmaxf(mx0, __shfl_xor_sync(0xffffffffu, mx0, 1));
        mx0 = fmaxf(mx0, __shfl_xor_sync(0xffffffffu, mx0, 2));
        mx1 = fmaxf(mx1, __shfl_xor_sync(0xffffffffu, mx1, 1));
        mx1 = fmaxf(mx1, __shfl_xor_sync(0xffffffffu, mx1, 2));
        float nm0 = fmaxf(m0, mx0), nm1 = fmaxf(m1, mx1);
        float corr0 = fast_exp(m0 - nm0), corr1 = fast_exp(m1 - nm1);
        float s0 = 0.f, s1 = 0.f;
        #pragma unroll
        for (int nb = 0; nb < 8; nb++) {
            sc[nb][0] = fast_exp(sc[nb][0] - nm0);
            sc[nb][1] = fast_exp(sc[nb][1] - nm0);
            sc[nb][2] = fast_exp(sc[nb][2] - nm1);
            sc[nb][3] = fast_exp(sc[nb][3] - nm1);
            s0 += sc[nb][0] + sc[nb][1];
            s1 += sc[nb][2] + sc[nb][3];
        }
        s0 += __shfl_xor_sync(0xffffffffu, s0, 1);
        s0 += __shfl_xor_sync(0xffffffffu, s0, 2);
        s1 += __shfl_xor_sync(0xffffffffu, s1, 1);
        s1 += __shfl_xor_sync(0xffffffffu, s1, 2);
        l0 = l0 * corr0 + s0;  m0 = nm0;
        l1 = l1 * corr1 + s1;  m1 = nm1;
        #pragma unroll
        for (int nb = 0; nb < 8; nb++) {
            o[nb][0] *= corr0; o[nb][1] *= corr0;
            o[nb][2] *= corr1; o[nb][3] *= corr1;
        }

        int pr = wq + qtr;
        #pragma unroll
        for (int nb = 0; nb < 8; nb++) {
            int pc = nb*8 + qlc*2;
            Ps[pr*PS_STRIDE + pc    ] = tf32r(sc[nb][0]);
            Ps[pr*PS_STRIDE + pc + 1] = tf32r(sc[nb][1]);
            Ps[(pr+8)*PS_STRIDE + pc    ] = tf32r(sc[nb][2]);
            Ps[(pr+8)*PS_STRIDE + pc + 1] = tf32r(sc[nb][3]);
        }
        __syncwarp();

        #pragma unroll
        for (int ks8 = 0; ks8 < 8; ks8++) {
            uint32_t pa[4];
            int pk = ks8*8 + qlc;
            pa[0] = __float_as_uint(Ps[(wq + qtr    )*PS_STRIDE + pk    ]);
            pa[1] = __float_as_uint(Ps[(wq + qtr + 8)*PS_STRIDE + pk    ]);
            pa[2] = __float_as_uint(Ps[(wq + qtr    )*PS_STRIDE + pk + 4]);
            pa[3] = __float_as_uint(Ps[(wq + qtr + 8)*PS_STRIDE + pk + 4]);
            #pragma unroll
            for (int g = 0; g < 4; g++) {
                uint32_t r4[4];
                int n = g * 16 + (lane & 7) + ((lane >> 4) << 3);
                int ch = 2*ks8 + ((lane >> 3) & 1);
                LDSM_X4(r4, vtB + att_off(n, ch));
                uint32_t b0[2] = {r4[0], r4[1]};
                uint32_t b1[2] = {r4[2], r4[3]};
                MMA_TF32(o[g*2    ], pa, b0);
                MMA_TF32(o[g*2 + 1], pa, b1);
            }
        }
        __syncwarp();
    }

    // fp16 output (feeds proj GEMM A)
    float inv0 = 1.0f / l0, inv1 = 1.0f / l1;
    size_t g0 = (size_t)(b*SEQ + q0 + wq + qtr) * DMODEL + h*HDIM;
    size_t g1 = g0 + 8 * DMODEL;
    #pragma unroll
    for (int nb = 0; nb < 8; nb++) {
        int d0 = nb*8 + qlc*2;
        *(__half2*)(y + g0 + d0) = __floats2half2_rn(o[nb][0]*inv0, o[nb][1]*inv0);
        *(__half2*)(y + g1 + d0) = __floats2half2_rn(o[nb][2]*inv1, o[nb][3]*inv1);
    }
}

// ---------------- loss reduce over fused partials ----------------------------
__global__ void __launch_bounds__(256) rowloss2_k(const float* __restrict__ pm,
                                                  const float* __restrict__ ps,
                                                  const float* __restrict__ logits,
                                                  const int* __restrict__ tgt,
                                                  float* __restrict__ rowloss)
{
    int n = blockIdx.x;
    const float* rm = pm + (size_t)n * PCOLS;
    const float* rs = ps + (size_t)n * PCOLS;
    float m = -1e30f, ssum = 0.f;
    for (int i = threadIdx.x; i < PCOLS; i += 256) {
        float m2 = rm[i], s2 = rs[i];
        float M = fmaxf(m, m2);
        ssum = ssum*fast_exp(m - M) + s2*fast_exp(m2 - M);
        m = M;
    }
    #pragma unroll
    for (int o = 16; o; o >>= 1) {
        float m2 = __shfl_xor_sync(0xffffffffu, m, o);
        float s2 = __shfl_xor_sync(0xffffffffu, ssum, o);
        float M  = fmaxf(m, m2);
        ssum = ssum*fast_exp(m - M) + s2*fast_exp(m2 - M);
        m = M;
    }
    __shared__ float smm[8], sms[8];
    int wid = threadIdx.x >> 5;
    if ((threadIdx.x & 31) == 0) { smm[wid] = m; sms[wid] = ssum; }
    __syncthreads();
    if (threadIdx.x == 0) {
        float M = smm[0], S = sms[0];
        for (int i = 1; i < 8; i++) {
            float M2 = fmaxf(M, smm[i]);
            S = S*fast_exp(M - M2) + sms[i]*fast_exp(smm[i] - M2);
            M = M2;
        }
        float lse = M + logf(S);
        rowloss[n] = lse - logits[(size_t)n * VOCAB + tgt[n]];
    }
}

__global__ void finalize_k(const float* __restrict__ rowloss, float* __restrict__ out_loss)
{
    float s = 0.f;
    for (int i = threadIdx.x; i < NTOK; i += 256) s += rowloss[i];
    #pragma unroll
    for (int o = 16; o; o >>= 1) s += __shfl_xor_sync(0xffffffffu, s, o);
    __shared__ float sm[8];
    int wid = threadIdx.x >> 5;
    if ((threadIdx.x & 31) == 0) sm[wid] = s;
    __syncthreads();
    if (threadIdx.x == 0) {
        float t = 0.f;
        for (int i = 0; i < 8; i++) t += sm[i];
        *out_loss = t * (1.0f/NTOK);
    }
}

// ---------------- launch -----------------------------------------------------
extern "C" void kernel_launch(void* const* d_in, const int* in_sizes, int n_in,
                              void* d_out, int out_size)
{
    const int*   idx     = (const int*)  d_in[0];
    const int*   targets = (const int*)  d_in[1];
    const float* wte     = (const float*)d_in[2];
    const float* wpe     = (const float*)d_in[3];
    const float* ln1_w   = (const float*)d_in[4];
    const float* ln1_b   = (const float*)d_in[5];
    const float* attn_w  = (const float*)d_in[6];
    const float* attn_b  = (const float*)d_in[7];
    const float* proj_w  = (const float*)d_in[8];
    const float* proj_b  = (const float*)d_in[9];
    const float* ln2_w   = (const float*)d_in[10];
    const float* ln2_b   = (const float*)d_in[11];
    const float* fc_w    = (const float*)d_in[12];
    const float* fc_b    = (const float*)d_in[13];
    const float* fcp_w   = (const float*)d_in[14];
    const float* fcp_b   = (const float*)d_in[15];
    const float* lnf_w   = (const float*)d_in[16];
    const float* lnf_b   = (const float*)d_in[17];

    float *px, *pqkv, *ppart, *plogfb, *prl, *ppm, *pps;
    __half *ph, *patt, *pffn, *pwq, *pwp, *pwf, *pwf2, *pwv;
    cudaGetSymbolAddress((void**)&px,    g_x);
    cudaGetSymbolAddress((void**)&ph,    g_h);
    cudaGetSymbolAddress((void**)&pqkv,  g_qkv);
    cudaGetSymbolAddress((void**)&patt,  g_att);
    cudaGetSymbolAddress((void**)&pffn,  g_ffn);
    cudaGetSymbolAddress((void**)&ppart, g_part);
    cudaGetSymbolAddress((void**)&plogfb,g_logits_fallback);
    cudaGetSymbolAddress((void**)&prl,   g_rowloss);
    cudaGetSymbolAddress((void**)&ppm,   g_pm);
    cudaGetSymbolAddress((void**)&pps,   g_ps);
    cudaGetSymbolAddress((void**)&pwq,   g_wq);
    cudaGetSymbolAddress((void**)&pwp,   g_wp);
    cudaGetSymbolAddress((void**)&pwf,   g_wf);
    cudaGetSymbolAddress((void**)&pwf2,  g_wf2);
    cudaGetSymbolAddress((void**)&pwv,   g_wv);

    static bool attr_done = false;
    if (!attr_done) {
        cudaFuncSetAttribute((const void*)gemm_tc<EPI_NONE,0>,  cudaFuncAttributeMaxDynamicSharedMemorySize, GT_SMEM);
        cudaFuncSetAttribute((const void*)gemm_tc<EPI_GELU,0>,  cudaFuncAttributeMaxDynamicSharedMemorySize, GT_SMEM);
        cudaFuncSetAttribute((const void*)gemm_tc<EPI_PART,0>,  cudaFuncAttributeMaxDynamicSharedMemorySize, GT_SMEM);
        cudaFuncSetAttribute((const void*)gemm_tc<EPI_LOSS,1>,  cudaFuncAttributeMaxDynamicSharedMemorySize, GT_SMEM);
        cudaFuncSetAttribute((const void*)attn_k, cudaFuncAttributeMaxDynamicSharedMemorySize, AT_SMEM);
        attr_done = true;
    }

    const long long LOGN = (long long)NTOK * VOCAB;
    float* logits_ptr;
    float* loss_ptr = nullptr;
    if ((long long)out_size >= LOGN) {
        logits_ptr = (float*)d_out;
        if ((long long)out_size > LOGN) loss_ptr = (float*)d_out + LOGN;
    } else {
        logits_ptr = plogfb;
        loss_ptr = (float*)d_out;
    }

    // weight fp32->fp16 conversion (per launch; ~130us at HBM)
    {
        long long nq  = (long long)LAYERS*3*DMODEL*DMODEL/4;
        long long np  = (long long)LAYERS*DMODEL*DMODEL/4;
        long long nf  = (long long)LAYERS*4*DMODEL*DMODEL/4;
        long long nv  = (long long)VOCAB*DMODEL/4;
        cvt_half_k<<<(int)((nq+255)/256), 256>>>(attn_w, pwq, (int)nq);
        cvt_half_k<<<(int)((np+255)/256), 256>>>(proj_w, pwp, (int)np);
        cvt_half_k<<<(int)((nf+255)/256), 256>>>(fc_w,  pwf,  (int)nf);
        cvt_half_k<<<(int)((nf+255)/256), 256>>>(fcp_w, pwf2, (int)nf);
        cvt_half_k<<<(int)((nv+255)/256), 256>>>(wte,   pwv,  (int)nv);
    }

    embed_k<<<NTOK, 256>>>(idx, wte, wpe, px);
    ln_k<<<NTOK, 256>>>(px, ln1_w, ln1_b, ph);

    dim3 gq (3*DMODEL/128, NTOK/128);       // 24 x 16
    dim3 gp2(DMODEL/128,   NTOK/128, 2);    //  8 x 16 x 2 (split-K)
    dim3 gf (4*DMODEL/128, NTOK/128);       // 32 x 16
    dim3 gv (NTOK/128, NVTILE);             // SWAP: x=M-tiles, y=N-tiles
    dim3 ga (SEQ/64, BATCH*NHEAD);

    for (int l = 0; l < LAYERS; l++) {
        gemm_tc<EPI_NONE,0><<<gq, 256, GT_SMEM>>>(ph, pwq + (size_t)l*3*DMODEL*DMODEL,
                                       attn_b + (size_t)l*3*DMODEL,
                                       pqkv, NTOK, 3*DMODEL, DMODEL, nullptr, nullptr);
        attn_k<<<ga, 128, AT_SMEM>>>(pqkv, patt);
        gemm_tc<EPI_PART,0><<<gp2, 256, GT_SMEM>>>(patt, pwp + (size_t)l*DMODEL*DMODEL,
                                        nullptr,
                                        ppart, NTOK, DMODEL, DMODEL, nullptr, nullptr);
        splitk_ln_k<<<NTOK, 256>>>(ppart, proj_b + (size_t)l*DMODEL, px,
                                   ln2_w + (size_t)l*DMODEL, ln2_b + (size_t)l*DMODEL, ph);
        gemm_tc<EPI_GELU,0><<<gf, 256, GT_SMEM>>>(ph, pwf + (size_t)l*4*DMODEL*DMODEL,
                                       fc_b + (size_t)l*4*DMODEL,
                                       (float*)pffn, NTOK, 4*DMODEL, DMODEL, nullptr, nullptr);
        gemm_tc<EPI_PART,0><<<gp2, 256, GT_SMEM>>>(pffn, pwf2 + (size_t)l*DMODEL*4*DMODEL,
                                        nullptr,
                                        ppart, NTOK, DMODEL, 4*DMODEL, nullptr, nullptr);
        const float* nw = (l + 1 < LAYERS) ? ln1_w + (size_t)(l+1)*DMODEL : lnf_w;
        const float* nb = (l + 1 < LAYERS) ? ln1_b + (size_t)(l+1)*DMODEL : lnf_b;
        splitk_ln_k<<<NTOK, 256>>>(ppart, fcp_b + (size_t)l*DMODEL, px, nw, nb, ph);
    }

    gemm_tc<EPI_LOSS,1><<<gv, 256, GT_SMEM>>>(ph, pwv, nullptr,
                                   logits_ptr, NTOK, VOCAB, DMODEL, ppm, pps);

    if (loss_ptr) {
        rowloss2_k<<<NTOK, 256>>>(ppm, pps, logits_ptr, targets, prl);
        finalize_k<<<1, 256>>>(prl, loss_ptr);
    }
}

// round 14
// speedup vs baseline: 1.0029x; 1.0014x over previous
#include <cuda_runtime.h>
#include <cuda_fp16.h>
#include <math.h>
#include <stdint.h>

// Problem constants
#define LAYERS 6
#define NHEAD  16
#define DMODEL 1024
#define HDIM   64
#define BATCH  2
#define SEQ    1024
#define NTOK   (BATCH*SEQ)     // 2048
#define VOCAB  50257
#define NVTILE ((VOCAB+127)/128)     // 393
#define PCOLS  (NVTILE*4)            // 1572 loss partials per row

// ---------------- scratch ----------------------------------------------------
__device__ float  g_x   [NTOK*DMODEL];
__device__ __half g_h   [NTOK*DMODEL];
__device__ float  g_qkv [NTOK*3*DMODEL];
__device__ __half g_att [NTOK*DMODEL];
__device__ __half g_ffn [NTOK*4*DMODEL];
__device__ float  g_part[2*(size_t)NTOK*DMODEL];    // split-K partials (proj/fcp)
__device__ float  g_logits_fallback[(size_t)NTOK*VOCAB];
__device__ float  g_rowloss[NTOK];
__device__ float  g_pm[(size_t)NTOK*PCOLS];
__device__ float  g_ps[(size_t)NTOK*PCOLS];
// fp16 weight copies (converted once per launch)
__device__ __half g_wq [(size_t)LAYERS*3*DMODEL*DMODEL];
__device__ __half g_wp [(size_t)LAYERS*DMODEL*DMODEL];
__device__ __half g_wf [(size_t)LAYERS*4*DMODEL*DMODEL];
__device__ __half g_wf2[(size_t)LAYERS*DMODEL*4*DMODEL];
__device__ __half g_wv [(size_t)VOCAB*DMODEL];

// ---------------- PTX helpers (sm_80-portable only) --------------------------
__device__ __forceinline__ uint32_t smem_to_u32(const void* p) {
    uint32_t a;
    asm("{ .reg .u64 t; cvta.to.shared.u64 t, %1; cvt.u32.u64 %0, t; }" : "=r"(a) : "l"(p));
    return a;
}
__device__ __forceinline__ void cp_async16(uint32_t dst, const void* src, int srcsize) {
    asm volatile("cp.async.cg.shared.global [%0], [%1], 16, %2;\n"
                 :: "r"(dst), "l"(src), "r"(srcsize) : "memory");
}
#define CP_COMMIT() asm volatile("cp.async.commit_group;" ::: "memory")

#define LDSM_X4(r, a) \
    asm volatile("ldmatrix.sync.aligned.m8n8.x4.shared.b16 {%0,%1,%2,%3}, [%4];" \
        : "=r"((r)[0]), "=r"((r)[1]), "=r"((r)[2]), "=r"((r)[3]) : "r"(a))

// fp16 MMA: m16n8k16, fp32 accumulate
#define MMA_F16(d, a, b) \
    asm volatile("mma.sync.aligned.m16n8k16.row.col.f32.f16.f16.f32 " \
        "{%0,%1,%2,%3}, {%4,%5,%6,%7}, {%8,%9}, {%0,%1,%2,%3};" \
        : "+f"((d)[0]), "+f"((d)[1]), "+f"((d)[2]), "+f"((d)[3]) \
        : "r"((a)[0]), "r"((a)[1]), "r"((a)[2]), "r"((a)[3]), "r"((b)[0]), "r"((b)[1]))

// tf32 MMA (attention keeps this path)
#define MMA_TF32(d, a, b) \
    asm volatile("mma.sync.aligned.m16n8k8.row.col.f32.tf32.tf32.f32 " \
        "{%0,%1,%2,%3}, {%4,%5,%6,%7}, {%8,%9}, {%0,%1,%2,%3};" \
        : "+f"((d)[0]), "+f"((d)[1]), "+f"((d)[2]), "+f"((d)[3]) \
        : "r"((a)[0]), "r"((a)[1]), "r"((a)[2]), "r"((a)[3]), "r"((b)[0]), "r"((b)[1]))

__device__ __forceinline__ float tf32r(float x) {
    uint32_t y;
    asm("cvt.rna.tf32.f32 %0, %1;" : "=r"(y) : "f"(x));
    return __uint_as_float(y);
}

// MUFU-free exp: magic-number 2^n split + deg-5 poly (all FMA pipe).
__device__ __forceinline__ float fast_exp(float x) {
    x = fmaxf(x, -87.0f);
    float f = fminf(x * 1.44269504088896341f, 126.0f);
    float t = f + 12582912.0f;
    int bits = __float_as_int(t);
    int n = (bits & 0x007FFFFF) - 0x00400000;
    float r = f - (t - 12582912.0f);
    float p = 1.33335581e-3f;
    p = p * r + 9.61812911e-3f;
    p = p * r + 5.55041087e-2f;
    p = p * r + 2.40226507e-1f;
    p = p * r + 6.93147181e-1f;
    p = p * r + 1.0f;
    return p * __int_as_float((n + 127) << 23);
}

// ---------------- fp16 mma.sync NT GEMM: C[M,N] = A[M,K]*B[N,K]^T (+epi) -----
// CTA tile 128x128, 8 warps 2x4, warp tile 64x32, BK=64 halfs, 3-stage cp.async.
// A,B fp16; accumulate fp32. SWAP=1: x=M-tiles, y=N-tiles.
// gridDim.z>1: split-K; EPI_PART writes raw fp32 partials at C + z*M*N.
enum { EPI_NONE = 0, EPI_GELU = 1, EPI_LOSS = 3, EPI_PART = 4 };

#define GBM 128
#define GBK 64
#define GSTAGES 3
#define GSTAGE_BYTES (GBM*GBK*2)                 // 16384
#define GT_SMEM (1024 + 2*GSTAGES*GSTAGE_BYTES)  // 99328

__device__ __forceinline__ uint32_t sw_off(int r, int c /*16B chunk 0..7*/) {
    return (uint32_t)(r * 128 + ((c ^ (r & 7)) << 4));
}

template<int EPI, int SWAP>
__global__ void __launch_bounds__(256, 2) gemm_tc(
    const __half* __restrict__ A, const __half* __restrict__ B,
    const float* __restrict__ bias,
    float* __restrict__ C, int M, int N, int K,
    float* __restrict__ Pm, float* __restrict__ Psum)
{
    extern __shared__ char dsm[];
    const int tid  = threadIdx.x;
    const int wid  = tid >> 5;
    const int lane = tid & 31;
    const int wm = wid >> 2;
    const int wn = wid & 3;
    const int bm = (SWAP ? blockIdx.x : blockIdx.y) * 128;
    const int bn = (SWAP ? blockIdx.y : blockIdx.x) * 128;
    const int ntile = SWAP ? blockIdx.y : blockIdx.x;

    uint32_t sbase = (smem_to_u32(dsm) + 1023u) & ~1023u;
    uint32_t aStage0 = sbase;
    uint32_t bStage0 = sbase + GSTAGES * GSTAGE_BYTES;

    const int T = K / (GBK * gridDim.z);
    const int koff = blockIdx.z * T * GBK;

    auto load_tile = [&](int kt, int slot) {
        int k0 = koff + kt * GBK;
        uint32_t aB = aStage0 + slot * GSTAGE_BYTES;
        uint32_t bB = bStage0 + slot * GSTAGE_BYTES;
        #pragma unroll
        for (int u = 0; u < 4; u++) {
            int f = tid + u * 256;
            int r = f >> 3, c = f & 7;
            cp_async16(aB + sw_off(r, c), A + (size_t)(bm + r) * K + k0 + c * 8, 16);
            int gb = bn + r;
            const __half* bsrc = B + (size_t)(gb < N ? gb : 0) * K + k0 + c * 8;
            cp_async16(bB + sw_off(r, c), bsrc, gb < N ? 16 : 0);
        }
        CP_COMMIT();
    };

    float acc[4][4][4];
    #pragma unroll
    for (int i = 0; i < 4; i++)
        #pragma unroll
        for (int j = 0; j < 4; j++)
            #pragma unroll
            for (int v = 0; v < 4; v++) acc[i][j][v] = 0.f;

    load_tile(0, 0);
    load_tile(1, 1);
    load_tile(2, 2);

    for (int kt = 0; kt < T; kt++) {
        if (kt < T - 2)       asm volatile("cp.async.wait_group 2;" ::: "memory");
        else if (kt == T - 2) asm volatile("cp.async.wait_group 1;" ::: "memory");
        else                  asm volatile("cp.async.wait_group 0;" ::: "memory");
        __syncthreads();

        int slot = kt % GSTAGES;
        uint32_t aS = aStage0 + slot * GSTAGE_BYTES;
        uint32_t bS = bStage0 + slot * GSTAGE_BYTES;

        #pragma unroll
        for (int kk = 0; kk < 4; kk++) {       // 4 x k16 per BK=64
            uint32_t af[4][4];
            uint32_t bf[4][2];
            #pragma unroll
            for (int mb = 0; mb < 4; mb++) {
                int row = wm * 64 + mb * 16 + (lane & 15);
                int chunk = kk * 2 + (lane >> 4);
                LDSM_X4(af[mb], aS + sw_off(row, chunk));
            }
            #pragma unroll
            for (int p = 0; p < 2; p++) {
                uint32_t r4[4];
                int n = wn * 32 + p * 16 + (lane & 7) + ((lane >> 4) << 3);
                int chunk = kk * 2 + ((lane >> 3) & 1);
                LDSM_X4(r4, bS + sw_off(n, chunk));
                bf[p*2  ][0] = r4[0]; bf[p*2  ][1] = r4[1];
                bf[p*2+1][0] = r4[2]; bf[p*2+1][1] = r4[3];
            }
            #pragma unroll
            for (int mb = 0; mb < 4; mb++)
                #pragma unroll
                for (int nb = 0; nb < 4; nb++)
                    MMA_F16(acc[mb][nb], af[mb], bf[nb]);
        }
        __syncthreads();
        if (kt + GSTAGES < T) load_tile(kt + GSTAGES, slot);
    }

    if (EPI == EPI_PART) {
        float* Cp = C + (size_t)blockIdx.z * M * (size_t)N;
        #pragma unroll
        for (int mb = 0; mb < 4; mb++) {
            int r0 = bm + wm * 64 + mb * 16 + (lane >> 2);
            #pragma unroll
            for (int nb = 0; nb < 4; nb++) {
                int col = bn + wn * 32 + nb * 8 + (lane & 3) * 2;
                #pragma unroll
                for (int half = 0; half < 2; half++) {
                    size_t row = (size_t)(r0 + half * 8);
                    *(float2*)(Cp + row * (size_t)N + col) =
                        make_float2(acc[mb][nb][half*2], acc[mb][nb][half*2 + 1]);
                }
            }
        }
        return;
    }

    if (EPI == EPI_LOSS) {
        #pragma unroll
        for (int mb = 0; mb < 4; mb++) {
            #pragma unroll
            for (int half = 0; half < 2; half++) {
                int rrow = bm + wm * 64 + mb * 16 + (lane >> 2) + half * 8;
                float vals[8];
                float vmax = -1e30f;
                #pragma unroll
                for (int nb = 0; nb < 4; nb++) {
                    int col = bn + wn * 32 + nb * 8 + (lane & 3) * 2;
                    float v0 = acc[mb][nb][half*2 + 0];
                    float v1 = acc[mb][nb][half*2 + 1];
                    size_t base = (size_t)rrow * N + col;
                    if (col + 1 < N) {
                        if ((base & 1) == 0) *(float2*)(C + base) = make_float2(v0, v1);
                        else { C[base] = v0; C[base + 1] = v1; }
                    } else if (col < N) {
                        C[base] = v0;
                    }
                    vals[nb*2    ] = (col     < N) ? v0 : -1e30f;
                    vals[nb*2 + 1] = (col + 1 < N) ? v1 : -1e30f;
                    vmax = fmaxf(vmax, fmaxf(vals[nb*2], vals[nb*2+1]));
                }
                vmax = fmaxf(vmax, __shfl_xor_sync(0xffffffffu, vmax, 1));
                vmax = fmaxf(vmax, __shfl_xor_sync(0xffffffffu, vmax, 2));
                float s = 0.f;
                #pragma unroll
                for (int j = 0; j < 8; j++) s += fast_exp(vals[j] - vmax);
                s += __shfl_xor_sync(0xffffffffu, s, 1);
                s += __shfl_xor_sync(0xffffffffu, s, 2);
                if ((lane & 3) == 0) {
                    size_t po = (size_t)rrow * PCOLS + ntile * 4 + wn;
                    Pm[po] = vmax;
                    Psum[po] = s;
                }
            }
        }
        return;
    }

    // EPI_NONE (fp32 out + bias) / EPI_GELU (fp16 out + bias)
    #pragma unroll
    for (int mb = 0; mb < 4; mb++) {
        int r0 = bm + wm * 64 + mb * 16 + (lane >> 2);
        #pragma unroll
        for (int nb = 0; nb < 4; nb++) {
            int col = bn + wn * 32 + nb * 8 + (lane & 3) * 2;
            #pragma unroll
            for (int half = 0; half < 2; half++) {
                size_t row = (size_t)(r0 + half * 8);
                float v0 = acc[mb][nb][half*2 + 0];
                float v1 = acc[mb][nb][half*2 + 1];
                size_t base = row * (size_t)N + col;
                if (col + 1 < N) {
                    if (bias) { v0 += bias[col]; v1 += bias[col+1]; }
                    if (EPI == EPI_GELU) {
                        v0 = 0.5f*v0*(1.0f + erff(v0*0.70710678118654752f));
                        v1 = 0.5f*v1*(1.0f + erff(v1*0.70710678118654752f));
                        *(__half2*)((__half*)C + base) = __floats2half2_rn(v0, v1);
                    } else {
                        if ((base & 1) == 0) {
                            *(float2*)(C + base) = make_float2(v0, v1);
                        } else {
                            C[base] = v0; C[base + 1] = v1;
                        }
                    }
                } else if (col < N) {
                    if (bias) v0 += bias[col];
                    if (EPI == EPI_GELU) {
                        v0 = 0.5f*v0*(1.0f + erff(v0*0.70710678118654752f));
                        ((__half*)C)[base] = __float2half_rn(v0);
                    } else {
                        C[base] = v0;
                    }
                }
            }
        }
    }
}

// ---------------- fp32 -> fp16 weight conversion ------------------------------
__global__ void __launch_bounds__(256) cvt_half_k(const float* __restrict__ src,
                                                  __half* __restrict__ dst, int n4)
{
    int i = blockIdx.x * 256 + threadIdx.x;
    if (i < n4) {
        float4 v = ((const float4*)src)[i];
        ((__half2*)dst)[i*2    ] = __floats2half2_rn(v.x, v.y);
        ((__half2*)dst)[i*2 + 1] = __floats2half2_rn(v.z, v.w);
    }
}

// ---------------- fused split-K reduce + residual + LayerNorm ----------------
// x += p0 + p1 + bias; h = fp16(LN(x) * w + b)
__global__ void __launch_bounds__(256) splitk_ln_k(
    const float* __restrict__ part, const float* __restrict__ bias,
    float* __restrict__ x,
    const float* __restrict__ lw, const float* __restrict__ lb,
    __half* __restrict__ h)
{
    int n = blockIdx.x;
    int i = threadIdx.x;
    float4 a = ((const float4*)(part + (size_t)n * DMODEL))[i];
    float4 b = ((const float4*)(part + (size_t)NTOK * DMODEL + (size_t)n * DMODEL))[i];
    float4 c = ((const float4*)bias)[i];
    float4 r = ((float4*)(x + (size_t)n * DMODEL))[i];
    float4 v = make_float4(a.x + b.x + c.x + r.x, a.y + b.y + c.y + r.y,
                           a.z + b.z + c.z + r.z, a.w + b.w + c.w + r.w);
    ((float4*)(x + (size_t)n * DMODEL))[i] = v;

    float s  = v.x + v.y + v.z + v.w;
    float ss = v.x*v.x + v.y*v.y + v.z*v.z + v.w*v.w;
    #pragma unroll
    for (int o = 16; o; o >>= 1) {
        s  += __shfl_xor_sync(0xffffffffu, s,  o);
        ss += __shfl_xor_sync(0xffffffffu, ss, o);
    }
    __shared__ float sm[8], sm2[8];
    int wid = i >> 5;
    if ((i & 31) == 0) { sm[wid] = s; sm2[wid] = ss; }
    __syncthreads();
    if (i < 32) {
        s  = (i < 8) ? sm [i] : 0.f;
        ss = (i < 8) ? sm2[i] : 0.f;
        #pragma unroll
        for (int o = 4; o; o >>= 1) {
            s  += __shfl_xor_sync(0xffffffffu, s,  o);
            ss += __shfl_xor_sync(0xffffffffu, ss, o);
        }
        if (i == 0) { sm[0] = s; sm2[0] = ss; }
    }
    __syncthreads();
    float mean = sm[0] * (1.0f/DMODEL);
    float var  = sm2[0] * (1.0f/DMODEL) - mean*mean;
    float inv  = rsqrtf(var + 1e-5f);
    float4 gw = ((const float4*)lw)[i];
    float4 gb = ((const float4*)lb)[i];
    __half* hrow = h + (size_t)n * DMODEL + i * 4;
    *(__half2*)(hrow    ) = __floats2half2_rn((v.x - mean)*inv*gw.x + gb.x,
                                              (v.y - mean)*inv*gw.y + gb.y);
    *(__half2*)(hrow + 2) = __floats2half2_rn((v.z - mean)*inv*gw.z + gb.z,
                                              (v.w - mean)*inv*gw.w + gb.w);
}

// ---------------- embedding --------------------------------------------------
__global__ void embed_k(const int* __restrict__ idx,
                        const float* __restrict__ wte,
                        const float* __restrict__ wpe,
                        float* __restrict__ x)
{
    int n = blockIdx.x;
    int tok = idx[n];
    int t = n % SEQ;
    const float4* a = (const float4*)(wte + (size_t)tok * DMODEL);
    const float4* p = (const float4*)(wpe + (size_t)t   * DMODEL);
    float4* o = (float4*)(x + (size_t)n * DMODEL);
    for (int i = threadIdx.x; i < DMODEL/4; i += blockDim.x) {
        float4 u = a[i], v = p[i];
        o[i] = make_float4(u.x+v.x, u.y+v.y, u.z+v.z, u.w+v.w);
    }
}

// ---------------- standalone layernorm (first ln1 only), fp16 out ------------
__global__ void __launch_bounds__(256) ln_k(const float* __restrict__ x,
                                            const float* __restrict__ w,
                                            const float* __restrict__ b,
                                            __half* __restrict__ out)
{
    int n = blockIdx.x;
    const float* row = x + (size_t)n * DMODEL;
    int i = threadIdx.x;
    float4 v = ((const float4*)row)[i];
    float s  = v.x + v.y + v.z + v.w;
    float ss = v.x*v.x + v.y*v.y + v.z*v.z + v.w*v.w;
    #pragma unroll
    for (int o = 16; o; o >>= 1) {
        s  += __shfl_xor_sync(0xffffffffu, s,  o);
        ss += __shfl_xor_sync(0xffffffffu, ss, o);
    }
    __shared__ float sm[8], sm2[8];
    int wid = i >> 5;
    if ((i & 31) == 0) { sm[wid] = s; sm2[wid] = ss; }
    __syncthreads();
    if (i < 32) {
        s  = (i < 8) ? sm [i] : 0.f;
        ss = (i < 8) ? sm2[i] : 0.f;
        #pragma unroll
        for (int o = 4; o; o >>= 1) {
            s  += __shfl_xor_sync(0xffffffffu, s,  o);
            ss += __shfl_xor_sync(0xffffffffu, ss, o);
        }
        if (i == 0) { sm[0] = s; sm2[0] = ss; }
    }
    __syncthreads();
    float mean = sm[0] * (1.0f/DMODEL);
    float var  = sm2[0] * (1.0f/DMODEL) - mean*mean;
    float inv  = rsqrtf(var + 1e-5f);
    float4 gw = ((const float4*)w)[i];
    float4 gb = ((const float4*)b)[i];
    __half* orow = out + (size_t)n * DMODEL + i * 4;
    *(__half2*)(orow    ) = __floats2half2_rn((v.x - mean)*inv*gw.x + gb.x,
                                              (v.y - mean)*inv*gw.y + gb.y);
    *(__half2*)(orow + 2) = __floats2half2_rn((v.z - mean)*inv*gw.z + gb.z,
                                              (v.w - mean)*inv*gw.w + gb.w);
}

// ---------------- tensor-core flash attention (tf32, fp32 qkv in, fp16 out) --
#define AT_KT 64
#define AT_SMEM 66560
#define PS_STRIDE 68

__device__ __forceinline__ uint32_t att_off(int r, int c /*16B chunk 0..15*/) {
    return (uint32_t)(r * 256 + ((c & 8) << 4) + (((c & 7) ^ (r & 7)) << 4));
}

__global__ void __launch_bounds__(128) attn_k(const float* __restrict__ qkv,
                                              __half* __restrict__ y)
{
    extern __shared__ float smf[];
    uint32_t qsB = smem_to_u32(smf);
    uint32_t ksB = qsB + 16384;
    uint32_t vtB = qsB + 32768;
    float* Ps = smf + 12288;

    const int bh = blockIdx.y;
    const int b = bh >> 4, h = bh & 15;
    const int q0 = (gridDim.x - 1 - blockIdx.x) * 64;
    const int tid = threadIdx.x, wid = tid >> 5, lane = tid & 31;
    const int wq = wid * 16;
    const int qtr = lane >> 2;
    const int qlc = lane & 3;

    #pragma unroll
    for (int u = 0; u < 8; u++) {
        int f = tid + u * 128;
        int r = f >> 4, c = f & 15;
        float4 v = *(const float4*)(qkv + (size_t)(b*SEQ + q0 + r)*3*DMODEL + h*HDIM + c*4);
        float4 w;
        w.x = tf32r(v.x * 0.125f); w.y = tf32r(v.y * 0.125f);
        w.z = tf32r(v.z * 0.125f); w.w = tf32r(v.w * 0.125f);
        *(float4*)((char*)smf + att_off(r, c)) = w;
    }

    float m0 = -1e30f, m1 = -1e30f, l0 = 0.f, l1 = 0.f;
    float o[8][4];
    #pragma unroll
    for (int nb = 0; nb < 8; nb++)
        #pragma unroll
        for (int v = 0; v < 4; v++) o[nb][v] = 0.f;

    const int row0 = q0 + wq + qtr;

    for (int k0 = 0; k0 < q0 + 64; k0 += AT_KT) {
        __syncthreads();
        #pragma unroll
        for (int u = 0; u < 8; u++) {
            int f = tid + u * 128;
            int r = f >> 4, c = f & 15;
            float4 v = *(const float4*)(qkv + (size_t)(b*SEQ + k0 + r)*3*DMODEL + DMODEL + h*HDIM + c*4);
            float4 w;
            w.x = tf32r(v.x); w.y = tf32r(v.y); w.z = tf32r(v.z); w.w = tf32r(v.w);
            *(float4*)((char*)smf + 16384 + att_off(r, c)) = w;
        }
        #pragma unroll
        for (int u = 0; u < 8; u++) {
            int f = tid + u * 128;
            int kt = f >> 4, c = f & 15;
            float4 v = *(const float4*)(qkv + (size_t)(b*SEQ + k0 + kt)*3*DMODEL + 2*DMODEL + h*HDIM + c*4);
            float vv[4] = {v.x, v.y, v.z, v.w};
            #pragma unroll
            for (int j = 0; j < 4; j++) {
                int d = c * 4 + j;
                *(float*)((char*)smf + 32768 + att_off(d, kt >> 2) + (kt & 3) * 4) = tf32r(vv[j]);
            }
        }
        __syncthreads();

        float sc[8][4];
        #pragma unroll
        for (int nb = 0; nb < 8; nb++)
            #pragma unroll
            for (int v = 0; v < 4; v++) sc[nb][v] = 0.f;

        #pragma unroll
        for (int ks8 = 0; ks8 < 8; ks8++) {
            uint32_t af[4];
            LDSM_X4(af, qsB + att_off(wq + (lane & 15), 2*ks8 + (lane >> 4)));
            #pragma unroll
            for (int g = 0; g < 4; g++) {
                uint32_t r4[4];
                int n = g * 16 + (lane & 7) + ((lane >> 4) << 3);
                int ch = 2*ks8 + ((lane >> 3) & 1);
                LDSM_X4(r4, ksB + att_off(n, ch));
                uint32_t b0[2] = {r4[0], r4[1]};
                uint32_t b1[2] = {r4[2], r4[3]};
                MMA_TF32(sc[g*2    ], af, b0);
                MMA_TF32(sc[g*2 + 1], af, b1);
            }
        }

        if (k0 + AT_KT - 1 > q0 + wq) {
            #pragma unroll
            for (int nb = 0; nb < 8; nb++) {
                int c0 = k0 + nb*8 + qlc*2;
                if (c0     > row0    ) sc[nb][0] = -1e30f;
                if (c0 + 1 > row0    ) sc[nb][1] = -1e30f;
                if (c0     > row0 + 8) sc[nb][2] = -1e30f;
                if (c0 + 1 > row0 + 8) sc[nb][3] = -1e30f;
            }
        }

        float mx0 = sc[0][0], mx1 = sc[0][2];
        #pragma unroll
        for (int nb = 0; nb < 8; nb++) {
            mx0 = fmaxf(mx0, fmaxf(sc[nb][0], sc[nb][1]));
            mx1 = fmaxf(mx1, fmaxf(sc[nb][2], sc[nb][3]));
        }
        mx0 = fmaxf(mx0, __shfl_xor_sync(0xffffffffu, mx0, 1));
        mx0 = fmaxf(mx0, __shfl_xor_sync(0xffffffffu, mx0, 2));
        mx1 = fmaxf(mx1, __shfl_xor_sync(0xffffffffu, mx1, 1));
        mx1 = fmaxf(mx1, __shfl_xor_sync(0xffffffffu, mx1, 2));
        float nm0 = fmaxf(m0, mx0), nm1 = fmaxf(m1, mx1);
        float corr0 = fast_exp(m0 - nm0), corr1 = fast_exp(m1 - nm1);
        float s0 = 0.f, s1 = 0.f;
        #pragma unroll
        for (int nb = 0; nb < 8; nb++) {
            sc[nb][0] = fast_exp(sc[nb][0] - nm0);
            sc[nb][1] = fast_exp(sc[nb][1] - nm0);
            sc[nb][2] = fast_exp(sc[nb][2] - nm1);
            sc[nb][3] = fast_exp(sc[nb][3] - nm1);
            s0 += sc[nb][0] + sc[nb][1];
            s1 += sc[nb][2] + sc[nb][3];
        }
        s0 += __shfl_xor_sync(0xffffffffu, s0, 1);
        s0 += __shfl_xor_sync(0xffffffffu, s0, 2);
        s1 += __shfl_xor_sync(0xffffffffu, s1, 1);
        s1 += __shfl_xor_sync(0xffffffffu, s1, 2);
        l0 = l0 * corr0 + s0;  m0 = nm0;
        l1 = l1 * corr1 + s1;  m1 = nm1;
        #pragma unroll
        for (int nb = 0; nb < 8; nb++) {
            o[nb][0] *= corr0; o[nb][1] *= corr0;
            o[nb][2] *= corr1; o[nb][3] *= corr1;
        }

        int pr = wq + qtr;
        #pragma unroll
        for (int nb = 0; nb < 8; nb++) {
            int pc = nb*8 + qlc*2;
            Ps[pr*PS_STRIDE + pc    ] = tf32r(sc[nb][0]);
            Ps[pr*PS_STRIDE + pc + 1] = tf32r(sc[nb][1]);
            Ps[(pr+8)*PS_STRIDE + pc    ] = tf32r(sc[nb][2]);
            Ps[(pr+8)*PS_STRIDE + pc + 1] = tf32r(sc[nb][3]);
        }
        __syncwarp();

        #pragma unroll
        for (int ks8 = 0; ks8 < 8; ks8++) {
            uint32_t pa[4];
            int pk = ks8*8 + qlc;
            pa[0] = __float_as_uint(Ps[(wq + qtr    )*PS_STRIDE + pk    ]);
            pa[1] = __float_as_uint(Ps[(wq + qtr + 8)*PS_STRIDE + pk    ]);
            pa[2] = __float_as_uint(Ps[(wq + qtr    )*PS_STRIDE + pk + 4]);
            pa[3] = __float_as_uint(Ps[(wq + qtr + 8)*PS_STRIDE + pk + 4]);
            #pragma unroll
            for (int g = 0; g < 4; g++) {
                uint32_t r4[4];
                int n = g * 16 + (lane & 7) + ((lane >> 4) << 3);
                int ch = 2*ks8 + ((lane >> 3) & 1);
                LDSM_X4(r4, vtB + att_off(n, ch));
                uint32_t b0[2] = {r4[0], r4[1]};
                uint32_t b1[2] = {r4[2], r4[3]};
                MMA_TF32(o[g*2    ], pa, b0);
                MMA_TF32(o[g*2 + 1], pa, b1);
            }
        }
        __syncwarp();
    }

    // fp16 output (feeds proj GEMM A)
    float inv0 = 1.0f / l0, inv1 = 1.0f / l1;
    size_t g0 = (size_t)(b*SEQ + q0 + wq + qtr) * DMODEL + h*HDIM;
    size_t g1 = g0 + 8 * DMODEL;
    #pragma unroll
    for (int nb = 0; nb < 8; nb++) {
        int d0 = nb*8 + qlc*2;
        *(__half2*)(y + g0 + d0) = __floats2half2_rn(o[nb][0]*inv0, o[nb][1]*inv0);
        *(__half2*)(y + g1 + d0) = __floats2half2_rn(o[nb][2]*inv1, o[nb][3]*inv1);
    }
}

// ---------------- loss reduce over fused partials ----------------------------
__global__ void __launch_bounds__(256) rowloss2_k(const float* __restrict__ pm,
                                                  const float* __restrict__ ps,
                                                  const float* __restrict__ logits,
                                                  const int* __restrict__ tgt,
                                                  float* __restrict__ rowloss)
{
    int n = blockIdx.x;
    const float* rm = pm + (size_t)n * PCOLS;
    const float* rs = ps + (size_t)n * PCOLS;
    float m = -1e30f, ssum = 0.f;
    for (int i = threadIdx.x; i < PCOLS; i += 256) {
        float m2 = rm[i], s2 = rs[i];
        float M = fmaxf(m, m2);
        ssum = ssum*fast_exp(m - M) + s2*fast_exp(m2 - M);
        m = M;
    }
    #pragma unroll
    for (int o = 16; o; o >>= 1) {
        float m2 = __shfl_xor_sync(0xffffffffu, m, o);
        float s2 = __shfl_xor_sync(0xffffffffu, ssum, o);
        float M  = fmaxf(m, m2);
        ssum = ssum*fast_exp(m - M) + s2*fast_exp(m2 - M);
        m = M;
    }
    __shared__ float smm[8], sms[8];
    int wid = threadIdx.x >> 5;
    if ((threadIdx.x & 31) == 0) { smm[wid] = m; sms[wid] = ssum; }
    __syncthreads();
    if (threadIdx.x == 0) {
        float M = smm[0], S = sms[0];
        for (int i = 1; i < 8; i++) {
            float M2 = fmaxf(M, smm[i]);
            S = S*fast_exp(M - M2) + sms[i]*fast_exp(smm[i] - M2);
            M = M2;
        }
        float lse = M + logf(S);
        rowloss[n] = lse - logits[(size_t)n * VOCAB + tgt[n]];
    }
}

__global__ void finalize_k(const float* __restrict__ rowloss, float* __restrict__ out_loss)
{
    float s = 0.f;
    for (int i = threadIdx.x; i < NTOK; i += 256) s += rowloss[i];
    #pragma unroll
    for (int o = 16; o; o >>= 1) s += __shfl_xor_sync(0xffffffffu, s, o);
    __shared__ float sm[8];
    int wid = threadIdx.x >> 5;
    if ((threadIdx.x & 31) == 0) sm[wid] = s;
    __syncthreads();
    if (threadIdx.x == 0) {
        float t = 0.f;
        for (int i = 0; i < 8; i++) t += sm[i];
        *out_loss = t * (1.0f/NTOK);
    }
}

// ---------------- launch -----------------------------------------------------
extern "C" void kernel_launch(void* const* d_in, const int* in_sizes, int n_in,
                              void* d_out, int out_size)
{
    const int*   idx     = (const int*)  d_in[0];
    const int*   targets = (const int*)  d_in[1];
    const float* wte     = (const float*)d_in[2];
    const float* wpe     = (const float*)d_in[3];
    const float* ln1_w   = (const float*)d_in[4];
    const float* ln1_b   = (const float*)d_in[5];
    const float* attn_w  = (const float*)d_in[6];
    const float* attn_b  = (const float*)d_in[7];
    const float* proj_w  = (const float*)d_in[8];
    const float* proj_b  = (const float*)d_in[9];
    const float* ln2_w   = (const float*)d_in[10];
    const float* ln2_b   = (const float*)d_in[11];
    const float* fc_w    = (const float*)d_in[12];
    const float* fc_b    = (const float*)d_in[13];
    const float* fcp_w   = (const float*)d_in[14];
    const float* fcp_b   = (const float*)d_in[15];
    const float* lnf_w   = (const float*)d_in[16];
    const float* lnf_b   = (const float*)d_in[17];

    float *px, *pqkv, *ppart, *plogfb, *prl, *ppm, *pps;
    __half *ph, *patt, *pffn, *pwq, *pwp, *pwf, *pwf2, *pwv;
    cudaGetSymbolAddress((void**)&px,    g_x);
    cudaGetSymbolAddress((void**)&ph,    g_h);
    cudaGetSymbolAddress((void**)&pqkv,  g_qkv);
    cudaGetSymbolAddress((void**)&patt,  g_att);
    cudaGetSymbolAddress((void**)&pffn,  g_ffn);
    cudaGetSymbolAddress((void**)&ppart, g_part);
    cudaGetSymbolAddress((void**)&plogfb,g_logits_fallback);
    cudaGetSymbolAddress((void**)&prl,   g_rowloss);
    cudaGetSymbolAddress((void**)&ppm,   g_pm);
    cudaGetSymbolAddress((void**)&pps,   g_ps);
    cudaGetSymbolAddress((void**)&pwq,   g_wq);
    cudaGetSymbolAddress((void**)&pwp,   g_wp);
    cudaGetSymbolAddress((void**)&pwf,   g_wf);
    cudaGetSymbolAddress((void**)&pwf2,  g_wf2);
    cudaGetSymbolAddress((void**)&pwv,   g_wv);

    static bool attr_done = false;
    if (!attr_done) {
        cudaFuncSetAttribute((const void*)gemm_tc<EPI_NONE,0>,  cudaFuncAttributeMaxDynamicSharedMemorySize, GT_SMEM);
        cudaFuncSetAttribute((const void*)gemm_tc<EPI_GELU,0>,  cudaFuncAttributeMaxDynamicSharedMemorySize, GT_SMEM);
        cudaFuncSetAttribute((const void*)gemm_tc<EPI_PART,0>,  cudaFuncAttributeMaxDynamicSharedMemorySize, GT_SMEM);
        cudaFuncSetAttribute((const void*)gemm_tc<EPI_LOSS,1>,  cudaFuncAttributeMaxDynamicSharedMemorySize, GT_SMEM);
        cudaFuncSetAttribute((const void*)attn_k, cudaFuncAttributeMaxDynamicSharedMemorySize, AT_SMEM);
        attr_done = true;
    }

    const long long LOGN = (long long)NTOK * VOCAB;
    float* logits_ptr;
    float* loss_ptr = nullptr;
    if ((long long)out_size >= LOGN) {
        logits_ptr = (float*)d_out;
        if ((long long)out_size > LOGN) loss_ptr = (float*)d_out + LOGN;
    } else {
        logits_ptr = plogfb;
        loss_ptr = (float*)d_out;
    }

    // weight fp32->fp16 conversion (per launch; ~130us at HBM)
    {
        long long nq  = (long long)LAYERS*3*DMODEL*DMODEL/4;
        long long np  = (long long)LAYERS*DMODEL*DMODEL/4;
        long long nf  = (long long)LAYERS*4*DMODEL*DMODEL/4;
        long long nv  = (long long)VOCAB*DMODEL/4;
        cvt_half_k<<<(int)((nq+255)/256), 256>>>(attn_w, pwq, (int)nq);
        cvt_half_k<<<(int)((np+255)/256), 256>>>(proj_w, pwp, (int)np);
        cvt_half_k<<<(int)((nf+255)/256), 256>>>(fc_w,  pwf,  (int)nf);
        cvt_half_k<<<(int)((nf+255)/256), 256>>>(fcp_w, pwf2, (int)nf);
        cvt_half_k<<<(int)((nv+255)/256), 256>>>(wte,   pwv,  (int)nv);
    }

    embed_k<<<NTOK, 256>>>(idx, wte, wpe, px);
    ln_k<<<NTOK, 256>>>(px, ln1_w, ln1_b, ph);

    dim3 gq (3*DMODEL/128, NTOK/128);       // 24 x 16
    dim3 gp2(DMODEL/128,   NTOK/128, 2);    //  8 x 16 x 2 (split-K)
    dim3 gf (4*DMODEL/128, NTOK/128);       // 32 x 16
    dim3 gv (NTOK/128, NVTILE);             // SWAP: x=M-tiles, y=N-tiles
    dim3 ga (SEQ/64, BATCH*NHEAD);

    for (int l = 0; l < LAYERS; l++) {
        gemm_tc<EPI_NONE,0><<<gq, 256, GT_SMEM>>>(ph, pwq + (size_t)l*3*DMODEL*DMODEL,
                                       attn_b + (size_t)l*3*DMODEL,
                                       pqkv, NTOK, 3*DMODEL, DMODEL, nullptr, nullptr);
        attn_k<<<ga, 128, AT_SMEM>>>(pqkv, patt);
        gemm_tc<EPI_PART,0><<<gp2, 256, GT_SMEM>>>(patt, pwp + (size_t)l*DMODEL*DMODEL,
                                        nullptr,
                                        ppart, NTOK, DMODEL, DMODEL, nullptr, nullptr);
        splitk_ln_k<<<NTOK, 256>>>(ppart, proj_b + (size_t)l*DMODEL, px,
                                   ln2_w + (size_t)l*DMODEL, ln2_b + (size_t)l*DMODEL, ph);
        gemm_tc<EPI_GELU,0><<<gf, 256, GT_SMEM>>>(ph, pwf + (size_t)l*4*DMODEL*DMODEL,
                                       fc_b + (size_t)l*4*DMODEL,
                                       (float*)pffn, NTOK, 4*DMODEL, DMODEL, nullptr, nullptr);
        gemm_tc<EPI_PART,0><<<gp2, 256, GT_SMEM>>>(pffn, pwf2 + (size_t)l*DMODEL*4*DMODEL,
                                        nullptr,
                                        ppart, NTOK, DMODEL, 4*DMODEL, nullptr, nullptr);
        const float* nw = (l + 1 < LAYERS) ? ln1_w + (size_t)(l+1)*DMODEL : lnf_w;
        const float* nb = (l + 1 < LAYERS) ? ln1_b + (size_t)(l+1)*DMODEL : lnf_b;
        splitk_ln_k<<<NTOK, 256>>>(ppart, fcp_b + (size_t)l*DMODEL, px, nw, nb, ph);
    }

    gemm_tc<EPI_LOSS,1><<<gv, 256, GT_SMEM>>>(ph, pwv, nullptr,
                                   logits_ptr, NTOK, VOCAB, DMODEL, ppm, pps);

    if (loss_ptr) {
        rowloss2_k<<<NTOK, 256>>>(ppm, pps, logits_ptr, targets, prl);
        finalize_k<<<1, 256>>>(prl, loss_ptr);
    }
}

// round 15
// speedup vs baseline: 1.0729x; 1.0698x over previous
#include <cuda_runtime.h>
#include <cuda_fp16.h>
#include <math.h>
#include <stdint.h>

// Problem constants
#define LAYERS 6
#define NHEAD  16
#define DMODEL 1024
#define HDIM   64
#define BATCH  2
#define SEQ    1024
#define NTOK   (BATCH*SEQ)     // 2048
#define VOCAB  50257
#define NVTILE ((VOCAB+127)/128)     // 393
#define PCOLS  (NVTILE*4)            // 1572 loss partials per row

// ---------------- scratch ----------------------------------------------------
__device__ float  g_x   [NTOK*DMODEL];
__device__ __half g_h   [NTOK*DMODEL];
__device__ __half g_qkv [NTOK*3*DMODEL];
__device__ __half g_att [NTOK*DMODEL];
__device__ __half g_ffn [NTOK*4*DMODEL];
__device__ float  g_part[2*(size_t)NTOK*DMODEL];    // split-K partials (proj/fcp)
__device__ float  g_logits_fallback[(size_t)NTOK*VOCAB];
__device__ float  g_rowloss[NTOK];
__device__ float  g_pm[(size_t)NTOK*PCOLS];
__device__ float  g_ps[(size_t)NTOK*PCOLS];
// fp16 weight copies (converted once per launch)
__device__ __half g_wq [(size_t)LAYERS*3*DMODEL*DMODEL];
__device__ __half g_wp [(size_t)LAYERS*DMODEL*DMODEL];
__device__ __half g_wf [(size_t)LAYERS*4*DMODEL*DMODEL];
__device__ __half g_wf2[(size_t)LAYERS*DMODEL*4*DMODEL];
__device__ __half g_wv [(size_t)VOCAB*DMODEL];

// ---------------- PTX helpers (sm_80-portable only) --------------------------
__device__ __forceinline__ uint32_t smem_to_u32(const void* p) {
    uint32_t a;
    asm("{ .reg .u64 t; cvta.to.shared.u64 t, %1; cvt.u32.u64 %0, t; }" : "=r"(a) : "l"(p));
    return a;
}
__device__ __forceinline__ void cp_async16(uint32_t dst, const void* src, int srcsize) {
    asm volatile("cp.async.cg.shared.global [%0], [%1], 16, %2;\n"
                 :: "r"(dst), "l"(src), "r"(srcsize) : "memory");
}
#define CP_COMMIT() asm volatile("cp.async.commit_group;" ::: "memory")

#define LDSM_X4(r, a) \
    asm volatile("ldmatrix.sync.aligned.m8n8.x4.shared.b16 {%0,%1,%2,%3}, [%4];" \
        : "=r"((r)[0]), "=r"((r)[1]), "=r"((r)[2]), "=r"((r)[3]) : "r"(a))

// fp16 MMA: m16n8k16, fp32 accumulate
#define MMA_F16(d, a, b) \
    asm volatile("mma.sync.aligned.m16n8k16.row.col.f32.f16.f16.f32 " \
        "{%0,%1,%2,%3}, {%4,%5,%6,%7}, {%8,%9}, {%0,%1,%2,%3};" \
        : "+f"((d)[0]), "+f"((d)[1]), "+f"((d)[2]), "+f"((d)[3]) \
        : "r"((a)[0]), "r"((a)[1]), "r"((a)[2]), "r"((a)[3]), "r"((b)[0]), "r"((b)[1]))

// MUFU-free exp: magic-number 2^n split + deg-5 poly (all FMA pipe).
__device__ __forceinline__ float fast_exp(float x) {
    x = fmaxf(x, -87.0f);
    float f = fminf(x * 1.44269504088896341f, 126.0f);
    float t = f + 12582912.0f;
    int bits = __float_as_int(t);
    int n = (bits & 0x007FFFFF) - 0x00400000;
    float r = f - (t - 12582912.0f);
    float p = 1.33335581e-3f;
    p = p * r + 9.61812911e-3f;
    p = p * r + 5.55041087e-2f;
    p = p * r + 2.40226507e-1f;
    p = p * r + 6.93147181e-1f;
    p = p * r + 1.0f;
    return p * __int_as_float((n + 127) << 23);
}

// ---------------- fp16 mma.sync NT GEMM: C[M,N] = A[M,K]*B[N,K]^T (+epi) -----
// CTA tile 128x128, 8 warps 2x4, warp tile 64x32, BK=64 halfs, 3-stage cp.async.
// A,B fp16; accumulate fp32. SWAP=1: x=M-tiles, y=N-tiles.
// gridDim.z>1: split-K; EPI_PART writes raw fp32 partials at C + z*M*N.
enum { EPI_HALF = 0, EPI_GELU = 1, EPI_LOSS = 3, EPI_PART = 4 };

#define GBM 128
#define GBK 64
#define GSTAGES 3
#define GSTAGE_BYTES (GBM*GBK*2)                 // 16384
#define GT_SMEM (1024 + 2*GSTAGES*GSTAGE_BYTES)  // 99328

__device__ __forceinline__ uint32_t sw_off(int r, int c /*16B chunk 0..7*/) {
    return (uint32_t)(r * 128 + ((c ^ (r & 7)) << 4));
}

template<int EPI, int SWAP>
__global__ void __launch_bounds__(256, 2) gemm_tc(
    const __half* __restrict__ A, const __half* __restrict__ B,
    const float* __restrict__ bias,
    float* __restrict__ C, int M, int N, int K,
    float* __restrict__ Pm, float* __restrict__ Psum)
{
    extern __shared__ char dsm[];
    const int tid  = threadIdx.x;
    const int wid  = tid >> 5;
    const int lane = tid & 31;
    const int wm = wid >> 2;
    const int wn = wid & 3;
    const int bm = (SWAP ? blockIdx.x : blockIdx.y) * 128;
    const int bn = (SWAP ? blockIdx.y : blockIdx.x) * 128;
    const int ntile = SWAP ? blockIdx.y : blockIdx.x;

    uint32_t sbase = (smem_to_u32(dsm) + 1023u) & ~1023u;
    uint32_t aStage0 = sbase;
    uint32_t bStage0 = sbase + GSTAGES * GSTAGE_BYTES;

    const int T = K / (GBK * gridDim.z);
    const int koff = blockIdx.z * T * GBK;

    auto load_tile = [&](int kt, int slot) {
        int k0 = koff + kt * GBK;
        uint32_t aB = aStage0 + slot * GSTAGE_BYTES;
        uint32_t bB = bStage0 + slot * GSTAGE_BYTES;
        #pragma unroll
        for (int u = 0; u < 4; u++) {
            int f = tid + u * 256;
            int r = f >> 3, c = f & 7;
            cp_async16(aB + sw_off(r, c), A + (size_t)(bm + r) * K + k0 + c * 8, 16);
            int gb = bn + r;
            const __half* bsrc = B + (size_t)(gb < N ? gb : 0) * K + k0 + c * 8;
            cp_async16(bB + sw_off(r, c), bsrc, gb < N ? 16 : 0);
        }
        CP_COMMIT();
    };

    float acc[4][4][4];
    #pragma unroll
    for (int i = 0; i < 4; i++)
        #pragma unroll
        for (int j = 0; j < 4; j++)
            #pragma unroll
            for (int v = 0; v < 4; v++) acc[i][j][v] = 0.f;

    load_tile(0, 0);
    load_tile(1, 1);
    load_tile(2, 2);

    for (int kt = 0; kt < T; kt++) {
        if (kt < T - 2)       asm volatile("cp.async.wait_group 2;" ::: "memory");
        else if (kt == T - 2) asm volatile("cp.async.wait_group 1;" ::: "memory");
        else                  asm volatile("cp.async.wait_group 0;" ::: "memory");
        __syncthreads();

        int slot = kt % GSTAGES;
        uint32_t aS = aStage0 + slot * GSTAGE_BYTES;
        uint32_t bS = bStage0 + slot * GSTAGE_BYTES;

        #pragma unroll
        for (int kk = 0; kk < 4; kk++) {       // 4 x k16 per BK=64
            uint32_t af[4][4];
            uint32_t bf[4][2];
            #pragma unroll
            for (int mb = 0; mb < 4; mb++) {
                int row = wm * 64 + mb * 16 + (lane & 15);
                int chunk = kk * 2 + (lane >> 4);
                LDSM_X4(af[mb], aS + sw_off(row, chunk));
            }
            #pragma unroll
            for (int p = 0; p < 2; p++) {
                uint32_t r4[4];
                int n = wn * 32 + p * 16 + (lane & 7) + ((lane >> 4) << 3);
                int chunk = kk * 2 + ((lane >> 3) & 1);
                LDSM_X4(r4, bS + sw_off(n, chunk));
                bf[p*2  ][0] = r4[0]; bf[p*2  ][1] = r4[1];
                bf[p*2+1][0] = r4[2]; bf[p*2+1][1] = r4[3];
            }
            #pragma unroll
            for (int mb = 0; mb < 4; mb++)
                #pragma unroll
                for (int nb = 0; nb < 4; nb++)
                    MMA_F16(acc[mb][nb], af[mb], bf[nb]);
        }
        __syncthreads();
        if (kt + GSTAGES < T) load_tile(kt + GSTAGES, slot);
    }

    if (EPI == EPI_PART) {
        float* Cp = C + (size_t)blockIdx.z * M * (size_t)N;
        #pragma unroll
        for (int mb = 0; mb < 4; mb++) {
            int r0 = bm + wm * 64 + mb * 16 + (lane >> 2);
            #pragma unroll
            for (int nb = 0; nb < 4; nb++) {
                int col = bn + wn * 32 + nb * 8 + (lane & 3) * 2;
                #pragma unroll
                for (int half = 0; half < 2; half++) {
                    size_t row = (size_t)(r0 + half * 8);
                    *(float2*)(Cp + row * (size_t)N + col) =
                        make_float2(acc[mb][nb][half*2], acc[mb][nb][half*2 + 1]);
                }
            }
        }
        return;
    }

    if (EPI == EPI_LOSS) {
        #pragma unroll
        for (int mb = 0; mb < 4; mb++) {
            #pragma unroll
            for (int half = 0; half < 2; half++) {
                int rrow = bm + wm * 64 + mb * 16 + (lane >> 2) + half * 8;
                float vals[8];
                float vmax = -1e30f;
                #pragma unroll
                for (int nb = 0; nb < 4; nb++) {
                    int col = bn + wn * 32 + nb * 8 + (lane & 3) * 2;
                    float v0 = acc[mb][nb][half*2 + 0];
                    float v1 = acc[mb][nb][half*2 + 1];
                    size_t base = (size_t)rrow * N + col;
                    if (col + 1 < N) {
                        if ((base & 1) == 0) *(float2*)(C + base) = make_float2(v0, v1);
                        else { C[base] = v0; C[base + 1] = v1; }
                    } else if (col < N) {
                        C[base] = v0;
                    }
                    vals[nb*2    ] = (col     < N) ? v0 : -1e30f;
                    vals[nb*2 + 1] = (col + 1 < N) ? v1 : -1e30f;
                    vmax = fmaxf(vmax, fmaxf(vals[nb*2], vals[nb*2+1]));
                }
                vmax = fmaxf(vmax, __shfl_xor_sync(0xffffffffu, vmax, 1));
                vmax = fmaxf(vmax, __shfl_xor_sync(0xffffffffu, vmax, 2));
                float s = 0.f;
                #pragma unroll
                for (int j = 0; j < 8; j++) s += fast_exp(vals[j] - vmax);
                s += __shfl_xor_sync(0xffffffffu, s, 1);
                s += __shfl_xor_sync(0xffffffffu, s, 2);
                if ((lane & 3) == 0) {
                    size_t po = (size_t)rrow * PCOLS + ntile * 4 + wn;
                    Pm[po] = vmax;
                    Psum[po] = s;
                }
            }
        }
        return;
    }

    // EPI_HALF (fp16 out + bias) / EPI_GELU (fp16 out + bias + gelu)
    #pragma unroll
    for (int mb = 0; mb < 4; mb++) {
        int r0 = bm + wm * 64 + mb * 16 + (lane >> 2);
        #pragma unroll
        for (int nb = 0; nb < 4; nb++) {
            int col = bn + wn * 32 + nb * 8 + (lane & 3) * 2;
            #pragma unroll
            for (int half = 0; half < 2; half++) {
                size_t row = (size_t)(r0 + half * 8);
                float v0 = acc[mb][nb][half*2 + 0];
                float v1 = acc[mb][nb][half*2 + 1];
                size_t base = row * (size_t)N + col;
                if (col + 1 < N) {
                    if (bias) { v0 += bias[col]; v1 += bias[col+1]; }
                    if (EPI == EPI_GELU) {
                        v0 = 0.5f*v0*(1.0f + erff(v0*0.70710678118654752f));
                        v1 = 0.5f*v1*(1.0f + erff(v1*0.70710678118654752f));
                    }
                    *(__half2*)((__half*)C + base) = __floats2half2_rn(v0, v1);
                } else if (col < N) {
                    if (bias) v0 += bias[col];
                    if (EPI == EPI_GELU) v0 = 0.5f*v0*(1.0f + erff(v0*0.70710678118654752f));
                    ((__half*)C)[base] = __float2half_rn(v0);
                }
            }
        }
    }
}

// ---------------- fp32 -> fp16 weight conversion ------------------------------
__global__ void __launch_bounds__(256) cvt_half_k(const float* __restrict__ src,
                                                  __half* __restrict__ dst, int n4)
{
    int i = blockIdx.x * 256 + threadIdx.x;
    if (i < n4) {
        float4 v = ((const float4*)src)[i];
        ((__half2*)dst)[i*2    ] = __floats2half2_rn(v.x, v.y);
        ((__half2*)dst)[i*2 + 1] = __floats2half2_rn(v.z, v.w);
    }
}

// ---------------- fused split-K reduce + residual + LayerNorm ----------------
__global__ void __launch_bounds__(256) splitk_ln_k(
    const float* __restrict__ part, const float* __restrict__ bias,
    float* __restrict__ x,
    const float* __restrict__ lw, const float* __restrict__ lb,
    __half* __restrict__ h)
{
    int n = blockIdx.x;
    int i = threadIdx.x;
    float4 a = ((const float4*)(part + (size_t)n * DMODEL))[i];
    float4 b = ((const float4*)(part + (size_t)NTOK * DMODEL + (size_t)n * DMODEL))[i];
    float4 c = ((const float4*)bias)[i];
    float4 r = ((float4*)(x + (size_t)n * DMODEL))[i];
    float4 v = make_float4(a.x + b.x + c.x + r.x, a.y + b.y + c.y + r.y,
                           a.z + b.z + c.z + r.z, a.w + b.w + c.w + r.w);
    ((float4*)(x + (size_t)n * DMODEL))[i] = v;

    float s  = v.x + v.y + v.z + v.w;
    float ss = v.x*v.x + v.y*v.y + v.z*v.z + v.w*v.w;
    #pragma unroll
    for (int o = 16; o; o >>= 1) {
        s  += __shfl_xor_sync(0xffffffffu, s,  o);
        ss += __shfl_xor_sync(0xffffffffu, ss, o);
    }
    __shared__ float sm[8], sm2[8];
    int wid = i >> 5;
    if ((i & 31) == 0) { sm[wid] = s; sm2[wid] = ss; }
    __syncthreads();
    if (i < 32) {
        s  = (i < 8) ? sm [i] : 0.f;
        ss = (i < 8) ? sm2[i] : 0.f;
        #pragma unroll
        for (int o = 4; o; o >>= 1) {
            s  += __shfl_xor_sync(0xffffffffu, s,  o);
            ss += __shfl_xor_sync(0xffffffffu, ss, o);
        }
        if (i == 0) { sm[0] = s; sm2[0] = ss; }
    }
    __syncthreads();
    float mean = sm[0] * (1.0f/DMODEL);
    float var  = sm2[0] * (1.0f/DMODEL) - mean*mean;
    float inv  = rsqrtf(var + 1e-5f);
    float4 gw = ((const float4*)lw)[i];
    float4 gb = ((const float4*)lb)[i];
    __half* hrow = h + (size_t)n * DMODEL + i * 4;
    *(__half2*)(hrow    ) = __floats2half2_rn((v.x - mean)*inv*gw.x + gb.x,
                                              (v.y - mean)*inv*gw.y + gb.y);
    *(__half2*)(hrow + 2) = __floats2half2_rn((v.z - mean)*inv*gw.z + gb.z,
                                              (v.w - mean)*inv*gw.w + gb.w);
}

// ---------------- embedding --------------------------------------------------
__global__ void embed_k(const int* __restrict__ idx,
                        const float* __restrict__ wte,
                        const float* __restrict__ wpe,
                        float* __restrict__ x)
{
    int n = blockIdx.x;
    int tok = idx[n];
    int t = n % SEQ;
    const float4* a = (const float4*)(wte + (size_t)tok * DMODEL);
    const float4* p = (const float4*)(wpe + (size_t)t   * DMODEL);
    float4* o = (float4*)(x + (size_t)n * DMODEL);
    for (int i = threadIdx.x; i < DMODEL/4; i += blockDim.x) {
        float4 u = a[i], v = p[i];
        o[i] = make_float4(u.x+v.x, u.y+v.y, u.z+v.z, u.w+v.w);
    }
}

// ---------------- standalone layernorm (first ln1 only), fp16 out ------------
__global__ void __launch_bounds__(256) ln_k(const float* __restrict__ x,
                                            const float* __restrict__ w,
                                            const float* __restrict__ b,
                                            __half* __restrict__ out)
{
    int n = blockIdx.x;
    const float* row = x + (size_t)n * DMODEL;
    int i = threadIdx.x;
    float4 v = ((const float4*)row)[i];
    float s  = v.x + v.y + v.z + v.w;
    float ss = v.x*v.x + v.y*v.y + v.z*v.z + v.w*v.w;
    #pragma unroll
    for (int o = 16; o; o >>= 1) {
        s  += __shfl_xor_sync(0xffffffffu, s,  o);
        ss += __shfl_xor_sync(0xffffffffu, ss, o);
    }
    __shared__ float sm[8], sm2[8];
    int wid = i >> 5;
    if ((i & 31) == 0) { sm[wid] = s; sm2[wid] = ss; }
    __syncthreads();
    if (i < 32) {
        s  = (i < 8) ? sm [i] : 0.f;
        ss = (i < 8) ? sm2[i] : 0.f;
        #pragma unroll
        for (int o = 4; o; o >>= 1) {
            s  += __shfl_xor_sync(0xffffffffu, s,  o);
            ss += __shfl_xor_sync(0xffffffffu, ss, o);
        }
        if (i == 0) { sm[0] = s; sm2[0] = ss; }
    }
    __syncthreads();
    float mean = sm[0] * (1.0f/DMODEL);
    float var  = sm2[0] * (1.0f/DMODEL) - mean*mean;
    float inv  = rsqrtf(var + 1e-5f);
    float4 gw = ((const float4*)w)[i];
    float4 gb = ((const float4*)b)[i];
    __half* orow = out + (size_t)n * DMODEL + i * 4;
    *(__half2*)(orow    ) = __floats2half2_rn((v.x - mean)*inv*gw.x + gb.x,
                                              (v.y - mean)*inv*gw.y + gb.y);
    *(__half2*)(orow + 2) = __floats2half2_rn((v.z - mean)*inv*gw.z + gb.z,
                                              (v.w - mean)*inv*gw.w + gb.w);
}

// ---------------- fp16 tensor-core flash attention ----------------------------
// 128 threads (4 warps), Q tile 64, K tile 64, m16n8k16 HMMA.
// smem: Qs 8K | Ks 8K | VT 8K | Ps 8K = 32KB (+pad). Scale 1/8 applied on scores.
#define AT_SMEM 33024

__global__ void __launch_bounds__(128) attn_k(const __half* __restrict__ qkv,
                                              __half* __restrict__ y)
{
    extern __shared__ char sm8[];
    uint32_t qsB = smem_to_u32(sm8);
    uint32_t ksB = qsB + 8192;
    uint32_t vtB = qsB + 16384;
    uint32_t psB = qsB + 24576;

    const int bh = blockIdx.y;
    const int b = bh >> 4, h = bh & 15;
    const int q0 = (gridDim.x - 1 - blockIdx.x) * 64;   // heavy tiles first
    const int tid = threadIdx.x, wid = tid >> 5, lane = tid & 31;
    const int wq = wid * 16;
    const int qtr = lane >> 2;
    const int qlc = lane & 3;

    // Q tile: 64 rows x 64 halfs via cp.async (raw; scale folded into scores)
    #pragma unroll
    for (int u = 0; u < 4; u++) {
        int f = tid + u * 128;
        int r = f >> 3, c = f & 7;
        cp_async16(qsB + sw_off(r, c),
                   qkv + (size_t)(b*SEQ + q0 + r)*3*DMODEL + h*HDIM + c*8, 16);
    }
    CP_COMMIT();

    float m0 = -1e30f, m1 = -1e30f, l0 = 0.f, l1 = 0.f;
    float o[8][4];
    #pragma unroll
    for (int nb = 0; nb < 8; nb++)
        #pragma unroll
        for (int v = 0; v < 4; v++) o[nb][v] = 0.f;

    const int row0 = q0 + wq + qtr;

    for (int k0 = 0; k0 < q0 + 64; k0 += 64) {
        __syncthreads();     // smem reuse barrier (also covers Q on iter 0 via wait below)
        // K tile via cp.async
        #pragma unroll
        for (int u = 0; u < 4; u++) {
            int f = tid + u * 128;
            int r = f >> 3, c = f & 7;
            cp_async16(ksB + sw_off(r, c),
                       qkv + (size_t)(b*SEQ + k0 + r)*3*DMODEL + DMODEL + h*HDIM + c*8, 16);
        }
        CP_COMMIT();
        // V^T tile: manual transpose scatter (halfs)
        #pragma unroll
        for (int u = 0; u < 4; u++) {
            int f = tid + u * 128;
            int kt = f >> 3, c = f & 7;
            uint4 vv = *(const uint4*)(qkv + (size_t)(b*SEQ + k0 + kt)*3*DMODEL + 2*DMODEL + h*HDIM + c*8);
            uint32_t w[4] = {vv.x, vv.y, vv.z, vv.w};
            #pragma unroll
            for (int j = 0; j < 4; j++) {
                #pragma unroll
                for (int e = 0; e < 2; e++) {
                    int d = c*8 + j*2 + e;
                    uint32_t off = (uint32_t)(d * 128 + (((kt >> 3) ^ (d & 7)) << 4) + (kt & 7) * 2);
                    *(__half*)(sm8 + 16384 + off) = ((__half*)&w[j])[e];
                }
            }
        }
        asm volatile("cp.async.wait_group 0;" ::: "memory");
        __syncthreads();

        // ---- QK^T (fp16 k16) ----
        float sc[8][4];
        #pragma unroll
        for (int nb = 0; nb < 8; nb++)
            #pragma unroll
            for (int v = 0; v < 4; v++) sc[nb][v] = 0.f;

        #pragma unroll
        for (int ks = 0; ks < 4; ks++) {
            uint32_t af[4];
            LDSM_X4(af, qsB + sw_off(wq + (lane & 15), ks*2 + (lane >> 4)));
            #pragma unroll
            for (int g = 0; g < 4; g++) {
                uint32_t r4[4];
                int n = g * 16 + (lane & 7) + ((lane >> 4) << 3);
                int ch = ks*2 + ((lane >> 3) & 1);
                LDSM_X4(r4, ksB + sw_off(n, ch));
                uint32_t b0[2] = {r4[0], r4[1]};
                uint32_t b1[2] = {r4[2], r4[3]};
                MMA_F16(sc[g*2    ], af, b0);
                MMA_F16(sc[g*2 + 1], af, b1);
            }
        }
        // scale 1/sqrt(64)
        #pragma unroll
        for (int nb = 0; nb < 8; nb++)
            #pragma unroll
            for (int v = 0; v < 4; v++) sc[nb][v] *= 0.125f;

        // ---- causal mask ----
        if (k0 + 63 > q0 + wq) {
            #pragma unroll
            for (int nb = 0; nb < 8; nb++) {
                int c0 = k0 + nb*8 + qlc*2;
                if (c0     > row0    ) sc[nb][0] = -1e30f;
                if (c0 + 1 > row0    ) sc[nb][1] = -1e30f;
                if (c0     > row0 + 8) sc[nb][2] = -1e30f;
                if (c0 + 1 > row0 + 8) sc[nb][3] = -1e30f;
            }
        }

        // ---- online softmax ----
        float mx0 = sc[0][0], mx1 = sc[0][2];
        #pragma unroll
        for (int nb = 0; nb < 8; nb++) {
            mx0 = fmaxf(mx0, fmaxf(sc[nb][0], sc[nb][1]));
            mx1 = fmaxf(mx1, fmaxf(sc[nb][2], sc[nb][3]));
        }
        mx0 = fmaxf(mx0, __shfl_xor_sync(0xffffffffu, mx0, 1));
        mx0 = fmaxf(mx0, __shfl_xor_sync(0xffffffffu, mx0, 2));
        mx1 = fmaxf(mx1, __shfl_xor_sync(0xffffffffu, mx1, 1));
        mx1 = fmaxf(mx1, __shfl_xor_sync(0xffffffffu, mx1, 2));
        float nm0 = fmaxf(m0, mx0), nm1 = fmaxf(m1, mx1);
        float corr0 = fast_exp(m0 - nm0), corr1 = fast_exp(m1 - nm1);
        float s0 = 0.f, s1 = 0.f;
        #pragma unroll
        for (int nb = 0; nb < 8; nb++) {
            sc[nb][0] = fast_exp(sc[nb][0] - nm0);
            sc[nb][1] = fast_exp(sc[nb][1] - nm0);
            sc[nb][2] = fast_exp(sc[nb][2] - nm1);
            sc[nb][3] = fast_exp(sc[nb][3] - nm1);
            s0 += sc[nb][0] + sc[nb][1];
            s1 += sc[nb][2] + sc[nb][3];
        }
        s0 += __shfl_xor_sync(0xffffffffu, s0, 1);
        s0 += __shfl_xor_sync(0xffffffffu, s0, 2);
        s1 += __shfl_xor_sync(0xffffffffu, s1, 1);
        s1 += __shfl_xor_sync(0xffffffffu, s1, 2);
        l0 = l0 * corr0 + s0;  m0 = nm0;
        l1 = l1 * corr1 + s1;  m1 = nm1;
        #pragma unroll
        for (int nb = 0; nb < 8; nb++) {
            o[nb][0] *= corr0; o[nb][1] *= corr0;
            o[nb][2] *= corr1; o[nb][3] *= corr1;
        }

        // ---- P frags -> Ps (fp16, swizzled rows of 64 halfs), warp-local ----
        {
            int pr = wq + qtr;
            #pragma unroll
            for (int nb = 0; nb < 8; nb++) {
                int pc = nb*8 + qlc*2;
                uint32_t off0 = (uint32_t)(pr * 128 + (((pc >> 3) ^ (pr & 7)) << 4) + (pc & 7) * 2);
                *(__half2*)(sm8 + 24576 + off0) = __floats2half2_rn(sc[nb][0], sc[nb][1]);
                int pr1 = pr + 8;
                uint32_t off1 = (uint32_t)(pr1 * 128 + (((pc >> 3) ^ (pr1 & 7)) << 4) + (pc & 7) * 2);
                *(__half2*)(sm8 + 24576 + off1) = __floats2half2_rn(sc[nb][2], sc[nb][3]);
            }
        }
        __syncwarp();

        // ---- P @ V (fp16 k16) ----
        #pragma unroll
        for (int ks = 0; ks < 4; ks++) {
            uint32_t pa[4];
            LDSM_X4(pa, psB + sw_off(wq + (lane & 15), ks*2 + (lane >> 4)));
            #pragma unroll
            for (int g = 0; g < 4; g++) {
                uint32_t r4[4];
                int n = g * 16 + (lane & 7) + ((lane >> 4) << 3);
                int ch = ks*2 + ((lane >> 3) & 1);
                LDSM_X4(r4, vtB + sw_off(n, ch));
                uint32_t b0[2] = {r4[0], r4[1]};
                uint32_t b1[2] = {r4[2], r4[3]};
                MMA_F16(o[g*2    ], pa, b0);
                MMA_F16(o[g*2 + 1], pa, b1);
            }
        }
        __syncwarp();
    }

    // fp16 output (feeds proj GEMM A)
    float inv0 = 1.0f / l0, inv1 = 1.0f / l1;
    size_t g0 = (size_t)(b*SEQ + q0 + wq + qtr) * DMODEL + h*HDIM;
    size_t g1 = g0 + 8 * DMODEL;
    #pragma unroll
    for (int nb = 0; nb < 8; nb++) {
        int d0 = nb*8 + qlc*2;
        *(__half2*)(y + g0 + d0) = __floats2half2_rn(o[nb][0]*inv0, o[nb][1]*inv0);
        *(__half2*)(y + g1 + d0) = __floats2half2_rn(o[nb][2]*inv1, o[nb][3]*inv1);
    }
}

// ---------------- loss reduce over fused partials ----------------------------
__global__ void __launch_bounds__(256) rowloss2_k(const float* __restrict__ pm,
                                                  const float* __restrict__ ps,
                                                  const float* __restrict__ logits,
                                                  const int* __restrict__ tgt,
                                                  float* __restrict__ rowloss)
{
    int n = blockIdx.x;
    const float* rm = pm + (size_t)n * PCOLS;
    const float* rs = ps + (size_t)n * PCOLS;
    float m = -1e30f, ssum = 0.f;
    for (int i = threadIdx.x; i < PCOLS; i += 256) {
        float m2 = rm[i], s2 = rs[i];
        float M = fmaxf(m, m2);
        ssum = ssum*fast_exp(m - M) + s2*fast_exp(m2 - M);
        m = M;
    }
    #pragma unroll
    for (int o = 16; o; o >>= 1) {
        float m2 = __shfl_xor_sync(0xffffffffu, m, o);
        float s2 = __shfl_xor_sync(0xffffffffu, ssum, o);
        float M  = fmaxf(m, m2);
        ssum = ssum*fast_exp(m - M) + s2*fast_exp(m2 - M);
        m = M;
    }
    __shared__ float smm[8], sms[8];
    int wid = threadIdx.x >> 5;
    if ((threadIdx.x & 31) == 0) { smm[wid] = m; sms[wid] = ssum; }
    __syncthreads();
    if (threadIdx.x == 0) {
        float M = smm[0], S = sms[0];
        for (int i = 1; i < 8; i++) {
            float M2 = fmaxf(M, smm[i]);
            S = S*fast_exp(M - M2) + sms[i]*fast_exp(smm[i] - M2);
            M = M2;
        }
        float lse = M + logf(S);
        rowloss[n] = lse - logits[(size_t)n * VOCAB + tgt[n]];
    }
}

__global__ void finalize_k(const float* __restrict__ rowloss, float* __restrict__ out_loss)
{
    float s = 0.f;
    for (int i = threadIdx.x; i < NTOK; i += 256) s += rowloss[i];
    #pragma unroll
    for (int o = 16; o; o >>= 1) s += __shfl_xor_sync(0xffffffffu, s, o);
    __shared__ float sm[8];
    int wid = threadIdx.x >> 5;
    if ((threadIdx.x & 31) == 0) sm[wid] = s;
    __syncthreads();
    if (threadIdx.x == 0) {
        float t = 0.f;
        for (int i = 0; i < 8; i++) t += sm[i];
        *out_loss = t * (1.0f/NTOK);
    }
}

// ---------------- launch -----------------------------------------------------
extern "C" void kernel_launch(void* const* d_in, const int* in_sizes, int n_in,
                              void* d_out, int out_size)
{
    const int*   idx     = (const int*)  d_in[0];
    const int*   targets = (const int*)  d_in[1];
    const float* wte     = (const float*)d_in[2];
    const float* wpe     = (const float*)d_in[3];
    const float* ln1_w   = (const float*)d_in[4];
    const float* ln1_b   = (const float*)d_in[5];
    const float* attn_w  = (const float*)d_in[6];
    const float* attn_b  = (const float*)d_in[7];
    const float* proj_w  = (const float*)d_in[8];
    const float* proj_b  = (const float*)d_in[9];
    const float* ln2_w   = (const float*)d_in[10];
    const float* ln2_b   = (const float*)d_in[11];
    const float* fc_w    = (const float*)d_in[12];
    const float* fc_b    = (const float*)d_in[13];
    const float* fcp_w   = (const float*)d_in[14];
    const float* fcp_b   = (const float*)d_in[15];
    const float* lnf_w   = (const float*)d_in[16];
    const float* lnf_b   = (const float*)d_in[17];

    float *px, *ppart, *plogfb, *prl, *ppm, *pps;
    __half *ph, *pqkv, *patt, *pffn, *pwq, *pwp, *pwf, *pwf2, *pwv;
    cudaGetSymbolAddress((void**)&px,    g_x);
    cudaGetSymbolAddress((void**)&ph,    g_h);
    cudaGetSymbolAddress((void**)&pqkv,  g_qkv);
    cudaGetSymbolAddress((void**)&patt,  g_att);
    cudaGetSymbolAddress((void**)&pffn,  g_ffn);
    cudaGetSymbolAddress((void**)&ppart, g_part);
    cudaGetSymbolAddress((void**)&plogfb,g_logits_fallback);
    cudaGetSymbolAddress((void**)&prl,   g_rowloss);
    cudaGetSymbolAddress((void**)&ppm,   g_pm);
    cudaGetSymbolAddress((void**)&pps,   g_ps);
    cudaGetSymbolAddress((void**)&pwq,   g_wq);
    cudaGetSymbolAddress((void**)&pwp,   g_wp);
    cudaGetSymbolAddress((void**)&pwf,   g_wf);
    cudaGetSymbolAddress((void**)&pwf2,  g_wf2);
    cudaGetSymbolAddress((void**)&pwv,   g_wv);

    static bool attr_done = false;
    if (!attr_done) {
        cudaFuncSetAttribute((const void*)gemm_tc<EPI_HALF,0>,  cudaFuncAttributeMaxDynamicSharedMemorySize, GT_SMEM);
        cudaFuncSetAttribute((const void*)gemm_tc<EPI_GELU,0>,  cudaFuncAttributeMaxDynamicSharedMemorySize, GT_SMEM);
        cudaFuncSetAttribute((const void*)gemm_tc<EPI_PART,0>,  cudaFuncAttributeMaxDynamicSharedMemorySize, GT_SMEM);
        cudaFuncSetAttribute((const void*)gemm_tc<EPI_LOSS,1>,  cudaFuncAttributeMaxDynamicSharedMemorySize, GT_SMEM);
        cudaFuncSetAttribute((const void*)attn_k, cudaFuncAttributeMaxDynamicSharedMemorySize, AT_SMEM);
        attr_done = true;
    }

    const long long LOGN = (long long)NTOK * VOCAB;
    float* logits_ptr;
    float* loss_ptr = nullptr;
    if ((long long)out_size >= LOGN) {
        logits_ptr = (float*)d_out;
        if ((long long)out_size > LOGN) loss_ptr = (float*)d_out + LOGN;
    } else {
        logits_ptr = plogfb;
        loss_ptr = (float*)d_out;
    }

    // weight fp32->fp16 conversion (per launch)
    {
        long long nq  = (long long)LAYERS*3*DMODEL*DMODEL/4;
        long long np  = (long long)LAYERS*DMODEL*DMODEL/4;
        long long nf  = (long long)LAYERS*4*DMODEL*DMODEL/4;
        long long nv  = (long long)VOCAB*DMODEL/4;
        cvt_half_k<<<(int)((nq+255)/256), 256>>>(attn_w, pwq, (int)nq);
        cvt_half_k<<<(int)((np+255)/256), 256>>>(proj_w, pwp, (int)np);
        cvt_half_k<<<(int)((nf+255)/256), 256>>>(fc_w,  pwf,  (int)nf);
        cvt_half_k<<<(int)((nf+255)/256), 256>>>(fcp_w, pwf2, (int)nf);
        cvt_half_k<<<(int)((nv+255)/256), 256>>>(wte,   pwv,  (int)nv);
    }

    embed_k<<<NTOK, 256>>>(idx, wte, wpe, px);
    ln_k<<<NTOK, 256>>>(px, ln1_w, ln1_b, ph);

    dim3 gq (3*DMODEL/128, NTOK/128);       // 24 x 16
    dim3 gp2(DMODEL/128,   NTOK/128, 2);    //  8 x 16 x 2 (split-K)
    dim3 gf (4*DMODEL/128, NTOK/128);       // 32 x 16
    dim3 gv (NTOK/128, NVTILE);             // SWAP: x=M-tiles, y=N-tiles
    dim3 ga (SEQ/64, BATCH*NHEAD);

    for (int l = 0; l < LAYERS; l++) {
        gemm_tc<EPI_HALF,0><<<gq, 256, GT_SMEM>>>(ph, pwq + (size_t)l*3*DMODEL*DMODEL,
                                       attn_b + (size_t)l*3*DMODEL,
                                       (float*)pqkv, NTOK, 3*DMODEL, DMODEL, nullptr, nullptr);
        attn_k<<<ga, 128, AT_SMEM>>>(pqkv, patt);
        gemm_tc<EPI_PART,0><<<gp2, 256, GT_SMEM>>>(patt, pwp + (size_t)l*DMODEL*DMODEL,
                                        nullptr,
                                        ppart, NTOK, DMODEL, DMODEL, nullptr, nullptr);
        splitk_ln_k<<<NTOK, 256>>>(ppart, proj_b + (size_t)l*DMODEL, px,
                                   ln2_w + (size_t)l*DMODEL, ln2_b + (size_t)l*DMODEL, ph);
        gemm_tc<EPI_GELU,0><<<gf, 256, GT_SMEM>>>(ph, pwf + (size_t)l*4*DMODEL*DMODEL,
                                       fc_b + (size_t)l*4*DMODEL,
                                       (float*)pffn, NTOK, 4*DMODEL, DMODEL, nullptr, nullptr);
        gemm_tc<EPI_PART,0><<<gp2, 256, GT_SMEM>>>(pffn, pwf2 + (size_t)l*DMODEL*4*DMODEL,
                                        nullptr,
                                        ppart, NTOK, DMODEL, 4*DMODEL, nullptr, nullptr);
        const float* nw = (l + 1 < LAYERS) ? ln1_w + (size_t)(l+1)*DMODEL : lnf_w;
        const float* nb = (l + 1 < LAYERS) ? ln1_b + (size_t)(l+1)*DMODEL : lnf_b;
        splitk_ln_k<<<NTOK, 256>>>(ppart, fcp_b + (size_t)l*DMODEL, px, nw, nb, ph);
    }

    gemm_tc<EPI_LOSS,1><<<gv, 256, GT_SMEM>>>(ph, pwv, nullptr,
                                   logits_ptr, NTOK, VOCAB, DMODEL, ppm, pps);

    if (loss_ptr) {
        rowloss2_k<<<NTOK, 256>>>(ppm, pps, logits_ptr, targets, prl);
        finalize_k<<<1, 256>>>(prl, loss_ptr);
    }
}

// round 16
// speedup vs baseline: 1.1052x; 1.0301x over previous
#include <cuda_runtime.h>
#include <cuda_fp16.h>
#include <math.h>
#include <stdint.h>

// Problem constants
#define LAYERS 6
#define NHEAD  16
#define DMODEL 1024
#define HDIM   64
#define BATCH  2
#define SEQ    1024
#define NTOK   (BATCH*SEQ)     // 2048
#define VOCAB  50257
#define NVTILE ((VOCAB+127)/128)     // 393
#define PCOLS  (NVTILE*4)            // 1572 loss partials per row

// ---------------- scratch ----------------------------------------------------
__device__ float  g_x   [NTOK*DMODEL];
__device__ __half g_h   [NTOK*DMODEL];
__device__ __half g_qkv [NTOK*3*DMODEL];
__device__ __half g_att [NTOK*DMODEL];
__device__ __half g_ffn [NTOK*4*DMODEL];
__device__ float  g_part[2*(size_t)NTOK*DMODEL];    // split-K partials (proj/fcp)
__device__ float  g_logits_fallback[(size_t)NTOK*VOCAB];
__device__ float  g_rowloss[NTOK];
__device__ float  g_pm[(size_t)NTOK*PCOLS];
__device__ float  g_ps[(size_t)NTOK*PCOLS];
// fp16 weight copies (converted once per launch)
__device__ __half g_wq [(size_t)LAYERS*3*DMODEL*DMODEL];
__device__ __half g_wp [(size_t)LAYERS*DMODEL*DMODEL];
__device__ __half g_wf [(size_t)LAYERS*4*DMODEL*DMODEL];
__device__ __half g_wf2[(size_t)LAYERS*DMODEL*4*DMODEL];
__device__ __half g_wv [(size_t)VOCAB*DMODEL];

// ---------------- PTX helpers (sm_80-portable only) --------------------------
__device__ __forceinline__ uint32_t smem_to_u32(const void* p) {
    uint32_t a;
    asm("{ .reg .u64 t; cvta.to.shared.u64 t, %1; cvt.u32.u64 %0, t; }" : "=r"(a) : "l"(p));
    return a;
}
__device__ __forceinline__ void cp_async16(uint32_t dst, const void* src, int srcsize) {
    asm volatile("cp.async.cg.shared.global [%0], [%1], 16, %2;\n"
                 :: "r"(dst), "l"(src), "r"(srcsize) : "memory");
}
#define CP_COMMIT() asm volatile("cp.async.commit_group;" ::: "memory")

#define LDSM_X4(r, a) \
    asm volatile("ldmatrix.sync.aligned.m8n8.x4.shared.b16 {%0,%1,%2,%3}, [%4];" \
        : "=r"((r)[0]), "=r"((r)[1]), "=r"((r)[2]), "=r"((r)[3]) : "r"(a))

// fp16 MMA: m16n8k16, fp32 accumulate
#define MMA_F16(d, a, b) \
    asm volatile("mma.sync.aligned.m16n8k16.row.col.f32.f16.f16.f32 " \
        "{%0,%1,%2,%3}, {%4,%5,%6,%7}, {%8,%9}, {%0,%1,%2,%3};" \
        : "+f"((d)[0]), "+f"((d)[1]), "+f"((d)[2]), "+f"((d)[3]) \
        : "r"((a)[0]), "r"((a)[1]), "r"((a)[2]), "r"((a)[3]), "r"((b)[0]), "r"((b)[1]))

// MUFU-free exp: magic-number 2^n split + deg-5 poly (all FMA pipe).
__device__ __forceinline__ float fast_exp(float x) {
    x = fmaxf(x, -87.0f);
    float f = fminf(x * 1.44269504088896341f, 126.0f);
    float t = f + 12582912.0f;
    int bits = __float_as_int(t);
    int n = (bits & 0x007FFFFF) - 0x00400000;
    float r = f - (t - 12582912.0f);
    float p = 1.33335581e-3f;
    p = p * r + 9.61812911e-3f;
    p = p * r + 5.55041087e-2f;
    p = p * r + 2.40226507e-1f;
    p = p * r + 6.93147181e-1f;
    p = p * r + 1.0f;
    return p * __int_as_float((n + 127) << 23);
}

// ---------------- fp16 mma.sync NT GEMM: C[M,N] = A[M,K]*B[N,K]^T (+epi) -----
// CTA tile 128x128, 8 warps 2x4, warp tile 64x32, BK=64 halfs.
// Single-barrier 3-stage pipeline (CUTLASS order): preload 2 tiles, per iter
// wait(kt) -> barrier -> issue load(kt+2) -> compute(kt).
enum { EPI_HALF = 0, EPI_GELU = 1, EPI_LOSS = 3, EPI_PART = 4 };

#define GBM 128
#define GBK 64
#define GSTAGES 3
#define GSTAGE_BYTES (GBM*GBK*2)                 // 16384
#define GT_SMEM (1024 + 2*GSTAGES*GSTAGE_BYTES)  // 99328

__device__ __forceinline__ uint32_t sw_off(int r, int c /*16B chunk 0..7*/) {
    return (uint32_t)(r * 128 + ((c ^ (r & 7)) << 4));
}

template<int EPI, int SWAP>
__global__ void __launch_bounds__(256, 2) gemm_tc(
    const __half* __restrict__ A, const __half* __restrict__ B,
    const float* __restrict__ bias,
    float* __restrict__ C, int M, int N, int K,
    float* __restrict__ Pm, float* __restrict__ Psum)
{
    extern __shared__ char dsm[];
    const int tid  = threadIdx.x;
    const int wid  = tid >> 5;
    const int lane = tid & 31;
    const int wm = wid >> 2;
    const int wn = wid & 3;
    const int bm = (SWAP ? blockIdx.x : blockIdx.y) * 128;
    const int bn = (SWAP ? blockIdx.y : blockIdx.x) * 128;
    const int ntile = SWAP ? blockIdx.y : blockIdx.x;

    uint32_t sbase = (smem_to_u32(dsm) + 1023u) & ~1023u;
    uint32_t aStage0 = sbase;
    uint32_t bStage0 = sbase + GSTAGES * GSTAGE_BYTES;

    const int T = K / (GBK * gridDim.z);
    const int koff = blockIdx.z * T * GBK;

    auto load_tile = [&](int kt, int slot) {
        int k0 = koff + kt * GBK;
        uint32_t aB = aStage0 + slot * GSTAGE_BYTES;
        uint32_t bB = bStage0 + slot * GSTAGE_BYTES;
        #pragma unroll
        for (int u = 0; u < 4; u++) {
            int f = tid + u * 256;
            int r = f >> 3, c = f & 7;
            cp_async16(aB + sw_off(r, c), A + (size_t)(bm + r) * K + k0 + c * 8, 16);
            int gb = bn + r;
            const __half* bsrc = B + (size_t)(gb < N ? gb : 0) * K + k0 + c * 8;
            cp_async16(bB + sw_off(r, c), bsrc, gb < N ? 16 : 0);
        }
        CP_COMMIT();
    };

    float acc[4][4][4];
    #pragma unroll
    for (int i = 0; i < 4; i++)
        #pragma unroll
        for (int j = 0; j < 4; j++)
            #pragma unroll
            for (int v = 0; v < 4; v++) acc[i][j][v] = 0.f;

    load_tile(0, 0);
    load_tile(1, 1);

    for (int kt = 0; kt < T; kt++) {
        if (kt < T - 1) asm volatile("cp.async.wait_group 1;" ::: "memory");
        else            asm volatile("cp.async.wait_group 0;" ::: "memory");
        __syncthreads();
        if (kt + 2 < T) load_tile(kt + 2, (kt + 2) % 3);

        int slot = kt % GSTAGES;
        uint32_t aS = aStage0 + slot * GSTAGE_BYTES;
        uint32_t bS = bStage0 + slot * GSTAGE_BYTES;

        #pragma unroll
        for (int kk = 0; kk < 4; kk++) {       // 4 x k16 per BK=64
            uint32_t af[4][4];
            uint32_t bf[4][2];
            #pragma unroll
            for (int mb = 0; mb < 4; mb++) {
                int row = wm * 64 + mb * 16 + (lane & 15);
                int chunk = kk * 2 + (lane >> 4);
                LDSM_X4(af[mb], aS + sw_off(row, chunk));
            }
            #pragma unroll
            for (int p = 0; p < 2; p++) {
                uint32_t r4[4];
                int n = wn * 32 + p * 16 + (lane & 7) + ((lane >> 4) << 3);
                int chunk = kk * 2 + ((lane >> 3) & 1);
                LDSM_X4(r4, bS + sw_off(n, chunk));
                bf[p*2  ][0] = r4[0]; bf[p*2  ][1] = r4[1];
                bf[p*2+1][0] = r4[2]; bf[p*2+1][1] = r4[3];
            }
            #pragma unroll
            for (int mb = 0; mb < 4; mb++)
                #pragma unroll
                for (int nb = 0; nb < 4; nb++)
                    MMA_F16(acc[mb][nb], af[mb], bf[nb]);
        }
    }

    if (EPI == EPI_PART) {
        float* Cp = C + (size_t)blockIdx.z * M * (size_t)N;
        #pragma unroll
        for (int mb = 0; mb < 4; mb++) {
            int r0 = bm + wm * 64 + mb * 16 + (lane >> 2);
            #pragma unroll
            for (int nb = 0; nb < 4; nb++) {
                int col = bn + wn * 32 + nb * 8 + (lane & 3) * 2;
                #pragma unroll
                for (int half = 0; half < 2; half++) {
                    size_t row = (size_t)(r0 + half * 8);
                    *(float2*)(Cp + row * (size_t)N + col) =
                        make_float2(acc[mb][nb][half*2], acc[mb][nb][half*2 + 1]);
                }
            }
        }
        return;
    }

    if (EPI == EPI_LOSS) {
        #pragma unroll
        for (int mb = 0; mb < 4; mb++) {
            #pragma unroll
            for (int half = 0; half < 2; half++) {
                int rrow = bm + wm * 64 + mb * 16 + (lane >> 2) + half * 8;
                float vals[8];
                float vmax = -1e30f;
                #pragma unroll
                for (int nb = 0; nb < 4; nb++) {
                    int col = bn + wn * 32 + nb * 8 + (lane & 3) * 2;
                    float v0 = acc[mb][nb][half*2 + 0];
                    float v1 = acc[mb][nb][half*2 + 1];
                    size_t base = (size_t)rrow * N + col;
                    if (col + 1 < N) {
                        if ((base & 1) == 0) *(float2*)(C + base) = make_float2(v0, v1);
                        else { C[base] = v0; C[base + 1] = v1; }
                    } else if (col < N) {
                        C[base] = v0;
                    }
                    vals[nb*2    ] = (col     < N) ? v0 : -1e30f;
                    vals[nb*2 + 1] = (col + 1 < N) ? v1 : -1e30f;
                    vmax = fmaxf(vmax, fmaxf(vals[nb*2], vals[nb*2+1]));
                }
                vmax = fmaxf(vmax, __shfl_xor_sync(0xffffffffu, vmax, 1));
                vmax = fmaxf(vmax, __shfl_xor_sync(0xffffffffu, vmax, 2));
                float s = 0.f;
                #pragma unroll
                for (int j = 0; j < 8; j++) s += fast_exp(vals[j] - vmax);
                s += __shfl_xor_sync(0xffffffffu, s, 1);
                s += __shfl_xor_sync(0xffffffffu, s, 2);
                if ((lane & 3) == 0) {
                    size_t po = (size_t)rrow * PCOLS + ntile * 4 + wn;
                    Pm[po] = vmax;
                    Psum[po] = s;
                }
            }
        }
        return;
    }

    // EPI_HALF (fp16 out + bias) / EPI_GELU (fp16 out + bias + gelu)
    #pragma unroll
    for (int mb = 0; mb < 4; mb++) {
        int r0 = bm + wm * 64 + mb * 16 + (lane >> 2);
        #pragma unroll
        for (int nb = 0; nb < 4; nb++) {
            int col = bn + wn * 32 + nb * 8 + (lane & 3) * 2;
            #pragma unroll
            for (int half = 0; half < 2; half++) {
                size_t row = (size_t)(r0 + half * 8);
                float v0 = acc[mb][nb][half*2 + 0];
                float v1 = acc[mb][nb][half*2 + 1];
                size_t base = row * (size_t)N + col;
                if (col + 1 < N) {
                    if (bias) { v0 += bias[col]; v1 += bias[col+1]; }
                    if (EPI == EPI_GELU) {
                        v0 = 0.5f*v0*(1.0f + erff(v0*0.70710678118654752f));
                        v1 = 0.5f*v1*(1.0f + erff(v1*0.70710678118654752f));
                    }
                    *(__half2*)((__half*)C + base) = __floats2half2_rn(v0, v1);
                } else if (col < N) {
                    if (bias) v0 += bias[col];
                    if (EPI == EPI_GELU) v0 = 0.5f*v0*(1.0f + erff(v0*0.70710678118654752f));
                    ((__half*)C)[base] = __float2half_rn(v0);
                }
            }
        }
    }
}

// ---------------- fp32 -> fp16 weight conversion ------------------------------
__global__ void __launch_bounds__(256) cvt_half_k(const float* __restrict__ src,
                                                  __half* __restrict__ dst, int n4)
{
    int i = blockIdx.x * 256 + threadIdx.x;
    if (i < n4) {
        float4 v = ((const float4*)src)[i];
        ((__half2*)dst)[i*2    ] = __floats2half2_rn(v.x, v.y);
        ((__half2*)dst)[i*2 + 1] = __floats2half2_rn(v.z, v.w);
    }
}

// ---------------- fused split-K reduce + residual + LayerNorm ----------------
__global__ void __launch_bounds__(256) splitk_ln_k(
    const float* __restrict__ part, const float* __restrict__ bias,
    float* __restrict__ x,
    const float* __restrict__ lw, const float* __restrict__ lb,
    __half* __restrict__ h)
{
    int n = blockIdx.x;
    int i = threadIdx.x;
    float4 a = ((const float4*)(part + (size_t)n * DMODEL))[i];
    float4 b = ((const float4*)(part + (size_t)NTOK * DMODEL + (size_t)n * DMODEL))[i];
    float4 c = ((const float4*)bias)[i];
    float4 r = ((float4*)(x + (size_t)n * DMODEL))[i];
    float4 v = make_float4(a.x + b.x + c.x + r.x, a.y + b.y + c.y + r.y,
                           a.z + b.z + c.z + r.z, a.w + b.w + c.w + r.w);
    ((float4*)(x + (size_t)n * DMODEL))[i] = v;

    float s  = v.x + v.y + v.z + v.w;
    float ss = v.x*v.x + v.y*v.y + v.z*v.z + v.w*v.w;
    #pragma unroll
    for (int o = 16; o; o >>= 1) {
        s  += __shfl_xor_sync(0xffffffffu, s,  o);
        ss += __shfl_xor_sync(0xffffffffu, ss, o);
    }
    __shared__ float sm[8], sm2[8];
    int wid = i >> 5;
    if ((i & 31) == 0) { sm[wid] = s; sm2[wid] = ss; }
    __syncthreads();
    if (i < 32) {
        s  = (i < 8) ? sm [i] : 0.f;
        ss = (i < 8) ? sm2[i] : 0.f;
        #pragma unroll
        for (int o = 4; o; o >>= 1) {
            s  += __shfl_xor_sync(0xffffffffu, s,  o);
            ss += __shfl_xor_sync(0xffffffffu, ss, o);
        }
        if (i == 0) { sm[0] = s; sm2[0] = ss; }
    }
    __syncthreads();
    float mean = sm[0] * (1.0f/DMODEL);
    float var  = sm2[0] * (1.0f/DMODEL) - mean*mean;
    float inv  = rsqrtf(var + 1e-5f);
    float4 gw = ((const float4*)lw)[i];
    float4 gb = ((const float4*)lb)[i];
    __half* hrow = h + (size_t)n * DMODEL + i * 4;
    *(__half2*)(hrow    ) = __floats2half2_rn((v.x - mean)*inv*gw.x + gb.x,
                                              (v.y - mean)*inv*gw.y + gb.y);
    *(__half2*)(hrow + 2) = __floats2half2_rn((v.z - mean)*inv*gw.z + gb.z,
                                              (v.w - mean)*inv*gw.w + gb.w);
}

// ---------------- embedding --------------------------------------------------
__global__ void embed_k(const int* __restrict__ idx,
                        const float* __restrict__ wte,
                        const float* __restrict__ wpe,
                        float* __restrict__ x)
{
    int n = blockIdx.x;
    int tok = idx[n];
    int t = n % SEQ;
    const float4* a = (const float4*)(wte + (size_t)tok * DMODEL);
    const float4* p = (const float4*)(wpe + (size_t)t   * DMODEL);
    float4* o = (float4*)(x + (size_t)n * DMODEL);
    for (int i = threadIdx.x; i < DMODEL/4; i += blockDim.x) {
        float4 u = a[i], v = p[i];
        o[i] = make_float4(u.x+v.x, u.y+v.y, u.z+v.z, u.w+v.w);
    }
}

// ---------------- standalone layernorm (first ln1 only), fp16 out ------------
__global__ void __launch_bounds__(256) ln_k(const float* __restrict__ x,
                                            const float* __restrict__ w,
                                            const float* __restrict__ b,
                                            __half* __restrict__ out)
{
    int n = blockIdx.x;
    const float* row = x + (size_t)n * DMODEL;
    int i = threadIdx.x;
    float4 v = ((const float4*)row)[i];
    float s  = v.x + v.y + v.z + v.w;
    float ss = v.x*v.x + v.y*v.y + v.z*v.z + v.w*v.w;
    #pragma unroll
    for (int o = 16; o; o >>= 1) {
        s  += __shfl_xor_sync(0xffffffffu, s,  o);
        ss += __shfl_xor_sync(0xffffffffu, ss, o);
    }
    __shared__ float sm[8], sm2[8];
    int wid = i >> 5;
    if ((i & 31) == 0) { sm[wid] = s; sm2[wid] = ss; }
    __syncthreads();
    if (i < 32) {
        s  = (i < 8) ? sm [i] : 0.f;
        ss = (i < 8) ? sm2[i] : 0.f;
        #pragma unroll
        for (int o = 4; o; o >>= 1) {
            s  += __shfl_xor_sync(0xffffffffu, s,  o);
            ss += __shfl_xor_sync(0xffffffffu, ss, o);
        }
        if (i == 0) { sm[0] = s; sm2[0] = ss; }
    }
    __syncthreads();
    float mean = sm[0] * (1.0f/DMODEL);
    float var  = sm2[0] * (1.0f/DMODEL) - mean*mean;
    float inv  = rsqrtf(var + 1e-5f);
    float4 gw = ((const float4*)w)[i];
    float4 gb = ((const float4*)b)[i];
    __half* orow = out + (size_t)n * DMODEL + i * 4;
    *(__half2*)(orow    ) = __floats2half2_rn((v.x - mean)*inv*gw.x + gb.x,
                                              (v.y - mean)*inv*gw.y + gb.y);
    *(__half2*)(orow + 2) = __floats2half2_rn((v.z - mean)*inv*gw.z + gb.z,
                                              (v.w - mean)*inv*gw.w + gb.w);
}

// ---------------- fp16 tensor-core flash attention ----------------------------
// 128 threads (4 warps), Q tile 64, K tile 64, m16n8k16 HMMA.
// smem: Qs 8K | Ks 8K | VT 8K | Ps 8K = 32KB (+pad). V rows prefetched into
// registers BEFORE the reuse barrier to hide LDG latency.
#define AT_SMEM 33024

__global__ void __launch_bounds__(128) attn_k(const __half* __restrict__ qkv,
                                              __half* __restrict__ y)
{
    extern __shared__ char sm8[];
    uint32_t qsB = smem_to_u32(sm8);
    uint32_t ksB = qsB + 8192;
    uint32_t vtB = qsB + 16384;
    uint32_t psB = qsB + 24576;

    const int bh = blockIdx.y;
    const int b = bh >> 4, h = bh & 15;
    const int q0 = (gridDim.x - 1 - blockIdx.x) * 64;   // heavy tiles first
    const int tid = threadIdx.x, wid = tid >> 5, lane = tid & 31;
    const int wq = wid * 16;
    const int qtr = lane >> 2;
    const int qlc = lane & 3;

    // Q tile via cp.async (raw; scale folded into scores)
    #pragma unroll
    for (int u = 0; u < 4; u++) {
        int f = tid + u * 128;
        int r = f >> 3, c = f & 7;
        cp_async16(qsB + sw_off(r, c),
                   qkv + (size_t)(b*SEQ + q0 + r)*3*DMODEL + h*HDIM + c*8, 16);
    }
    CP_COMMIT();

    float m0 = -1e30f, m1 = -1e30f, l0 = 0.f, l1 = 0.f;
    float o[8][4];
    #pragma unroll
    for (int nb = 0; nb < 8; nb++)
        #pragma unroll
        for (int v = 0; v < 4; v++) o[nb][v] = 0.f;

    const int row0 = q0 + wq + qtr;

    for (int k0 = 0; k0 < q0 + 64; k0 += 64) {
        // ---- prefetch V rows into registers (no smem dependency) ----
        uint4 vreg[4];
        #pragma unroll
        for (int u = 0; u < 4; u++) {
            int f = tid + u * 128;
            int kt = f >> 3, c = f & 7;
            vreg[u] = *(const uint4*)(qkv + (size_t)(b*SEQ + k0 + kt)*3*DMODEL + 2*DMODEL + h*HDIM + c*8);
        }

        __syncthreads();     // smem reuse barrier
        // K tile via cp.async
        #pragma unroll
        for (int u = 0; u < 4; u++) {
            int f = tid + u * 128;
            int r = f >> 3, c = f & 7;
            cp_async16(ksB + sw_off(r, c),
                       qkv + (size_t)(b*SEQ + k0 + r)*3*DMODEL + DMODEL + h*HDIM + c*8, 16);
        }
        CP_COMMIT();
        // V^T scatter from registers
        #pragma unroll
        for (int u = 0; u < 4; u++) {
            int f = tid + u * 128;
            int kt = f >> 3, c = f & 7;
            uint32_t w[4] = {vreg[u].x, vreg[u].y, vreg[u].z, vreg[u].w};
            #pragma unroll
            for (int j = 0; j < 4; j++) {
                #pragma unroll
                for (int e = 0; e < 2; e++) {
                    int d = c*8 + j*2 + e;
                    uint32_t off = (uint32_t)(d * 128 + (((kt >> 3) ^ (d & 7)) << 4) + (kt & 7) * 2);
                    *(__half*)(sm8 + 16384 + off) = ((__half*)&w[j])[e];
                }
            }
        }
        asm volatile("cp.async.wait_group 0;" ::: "memory");
        __syncthreads();

        // ---- QK^T (fp16 k16) ----
        float sc[8][4];
        #pragma unroll
        for (int nb = 0; nb < 8; nb++)
            #pragma unroll
            for (int v = 0; v < 4; v++) sc[nb][v] = 0.f;

        #pragma unroll
        for (int ks = 0; ks < 4; ks++) {
            uint32_t af[4];
            LDSM_X4(af, qsB + sw_off(wq + (lane & 15), ks*2 + (lane >> 4)));
            #pragma unroll
            for (int g = 0; g < 4; g++) {
                uint32_t r4[4];
                int n = g * 16 + (lane & 7) + ((lane >> 4) << 3);
                int ch = ks*2 + ((lane >> 3) & 1);
                LDSM_X4(r4, ksB + sw_off(n, ch));
                uint32_t b0[2] = {r4[0], r4[1]};
                uint32_t b1[2] = {r4[2], r4[3]};
                MMA_F16(sc[g*2    ], af, b0);
                MMA_F16(sc[g*2 + 1], af, b1);
            }
        }
        // scale 1/sqrt(64)
        #pragma unroll
        for (int nb = 0; nb < 8; nb++)
            #pragma unroll
            for (int v = 0; v < 4; v++) sc[nb][v] *= 0.125f;

        // ---- causal mask ----
        if (k0 + 63 > q0 + wq) {
            #pragma unroll
            for (int nb = 0; nb < 8; nb++) {
                int c0 = k0 + nb*8 + qlc*2;
                if (c0     > row0    ) sc[nb][0] = -1e30f;
                if (c0 + 1 > row0    ) sc[nb][1] = -1e30f;
                if (c0     > row0 + 8) sc[nb][2] = -1e30f;
                if (c0 + 1 > row0 + 8) sc[nb][3] = -1e30f;
            }
        }

        // ---- online softmax ----
        float mx0 = sc[0][0], mx1 = sc[0][2];
        #pragma unroll
        for (int nb = 0; nb < 8; nb++) {
            mx0 = fmaxf(mx0, fmaxf(sc[nb][0], sc[nb][1]));
            mx1 = fmaxf(mx1, fmaxf(sc[nb][2], sc[nb][3]));
        }
        mx0 = fmaxf(mx0, __shfl_xor_sync(0xffffffffu, mx0, 1));
        mx0 = fmaxf(mx0, __shfl_xor_sync(0xffffffffu, mx0, 2));
        mx1 = fmaxf(mx1, __shfl_xor_sync(0xffffffffu, mx1, 1));
        mx1 = fmaxf(mx1, __shfl_xor_sync(0xffffffffu, mx1, 2));
        float nm0 = fmaxf(m0, mx0), nm1 = fmaxf(m1, mx1);
        float corr0 = fast_exp(m0 - nm0), corr1 = fast_exp(m1 - nm1);
        float s0 = 0.f, s1 = 0.f;
        #pragma unroll
        for (int nb = 0; nb < 8; nb++) {
            sc[nb][0] = fast_exp(sc[nb][0] - nm0);
            sc[nb][1] = fast_exp(sc[nb][1] - nm0);
            sc[nb][2] = fast_exp(sc[nb][2] - nm1);
            sc[nb][3] = fast_exp(sc[nb][3] - nm1);
            s0 += sc[nb][0] + sc[nb][1];
            s1 += sc[nb][2] + sc[nb][3];
        }
        s0 += __shfl_xor_sync(0xffffffffu, s0, 1);
        s0 += __shfl_xor_sync(0xffffffffu, s0, 2);
        s1 += __shfl_xor_sync(0xffffffffu, s1, 1);
        s1 += __shfl_xor_sync(0xffffffffu, s1, 2);
        l0 = l0 * corr0 + s0;  m0 = nm0;
        l1 = l1 * corr1 + s1;  m1 = nm1;
        #pragma unroll
        for (int nb = 0; nb < 8; nb++) {
            o[nb][0] *= corr0; o[nb][1] *= corr0;
            o[nb][2] *= corr1; o[nb][3] *= corr1;
        }

        // ---- P frags -> Ps (fp16, swizzled rows of 64 halfs), warp-local ----
        {
            int pr = wq + qtr;
            #pragma unroll
            for (int nb = 0; nb < 8; nb++) {
                int pc = nb*8 + qlc*2;
                uint32_t off0 = (uint32_t)(pr * 128 + (((pc >> 3) ^ (pr & 7)) << 4) + (pc & 7) * 2);
                *(__half2*)(sm8 + 24576 + off0) = __floats2half2_rn(sc[nb][0], sc[nb][1]);
                int pr1 = pr + 8;
                uint32_t off1 = (uint32_t)(pr1 * 128 + (((pc >> 3) ^ (pr1 & 7)) << 4) + (pc & 7) * 2);
                *(__half2*)(sm8 + 24576 + off1) = __floats2half2_rn(sc[nb][2], sc[nb][3]);
            }
        }
        __syncwarp();

        // ---- P @ V (fp16 k16) ----
        #pragma unroll
        for (int ks = 0; ks < 4; ks++) {
            uint32_t pa[4];
            LDSM_X4(pa, psB + sw_off(wq + (lane & 15), ks*2 + (lane >> 4)));
            #pragma unroll
            for (int g = 0; g < 4; g++) {
                uint32_t r4[4];
                int n = g * 16 + (lane & 7) + ((lane >> 4) << 3);
                int ch = ks*2 + ((lane >> 3) & 1);
                LDSM_X4(r4, vtB + sw_off(n, ch));
                uint32_t b0[2] = {r4[0], r4[1]};
                uint32_t b1[2] = {r4[2], r4[3]};
                MMA_F16(o[g*2    ], pa, b0);
                MMA_F16(o[g*2 + 1], pa, b1);
            }
        }
        __syncwarp();
    }

    // fp16 output (feeds proj GEMM A)
    float inv0 = 1.0f / l0, inv1 = 1.0f / l1;
    size_t g0 = (size_t)(b*SEQ + q0 + wq + qtr) * DMODEL + h*HDIM;
    size_t g1 = g0 + 8 * DMODEL;
    #pragma unroll
    for (int nb = 0; nb < 8; nb++) {
        int d0 = nb*8 + qlc*2;
        *(__half2*)(y + g0 + d0) = __floats2half2_rn(o[nb][0]*inv0, o[nb][1]*inv0);
        *(__half2*)(y + g1 + d0) = __floats2half2_rn(o[nb][2]*inv1, o[nb][3]*inv1);
    }
}

// ---------------- loss reduce over fused partials ----------------------------
__global__ void __launch_bounds__(256) rowloss2_k(const float* __restrict__ pm,
                                                  const float* __restrict__ ps,
                                                  const float* __restrict__ logits,
                                                  const int* __restrict__ tgt,
                                                  float* __restrict__ rowloss)
{
    int n = blockIdx.x;
    const float* rm = pm + (size_t)n * PCOLS;
    const float* rs = ps + (size_t)n * PCOLS;
    float m = -1e30f, ssum = 0.f;
    for (int i = threadIdx.x; i < PCOLS; i += 256) {
        float m2 = rm[i], s2 = rs[i];
        float M = fmaxf(m, m2);
        ssum = ssum*fast_exp(m - M) + s2*fast_exp(m2 - M);
        m = M;
    }
    #pragma unroll
    for (int o = 16; o; o >>= 1) {
        float m2 = __shfl_xor_sync(0xffffffffu, m, o);
        float s2 = __shfl_xor_sync(0xffffffffu, ssum, o);
        float M  = fmaxf(m, m2);
        ssum = ssum*fast_exp(m - M) + s2*fast_exp(m2 - M);
        m = M;
    }
    __shared__ float smm[8], sms[8];
    int wid = threadIdx.x >> 5;
    if ((threadIdx.x & 31) == 0) { smm[wid] = m; sms[wid] = ssum; }
    __syncthreads();
    if (threadIdx.x == 0) {
        float M = smm[0], S = sms[0];
        for (int i = 1; i < 8; i++) {
            float M2 = fmaxf(M, smm[i]);
            S = S*fast_exp(M - M2) + sms[i]*fast_exp(smm[i] - M2);
            M = M2;
        }
        float lse = M + logf(S);
        rowloss[n] = lse - logits[(size_t)n * VOCAB + tgt[n]];
    }
}

__global__ void finalize_k(const float* __restrict__ rowloss, float* __restrict__ out_loss)
{
    float s = 0.f;
    for (int i = threadIdx.x; i < NTOK; i += 256) s += rowloss[i];
    #pragma unroll
    for (int o = 16; o; o >>= 1) s += __shfl_xor_sync(0xffffffffu, s, o);
    __shared__ float sm[8];
    int wid = threadIdx.x >> 5;
    if ((threadIdx.x & 31) == 0) sm[wid] = s;
    __syncthreads();
    if (threadIdx.x == 0) {
        float t = 0.f;
        for (int i = 0; i < 8; i++) t += sm[i];
        *out_loss = t * (1.0f/NTOK);
    }
}

// ---------------- launch -----------------------------------------------------
extern "C" void kernel_launch(void* const* d_in, const int* in_sizes, int n_in,
                              void* d_out, int out_size)
{
    const int*   idx     = (const int*)  d_in[0];
    const int*   targets = (const int*)  d_in[1];
    const float* wte     = (const float*)d_in[2];
    const float* wpe     = (const float*)d_in[3];
    const float* ln1_w   = (const float*)d_in[4];
    const float* ln1_b   = (const float*)d_in[5];
    const float* attn_w  = (const float*)d_in[6];
    const float* attn_b  = (const float*)d_in[7];
    const float* proj_w  = (const float*)d_in[8];
    const float* proj_b  = (const float*)d_in[9];
    const float* ln2_w   = (const float*)d_in[10];
    const float* ln2_b   = (const float*)d_in[11];
    const float* fc_w    = (const float*)d_in[12];
    const float* fc_b    = (const float*)d_in[13];
    const float* fcp_w   = (const float*)d_in[14];
    const float* fcp_b   = (const float*)d_in[15];
    const float* lnf_w   = (const float*)d_in[16];
    const float* lnf_b   = (const float*)d_in[17];

    float *px, *ppart, *plogfb, *prl, *ppm, *pps;
    __half *ph, *pqkv, *patt, *pffn, *pwq, *pwp, *pwf, *pwf2, *pwv;
    cudaGetSymbolAddress((void**)&px,    g_x);
    cudaGetSymbolAddress((void**)&ph,    g_h);
    cudaGetSymbolAddress((void**)&pqkv,  g_qkv);
    cudaGetSymbolAddress((void**)&patt,  g_att);
    cudaGetSymbolAddress((void**)&pffn,  g_ffn);
    cudaGetSymbolAddress((void**)&ppart, g_part);
    cudaGetSymbolAddress((void**)&plogfb,g_logits_fallback);
    cudaGetSymbolAddress((void**)&prl,   g_rowloss);
    cudaGetSymbolAddress((void**)&ppm,   g_pm);
    cudaGetSymbolAddress((void**)&pps,   g_ps);
    cudaGetSymbolAddress((void**)&pwq,   g_wq);
    cudaGetSymbolAddress((void**)&pwp,   g_wp);
    cudaGetSymbolAddress((void**)&pwf,   g_wf);
    cudaGetSymbolAddress((void**)&pwf2,  g_wf2);
    cudaGetSymbolAddress((void**)&pwv,   g_wv);

    static bool attr_done = false;
    if (!attr_done) {
        cudaFuncSetAttribute((const void*)gemm_tc<EPI_HALF,0>,  cudaFuncAttributeMaxDynamicSharedMemorySize, GT_SMEM);
        cudaFuncSetAttribute((const void*)gemm_tc<EPI_GELU,0>,  cudaFuncAttributeMaxDynamicSharedMemorySize, GT_SMEM);
        cudaFuncSetAttribute((const void*)gemm_tc<EPI_PART,0>,  cudaFuncAttributeMaxDynamicSharedMemorySize, GT_SMEM);
        cudaFuncSetAttribute((const void*)gemm_tc<EPI_LOSS,1>,  cudaFuncAttributeMaxDynamicSharedMemorySize, GT_SMEM);
        cudaFuncSetAttribute((const void*)attn_k, cudaFuncAttributeMaxDynamicSharedMemorySize, AT_SMEM);
        attr_done = true;
    }

    const long long LOGN = (long long)NTOK * VOCAB;
    float* logits_ptr;
    float* loss_ptr = nullptr;
    if ((long long)out_size >= LOGN) {
        logits_ptr = (float*)d_out;
        if ((long long)out_size > LOGN) loss_ptr = (float*)d_out + LOGN;
    } else {
        logits_ptr = plogfb;
        loss_ptr = (float*)d_out;
    }

    // weight fp32->fp16 conversion (per launch)
    {
        long long nq  = (long long)LAYERS*3*DMODEL*DMODEL/4;
        long long np  = (long long)LAYERS*DMODEL*DMODEL/4;
        long long nf  = (long long)LAYERS*4*DMODEL*DMODEL/4;
        long long nv  = (long long)VOCAB*DMODEL/4;
        cvt_half_k<<<(int)((nq+255)/256), 256>>>(attn_w, pwq, (int)nq);
        cvt_half_k<<<(int)((np+255)/256), 256>>>(proj_w, pwp, (int)np);
        cvt_half_k<<<(int)((nf+255)/256), 256>>>(fc_w,  pwf,  (int)nf);
        cvt_half_k<<<(int)((nf+255)/256), 256>>>(fcp_w, pwf2, (int)nf);
        cvt_half_k<<<(int)((nv+255)/256), 256>>>(wte,   pwv,  (int)nv);
    }

    embed_k<<<NTOK, 256>>>(idx, wte, wpe, px);
    ln_k<<<NTOK, 256>>>(px, ln1_w, ln1_b, ph);

    dim3 gq (3*DMODEL/128, NTOK/128);       // 24 x 16
    dim3 gp2(DMODEL/128,   NTOK/128, 2);    //  8 x 16 x 2 (split-K)
    dim3 gf (4*DMODEL/128, NTOK/128);       // 32 x 16
    dim3 gv (NTOK/128, NVTILE);             // SWAP: x=M-tiles, y=N-tiles
    dim3 ga (SEQ/64, BATCH*NHEAD);

    for (int l = 0; l < LAYERS; l++) {
        gemm_tc<EPI_HALF,0><<<gq, 256, GT_SMEM>>>(ph, pwq + (size_t)l*3*DMODEL*DMODEL,
                                       attn_b + (size_t)l*3*DMODEL,
                                       (float*)pqkv, NTOK, 3*DMODEL, DMODEL, nullptr, nullptr);
        attn_k<<<ga, 128, AT_SMEM>>>(pqkv, patt);
        gemm_tc<EPI_PART,0><<<gp2, 256, GT_SMEM>>>(patt, pwp + (size_t)l*DMODEL*DMODEL,
                                        nullptr,
                                        ppart, NTOK, DMODEL, DMODEL, nullptr, nullptr);
        splitk_ln_k<<<NTOK, 256>>>(ppart, proj_b + (size_t)l*DMODEL, px,
                                   ln2_w + (size_t)l*DMODEL, ln2_b + (size_t)l*DMODEL, ph);
        gemm_tc<EPI_GELU,0><<<gf, 256, GT_SMEM>>>(ph, pwf + (size_t)l*4*DMODEL*DMODEL,
                                       fc_b + (size_t)l*4*DMODEL,
                                       (float*)pffn, NTOK, 4*DMODEL, DMODEL, nullptr, nullptr);
        gemm_tc<EPI_PART,0><<<gp2, 256, GT_SMEM>>>(pffn, pwf2 + (size_t)l*DMODEL*4*DMODEL,
                                        nullptr,
                                        ppart, NTOK, DMODEL, 4*DMODEL, nullptr, nullptr);
        const float* nw = (l + 1 < LAYERS) ? ln1_w + (size_t)(l+1)*DMODEL : lnf_w;
        const float* nb = (l + 1 < LAYERS) ? ln1_b + (size_t)(l+1)*DMODEL : lnf_b;
        splitk_ln_k<<<NTOK, 256>>>(ppart, fcp_b + (size_t)l*DMODEL, px, nw, nb, ph);
    }

    gemm_tc<EPI_LOSS,1><<<gv, 256, GT_SMEM>>>(ph, pwv, nullptr,
                                   logits_ptr, NTOK, VOCAB, DMODEL, ppm, pps);

    if (loss_ptr) {
        rowloss2_k<<<NTOK, 256>>>(ppm, pps, logits_ptr, targets, prl);
        finalize_k<<<1, 256>>>(prl, loss_ptr);
    }
}

// round 17
// speedup vs baseline: 1.1108x; 1.0050x over previous
#include <cuda_runtime.h>
#include <cuda_fp16.h>
#include <math.h>
#include <stdint.h>

// Problem constants
#define LAYERS 6
#define NHEAD  16
#define DMODEL 1024
#define HDIM   64
#define BATCH  2
#define SEQ    1024
#define NTOK   (BATCH*SEQ)     // 2048
#define VOCAB  50257
#define NVTILE ((VOCAB+127)/128)     // 393
#define PCOLS  (NVTILE*4)            // 1572 loss partials per row

// ---------------- scratch ----------------------------------------------------
__device__ float  g_x   [NTOK*DMODEL];
__device__ __half g_h   [NTOK*DMODEL];
__device__ __half g_qkv [NTOK*3*DMODEL];
__device__ __half g_att [NTOK*DMODEL];
__device__ __half g_ffn [NTOK*4*DMODEL];
__device__ float  g_part[2*(size_t)NTOK*DMODEL];    // split-K partials (proj/fcp)
__device__ float  g_logits_fallback[(size_t)NTOK*VOCAB];
__device__ float  g_rowloss[NTOK];
__device__ float  g_pm[(size_t)NTOK*PCOLS];
__device__ float  g_ps[(size_t)NTOK*PCOLS];
// fp16 weight copies (converted once per launch)
__device__ __half g_wq [(size_t)LAYERS*3*DMODEL*DMODEL];
__device__ __half g_wp [(size_t)LAYERS*DMODEL*DMODEL];
__device__ __half g_wf [(size_t)LAYERS*4*DMODEL*DMODEL];
__device__ __half g_wf2[(size_t)LAYERS*DMODEL*4*DMODEL];
__device__ __half g_wv [(size_t)VOCAB*DMODEL];

// ---------------- PTX helpers (sm_80-portable only) --------------------------
__device__ __forceinline__ uint32_t smem_to_u32(const void* p) {
    uint32_t a;
    asm("{ .reg .u64 t; cvta.to.shared.u64 t, %1; cvt.u32.u64 %0, t; }" : "=r"(a) : "l"(p));
    return a;
}
__device__ __forceinline__ void cp_async16(uint32_t dst, const void* src, int srcsize) {
    asm volatile("cp.async.cg.shared.global [%0], [%1], 16, %2;\n"
                 :: "r"(dst), "l"(src), "r"(srcsize) : "memory");
}
#define CP_COMMIT() asm volatile("cp.async.commit_group;" ::: "memory")

#define LDSM_X4(r, a) \
    asm volatile("ldmatrix.sync.aligned.m8n8.x4.shared.b16 {%0,%1,%2,%3}, [%4];" \
        : "=r"((r)[0]), "=r"((r)[1]), "=r"((r)[2]), "=r"((r)[3]) : "r"(a))

// fp16 MMA: m16n8k16, fp32 accumulate
#define MMA_F16(d, a, b) \
    asm volatile("mma.sync.aligned.m16n8k16.row.col.f32.f16.f16.f32 " \
        "{%0,%1,%2,%3}, {%4,%5,%6,%7}, {%8,%9}, {%0,%1,%2,%3};" \
        : "+f"((d)[0]), "+f"((d)[1]), "+f"((d)[2]), "+f"((d)[3]) \
        : "r"((a)[0]), "r"((a)[1]), "r"((a)[2]), "r"((a)[3]), "r"((b)[0]), "r"((b)[1]))

// MUFU-free exp: magic-number 2^n split + deg-5 poly (all FMA pipe).
__device__ __forceinline__ float fast_exp(float x) {
    x = fmaxf(x, -87.0f);
    float f = fminf(x * 1.44269504088896341f, 126.0f);
    float t = f + 12582912.0f;
    int bits = __float_as_int(t);
    int n = (bits & 0x007FFFFF) - 0x00400000;
    float r = f - (t - 12582912.0f);
    float p = 1.33335581e-3f;
    p = p * r + 9.61812911e-3f;
    p = p * r + 5.55041087e-2f;
    p = p * r + 2.40226507e-1f;
    p = p * r + 6.93147181e-1f;
    p = p * r + 1.0f;
    return p * __int_as_float((n + 127) << 23);
}

// ---------------- fp16 mma.sync NT GEMM: C[M,N] = A[M,K]*B[N,K]^T (+epi) -----
// CTA tile 128x128, 8 warps 2x4, warp tile 64x32, BK=64 halfs.
// Single-barrier 3-stage pipeline: preload 2, per iter wait -> barrier ->
// issue load(kt+2) -> compute(kt).
enum { EPI_HALF = 0, EPI_GELU = 1, EPI_LOSS = 3, EPI_PART = 4 };

#define GBM 128
#define GBK 64
#define GSTAGES 3
#define GSTAGE_BYTES (GBM*GBK*2)                 // 16384
#define GT_SMEM (1024 + 2*GSTAGES*GSTAGE_BYTES)  // 99328

__device__ __forceinline__ uint32_t sw_off(int r, int c /*16B chunk 0..7*/) {
    return (uint32_t)(r * 128 + ((c ^ (r & 7)) << 4));
}

template<int EPI, int SWAP>
__global__ void __launch_bounds__(256, 2) gemm_tc(
    const __half* __restrict__ A, const __half* __restrict__ B,
    const float* __restrict__ bias,
    float* __restrict__ C, int M, int N, int K,
    float* __restrict__ Pm, float* __restrict__ Psum)
{
    extern __shared__ char dsm[];
    const int tid  = threadIdx.x;
    const int wid  = tid >> 5;
    const int lane = tid & 31;
    const int wm = wid >> 2;
    const int wn = wid & 3;
    const int bm = (SWAP ? blockIdx.x : blockIdx.y) * 128;
    const int bn = (SWAP ? blockIdx.y : blockIdx.x) * 128;
    const int ntile = SWAP ? blockIdx.y : blockIdx.x;

    uint32_t sbase = (smem_to_u32(dsm) + 1023u) & ~1023u;
    uint32_t aStage0 = sbase;
    uint32_t bStage0 = sbase + GSTAGES * GSTAGE_BYTES;

    const int T = K / (GBK * gridDim.z);
    const int koff = blockIdx.z * T * GBK;

    auto load_tile = [&](int kt, int slot) {
        int k0 = koff + kt * GBK;
        uint32_t aB = aStage0 + slot * GSTAGE_BYTES;
        uint32_t bB = bStage0 + slot * GSTAGE_BYTES;
        #pragma unroll
        for (int u = 0; u < 4; u++) {
            int f = tid + u * 256;
            int r = f >> 3, c = f & 7;
            cp_async16(aB + sw_off(r, c), A + (size_t)(bm + r) * K + k0 + c * 8, 16);
            int gb = bn + r;
            const __half* bsrc = B + (size_t)(gb < N ? gb : 0) * K + k0 + c * 8;
            cp_async16(bB + sw_off(r, c), bsrc, gb < N ? 16 : 0);
        }
        CP_COMMIT();
    };

    float acc[4][4][4];
    #pragma unroll
    for (int i = 0; i < 4; i++)
        #pragma unroll
        for (int j = 0; j < 4; j++)
            #pragma unroll
            for (int v = 0; v < 4; v++) acc[i][j][v] = 0.f;

    load_tile(0, 0);
    load_tile(1, 1);

    for (int kt = 0; kt < T; kt++) {
        if (kt < T - 1) asm volatile("cp.async.wait_group 1;" ::: "memory");
        else            asm volatile("cp.async.wait_group 0;" ::: "memory");
        __syncthreads();
        if (kt + 2 < T) load_tile(kt + 2, (kt + 2) % 3);

        int slot = kt % GSTAGES;
        uint32_t aS = aStage0 + slot * GSTAGE_BYTES;
        uint32_t bS = bStage0 + slot * GSTAGE_BYTES;

        #pragma unroll
        for (int kk = 0; kk < 4; kk++) {       // 4 x k16 per BK=64
            uint32_t af[4][4];
            uint32_t bf[4][2];
            #pragma unroll
            for (int mb = 0; mb < 4; mb++) {
                int row = wm * 64 + mb * 16 + (lane & 15);
                int chunk = kk * 2 + (lane >> 4);
                LDSM_X4(af[mb], aS + sw_off(row, chunk));
            }
            #pragma unroll
            for (int p = 0; p < 2; p++) {
                uint32_t r4[4];
                int n = wn * 32 + p * 16 + (lane & 7) + ((lane >> 4) << 3);
                int chunk = kk * 2 + ((lane >> 3) & 1);
                LDSM_X4(r4, bS + sw_off(n, chunk));
                bf[p*2  ][0] = r4[0]; bf[p*2  ][1] = r4[1];
                bf[p*2+1][0] = r4[2]; bf[p*2+1][1] = r4[3];
            }
            #pragma unroll
            for (int mb = 0; mb < 4; mb++)
                #pragma unroll
                for (int nb = 0; nb < 4; nb++)
                    MMA_F16(acc[mb][nb], af[mb], bf[nb]);
        }
    }

    if (EPI == EPI_PART) {
        float* Cp = C + (size_t)blockIdx.z * M * (size_t)N;
        #pragma unroll
        for (int mb = 0; mb < 4; mb++) {
            int r0 = bm + wm * 64 + mb * 16 + (lane >> 2);
            #pragma unroll
            for (int nb = 0; nb < 4; nb++) {
                int col = bn + wn * 32 + nb * 8 + (lane & 3) * 2;
                #pragma unroll
                for (int half = 0; half < 2; half++) {
                    size_t row = (size_t)(r0 + half * 8);
                    *(float2*)(Cp + row * (size_t)N + col) =
                        make_float2(acc[mb][nb][half*2], acc[mb][nb][half*2 + 1]);
                }
            }
        }
        return;
    }

    if (EPI == EPI_LOSS) {
        #pragma unroll
        for (int mb = 0; mb < 4; mb++) {
            #pragma unroll
            for (int half = 0; half < 2; half++) {
                int rrow = bm + wm * 64 + mb * 16 + (lane >> 2) + half * 8;
                float vals[8];
                float vmax = -1e30f;
                #pragma unroll
                for (int nb = 0; nb < 4; nb++) {
                    int col = bn + wn * 32 + nb * 8 + (lane & 3) * 2;
                    float v0 = acc[mb][nb][half*2 + 0];
                    float v1 = acc[mb][nb][half*2 + 1];
                    size_t base = (size_t)rrow * N + col;
                    if (col + 1 < N) {
                        if ((base & 1) == 0) *(float2*)(C + base) = make_float2(v0, v1);
                        else { C[base] = v0; C[base + 1] = v1; }
                    } else if (col < N) {
                        C[base] = v0;
                    }
                    vals[nb*2    ] = (col     < N) ? v0 : -1e30f;
                    vals[nb*2 + 1] = (col + 1 < N) ? v1 : -1e30f;
                    vmax = fmaxf(vmax, fmaxf(vals[nb*2], vals[nb*2+1]));
                }
                vmax = fmaxf(vmax, __shfl_xor_sync(0xffffffffu, vmax, 1));
                vmax = fmaxf(vmax, __shfl_xor_sync(0xffffffffu, vmax, 2));
                float s = 0.f;
                #pragma unroll
                for (int j = 0; j < 8; j++) s += fast_exp(vals[j] - vmax);
                s += __shfl_xor_sync(0xffffffffu, s, 1);
                s += __shfl_xor_sync(0xffffffffu, s, 2);
                if ((lane & 3) == 0) {
                    size_t po = (size_t)rrow * PCOLS + ntile * 4 + wn;
                    Pm[po] = vmax;
                    Psum[po] = s;
                }
            }
        }
        return;
    }

    // EPI_HALF (fp16 out + bias) / EPI_GELU (fp16 out + bias + gelu)
    #pragma unroll
    for (int mb = 0; mb < 4; mb++) {
        int r0 = bm + wm * 64 + mb * 16 + (lane >> 2);
        #pragma unroll
        for (int nb = 0; nb < 4; nb++) {
            int col = bn + wn * 32 + nb * 8 + (lane & 3) * 2;
            #pragma unroll
            for (int half = 0; half < 2; half++) {
                size_t row = (size_t)(r0 + half * 8);
                float v0 = acc[mb][nb][half*2 + 0];
                float v1 = acc[mb][nb][half*2 + 1];
                size_t base = row * (size_t)N + col;
                if (col + 1 < N) {
                    if (bias) { v0 += bias[col]; v1 += bias[col+1]; }
                    if (EPI == EPI_GELU) {
                        v0 = 0.5f*v0*(1.0f + erff(v0*0.70710678118654752f));
                        v1 = 0.5f*v1*(1.0f + erff(v1*0.70710678118654752f));
                    }
                    *(__half2*)((__half*)C + base) = __floats2half2_rn(v0, v1);
                } else if (col < N) {
                    if (bias) v0 += bias[col];
                    if (EPI == EPI_GELU) v0 = 0.5f*v0*(1.0f + erff(v0*0.70710678118654752f));
                    ((__half*)C)[base] = __float2half_rn(v0);
                }
            }
        }
    }
}

// ---------------- fp32 -> fp16 weight conversion ------------------------------
__global__ void __launch_bounds__(256) cvt_half_k(const float* __restrict__ src,
                                                  __half* __restrict__ dst, int n4)
{
    int i = blockIdx.x * 256 + threadIdx.x;
    if (i < n4) {
        float4 v = ((const float4*)src)[i];
        ((__half2*)dst)[i*2    ] = __floats2half2_rn(v.x, v.y);
        ((__half2*)dst)[i*2 + 1] = __floats2half2_rn(v.z, v.w);
    }
}

// ---------------- fused split-K reduce + residual + LayerNorm ----------------
__global__ void __launch_bounds__(256) splitk_ln_k(
    const float* __restrict__ part, const float* __restrict__ bias,
    float* __restrict__ x,
    const float* __restrict__ lw, const float* __restrict__ lb,
    __half* __restrict__ h)
{
    int n = blockIdx.x;
    int i = threadIdx.x;
    float4 a = ((const float4*)(part + (size_t)n * DMODEL))[i];
    float4 b = ((const float4*)(part + (size_t)NTOK * DMODEL + (size_t)n * DMODEL))[i];
    float4 c = ((const float4*)bias)[i];
    float4 r = ((float4*)(x + (size_t)n * DMODEL))[i];
    float4 v = make_float4(a.x + b.x + c.x + r.x, a.y + b.y + c.y + r.y,
                           a.z + b.z + c.z + r.z, a.w + b.w + c.w + r.w);
    ((float4*)(x + (size_t)n * DMODEL))[i] = v;

    float s  = v.x + v.y + v.z + v.w;
    float ss = v.x*v.x + v.y*v.y + v.z*v.z + v.w*v.w;
    #pragma unroll
    for (int o = 16; o; o >>= 1) {
        s  += __shfl_xor_sync(0xffffffffu, s,  o);
        ss += __shfl_xor_sync(0xffffffffu, ss, o);
    }
    __shared__ float sm[8], sm2[8];
    int wid = i >> 5;
    if ((i & 31) == 0) { sm[wid] = s; sm2[wid] = ss; }
    __syncthreads();
    if (i < 32) {
        s  = (i < 8) ? sm [i] : 0.f;
        ss = (i < 8) ? sm2[i] : 0.f;
        #pragma unroll
        for (int o = 4; o; o >>= 1) {
            s  += __shfl_xor_sync(0xffffffffu, s,  o);
            ss += __shfl_xor_sync(0xffffffffu, ss, o);
        }
        if (i == 0) { sm[0] = s; sm2[0] = ss; }
    }
    __syncthreads();
    float mean = sm[0] * (1.0f/DMODEL);
    float var  = sm2[0] * (1.0f/DMODEL) - mean*mean;
    float inv  = rsqrtf(var + 1e-5f);
    float4 gw = ((const float4*)lw)[i];
    float4 gb = ((const float4*)lb)[i];
    __half* hrow = h + (size_t)n * DMODEL + i * 4;
    *(__half2*)(hrow    ) = __floats2half2_rn((v.x - mean)*inv*gw.x + gb.x,
                                              (v.y - mean)*inv*gw.y + gb.y);
    *(__half2*)(hrow + 2) = __floats2half2_rn((v.z - mean)*inv*gw.z + gb.z,
                                              (v.w - mean)*inv*gw.w + gb.w);
}

// ---------------- fused embedding + first LayerNorm ---------------------------
__global__ void __launch_bounds__(256) embed_ln_k(
    const int* __restrict__ idx,
    const float* __restrict__ wte, const float* __restrict__ wpe,
    const float* __restrict__ lw, const float* __restrict__ lb,
    float* __restrict__ x, __half* __restrict__ h)
{
    int n = blockIdx.x;
    int tok = idx[n];
    int t = n % SEQ;
    int i = threadIdx.x;
    float4 u = ((const float4*)(wte + (size_t)tok * DMODEL))[i];
    float4 p = ((const float4*)(wpe + (size_t)t   * DMODEL))[i];
    float4 v = make_float4(u.x+p.x, u.y+p.y, u.z+p.z, u.w+p.w);
    ((float4*)(x + (size_t)n * DMODEL))[i] = v;

    float s  = v.x + v.y + v.z + v.w;
    float ss = v.x*v.x + v.y*v.y + v.z*v.z + v.w*v.w;
    #pragma unroll
    for (int o = 16; o; o >>= 1) {
        s  += __shfl_xor_sync(0xffffffffu, s,  o);
        ss += __shfl_xor_sync(0xffffffffu, ss, o);
    }
    __shared__ float sm[8], sm2[8];
    int wid = i >> 5;
    if ((i & 31) == 0) { sm[wid] = s; sm2[wid] = ss; }
    __syncthreads();
    if (i < 32) {
        s  = (i < 8) ? sm [i] : 0.f;
        ss = (i < 8) ? sm2[i] : 0.f;
        #pragma unroll
        for (int o = 4; o; o >>= 1) {
            s  += __shfl_xor_sync(0xffffffffu, s,  o);
            ss += __shfl_xor_sync(0xffffffffu, ss, o);
        }
        if (i == 0) { sm[0] = s; sm2[0] = ss; }
    }
    __syncthreads();
    float mean = sm[0] * (1.0f/DMODEL);
    float var  = sm2[0] * (1.0f/DMODEL) - mean*mean;
    float inv  = rsqrtf(var + 1e-5f);
    float4 gw = ((const float4*)lw)[i];
    float4 gb = ((const float4*)lb)[i];
    __half* hrow = h + (size_t)n * DMODEL + i * 4;
    *(__half2*)(hrow    ) = __floats2half2_rn((v.x - mean)*inv*gw.x + gb.x,
                                              (v.y - mean)*inv*gw.y + gb.y);
    *(__half2*)(hrow + 2) = __floats2half2_rn((v.z - mean)*inv*gw.z + gb.z,
                                              (v.w - mean)*inv*gw.w + gb.w);
}

// ---------------- fp16 flash attention, double-buffered K/V -------------------
// 128 threads (4 warps), Q tile 64, K tile 64, m16n8k16 HMMA.
// smem: Qs 8K | Ks[2] 8K each | VT[2] 8K each | Ps 8K = 48KB (+pad).
// K_{i+1} cp.async issued at top of iter i (other buffer) -> latency hidden.
#define AT_SMEM 49408

__global__ void __launch_bounds__(128) attn_k(const __half* __restrict__ qkv,
                                              __half* __restrict__ y)
{
    extern __shared__ char sm8[];
    uint32_t qsB = smem_to_u32(sm8);
    const uint32_t ksOff[2] = {8192, 16384};
    const uint32_t vtOff[2] = {24576, 32768};
    uint32_t psB = qsB + 40960;

    const int bh = blockIdx.y;
    const int b = bh >> 4, h = bh & 15;
    const int q0 = (gridDim.x - 1 - blockIdx.x) * 64;   // heavy tiles first
    const int tid = threadIdx.x, wid = tid >> 5, lane = tid & 31;
    const int wq = wid * 16;
    const int qtr = lane >> 2;
    const int qlc = lane & 3;

    // Q tile via cp.async (group 0 with K0 below)
    #pragma unroll
    for (int u = 0; u < 4; u++) {
        int f = tid + u * 128;
        int r = f >> 3, c = f & 7;
        cp_async16(qsB + sw_off(r, c),
                   qkv + (size_t)(b*SEQ + q0 + r)*3*DMODEL + h*HDIM + c*8, 16);
    }
    // K0 tile via cp.async into ks[0]
    #pragma unroll
    for (int u = 0; u < 4; u++) {
        int f = tid + u * 128;
        int r = f >> 3, c = f & 7;
        cp_async16(qsB + ksOff[0] + sw_off(r, c),
                   qkv + (size_t)(b*SEQ + r)*3*DMODEL + DMODEL + h*HDIM + c*8, 16);
    }
    CP_COMMIT();
    // V0 rows into registers
    uint4 vreg[4];
    #pragma unroll
    for (int u = 0; u < 4; u++) {
        int f = tid + u * 128;
        int kt = f >> 3, c = f & 7;
        vreg[u] = *(const uint4*)(qkv + (size_t)(b*SEQ + kt)*3*DMODEL + 2*DMODEL + h*HDIM + c*8);
    }

    float m0 = -1e30f, m1 = -1e30f, l0 = 0.f, l1 = 0.f;
    float o[8][4];
    #pragma unroll
    for (int nb = 0; nb < 8; nb++)
        #pragma unroll
        for (int v = 0; v < 4; v++) o[nb][v] = 0.f;

    const int row0 = q0 + wq + qtr;
    const int T = q0 / 64 + 1;

    for (int i = 0; i < T; i++) {
        const int s = i & 1, sn = s ^ 1;
        const int k0 = i * 64;

        asm volatile("cp.async.wait_group 0;" ::: "memory");
        __syncthreads();      // K_i (and Q) visible; prior reads of ks[sn], vt[s] done

        // issue K_{i+1} into the alternate buffer (latency hidden this iter)
        if (i + 1 < T) {
            #pragma unroll
            for (int u = 0; u < 4; u++) {
                int f = tid + u * 128;
                int r = f >> 3, c = f & 7;
                cp_async16(qsB + ksOff[sn] + sw_off(r, c),
                           qkv + (size_t)(b*SEQ + k0 + 64 + r)*3*DMODEL + DMODEL + h*HDIM + c*8, 16);
            }
            CP_COMMIT();
        }

        // scatter V_i (registers) -> vt[s]
        #pragma unroll
        for (int u = 0; u < 4; u++) {
            int f = tid + u * 128;
            int kt = f >> 3, c = f & 7;
            uint32_t w[4] = {vreg[u].x, vreg[u].y, vreg[u].z, vreg[u].w};
            #pragma unroll
            for (int j = 0; j < 4; j++) {
                #pragma unroll
                for (int e = 0; e < 2; e++) {
                    int d = c*8 + j*2 + e;
                    uint32_t off = (uint32_t)(d * 128 + (((kt >> 3) ^ (d & 7)) << 4) + (kt & 7) * 2);
                    *(__half*)(sm8 + vtOff[s] + off) = ((__half*)&w[j])[e];
                }
            }
        }
        // prefetch V_{i+1} into registers
        if (i + 1 < T) {
            #pragma unroll
            for (int u = 0; u < 4; u++) {
                int f = tid + u * 128;
                int kt = f >> 3, c = f & 7;
                vreg[u] = *(const uint4*)(qkv + (size_t)(b*SEQ + k0 + 64 + kt)*3*DMODEL + 2*DMODEL + h*HDIM + c*8);
            }
        }

        // ---- QK^T (fp16 k16) on ks[s] ----
        uint32_t ksB = qsB + ksOff[s];
        float sc[8][4];
        #pragma unroll
        for (int nb = 0; nb < 8; nb++)
            #pragma unroll
            for (int v = 0; v < 4; v++) sc[nb][v] = 0.f;

        #pragma unroll
        for (int ks = 0; ks < 4; ks++) {
            uint32_t af[4];
            LDSM_X4(af, qsB + sw_off(wq + (lane & 15), ks*2 + (lane >> 4)));
            #pragma unroll
            for (int g = 0; g < 4; g++) {
                uint32_t r4[4];
                int n = g * 16 + (lane & 7) + ((lane >> 4) << 3);
                int ch = ks*2 + ((lane >> 3) & 1);
                LDSM_X4(r4, ksB + sw_off(n, ch));
                uint32_t b0[2] = {r4[0], r4[1]};
                uint32_t b1[2] = {r4[2], r4[3]};
                MMA_F16(sc[g*2    ], af, b0);
                MMA_F16(sc[g*2 + 1], af, b1);
            }
        }
        // scale 1/sqrt(64)
        #pragma unroll
        for (int nb = 0; nb < 8; nb++)
            #pragma unroll
            for (int v = 0; v < 4; v++) sc[nb][v] *= 0.125f;

        // ---- causal mask ----
        if (k0 + 63 > q0 + wq) {
            #pragma unroll
            for (int nb = 0; nb < 8; nb++) {
                int c0 = k0 + nb*8 + qlc*2;
                if (c0     > row0    ) sc[nb][0] = -1e30f;
                if (c0 + 1 > row0    ) sc[nb][1] = -1e30f;
                if (c0     > row0 + 8) sc[nb][2] = -1e30f;
                if (c0 + 1 > row0 + 8) sc[nb][3] = -1e30f;
            }
        }

        // ---- online softmax ----
        float mx0 = sc[0][0], mx1 = sc[0][2];
        #pragma unroll
        for (int nb = 0; nb < 8; nb++) {
            mx0 = fmaxf(mx0, fmaxf(sc[nb][0], sc[nb][1]));
            mx1 = fmaxf(mx1, fmaxf(sc[nb][2], sc[nb][3]));
        }
        mx0 = fmaxf(mx0, __shfl_xor_sync(0xffffffffu, mx0, 1));
        mx0 = fmaxf(mx0, __shfl_xor_sync(0xffffffffu, mx0, 2));
        mx1 = fmaxf(mx1, __shfl_xor_sync(0xffffffffu, mx1, 1));
        mx1 = fmaxf(mx1, __shfl_xor_sync(0xffffffffu, mx1, 2));
        float nm0 = fmaxf(m0, mx0), nm1 = fmaxf(m1, mx1);
        float corr0 = fast_exp(m0 - nm0), corr1 = fast_exp(m1 - nm1);
        float s0 = 0.f, s1 = 0.f;
        #pragma unroll
        for (int nb = 0; nb < 8; nb++) {
            sc[nb][0] = fast_exp(sc[nb][0] - nm0);
            sc[nb][1] = fast_exp(sc[nb][1] - nm0);
            sc[nb][2] = fast_exp(sc[nb][2] - nm1);
            sc[nb][3] = fast_exp(sc[nb][3] - nm1);
            s0 += sc[nb][0] + sc[nb][1];
            s1 += sc[nb][2] + sc[nb][3];
        }
        s0 += __shfl_xor_sync(0xffffffffu, s0, 1);
        s0 += __shfl_xor_sync(0xffffffffu, s0, 2);
        s1 += __shfl_xor_sync(0xffffffffu, s1, 1);
        s1 += __shfl_xor_sync(0xffffffffu, s1, 2);
        l0 = l0 * corr0 + s0;  m0 = nm0;
        l1 = l1 * corr1 + s1;  m1 = nm1;
        #pragma unroll
        for (int nb = 0; nb < 8; nb++) {
            o[nb][0] *= corr0; o[nb][1] *= corr0;
            o[nb][2] *= corr1; o[nb][3] *= corr1;
        }

        // ---- P frags -> Ps (fp16, swizzled), warp-local ----
        {
            int pr = wq + qtr;
            #pragma unroll
            for (int nb = 0; nb < 8; nb++) {
                int pc = nb*8 + qlc*2;
                uint32_t off0 = (uint32_t)(pr * 128 + (((pc >> 3) ^ (pr & 7)) << 4) + (pc & 7) * 2);
                *(__half2*)(sm8 + 40960 + off0) = __floats2half2_rn(sc[nb][0], sc[nb][1]);
                int pr1 = pr + 8;
                uint32_t off1 = (uint32_t)(pr1 * 128 + (((pc >> 3) ^ (pr1 & 7)) << 4) + (pc & 7) * 2);
                *(__half2*)(sm8 + 40960 + off1) = __floats2half2_rn(sc[nb][2], sc[nb][3]);
            }
        }

        __syncthreads();      // all warps' V_i scatter visible before PV

        // ---- P @ V (fp16 k16) on vt[s] ----
        uint32_t vtB = qsB + vtOff[s];
        #pragma unroll
        for (int ks = 0; ks < 4; ks++) {
            uint32_t pa[4];
            LDSM_X4(pa, psB + sw_off(wq + (lane & 15), ks*2 + (lane >> 4)));
            #pragma unroll
            for (int g = 0; g < 4; g++) {
                uint32_t r4[4];
                int n = g * 16 + (lane & 7) + ((lane >> 4) << 3);
                int ch = ks*2 + ((lane >> 3) & 1);
                LDSM_X4(r4, vtB + sw_off(n, ch));
                uint32_t b0[2] = {r4[0], r4[1]};
                uint32_t b1[2] = {r4[2], r4[3]};
                MMA_F16(o[g*2    ], pa, b0);
                MMA_F16(o[g*2 + 1], pa, b1);
            }
        }
    }

    // fp16 output (feeds proj GEMM A)
    float inv0 = 1.0f / l0, inv1 = 1.0f / l1;
    size_t g0 = (size_t)(b*SEQ + q0 + wq + qtr) * DMODEL + h*HDIM;
    size_t g1 = g0 + 8 * DMODEL;
    #pragma unroll
    for (int nb = 0; nb < 8; nb++) {
        int d0 = nb*8 + qlc*2;
        *(__half2*)(y + g0 + d0) = __floats2half2_rn(o[nb][0]*inv0, o[nb][1]*inv0);
        *(__half2*)(y + g1 + d0) = __floats2half2_rn(o[nb][2]*inv1, o[nb][3]*inv1);
    }
}

// ---------------- loss reduce over fused partials ----------------------------
__global__ void __launch_bounds__(256) rowloss2_k(const float* __restrict__ pm,
                                                  const float* __restrict__ ps,
                                                  const float* __restrict__ logits,
                                                  const int* __restrict__ tgt,
                                                  float* __restrict__ rowloss)
{
    int n = blockIdx.x;
    const float* rm = pm + (size_t)n * PCOLS;
    const float* rs = ps + (size_t)n * PCOLS;
    float m = -1e30f, ssum = 0.f;
    for (int i = threadIdx.x; i < PCOLS; i += 256) {
        float m2 = rm[i], s2 = rs[i];
        float M = fmaxf(m, m2);
        ssum = ssum*fast_exp(m - M) + s2*fast_exp(m2 - M);
        m = M;
    }
    #pragma unroll
    for (int o = 16; o; o >>= 1) {
        float m2 = __shfl_xor_sync(0xffffffffu, m, o);
        float s2 = __shfl_xor_sync(0xffffffffu, ssum, o);
        float M  = fmaxf(m, m2);
        ssum = ssum*fast_exp(m - M) + s2*fast_exp(m2 - M);
        m = M;
    }
    __shared__ float smm[8], sms[8];
    int wid = threadIdx.x >> 5;
    if ((threadIdx.x & 31) == 0) { smm[wid] = m; sms[wid] = ssum; }
    __syncthreads();
    if (threadIdx.x == 0) {
        float M = smm[0], S = sms[0];
        for (int i = 1; i < 8; i++) {
            float M2 = fmaxf(M, smm[i]);
            S = S*fast_exp(M - M2) + sms[i]*fast_exp(smm[i] - M2);
            M = M2;
        }
        float lse = M + logf(S);
        rowloss[n] = lse - logits[(size_t)n * VOCAB + tgt[n]];
    }
}

__global__ void finalize_k(const float* __restrict__ rowloss, float* __restrict__ out_loss)
{
    float s = 0.f;
    for (int i = threadIdx.x; i < NTOK; i += 256) s += rowloss[i];
    #pragma unroll
    for (int o = 16; o; o >>= 1) s += __shfl_xor_sync(0xffffffffu, s, o);
    __shared__ float sm[8];
    int wid = threadIdx.x >> 5;
    if ((threadIdx.x & 31) == 0) sm[wid] = s;
    __syncthreads();
    if (threadIdx.x == 0) {
        float t = 0.f;
        for (int i = 0; i < 8; i++) t += sm[i];
        *out_loss = t * (1.0f/NTOK);
    }
}

// ---------------- launch -----------------------------------------------------
extern "C" void kernel_launch(void* const* d_in, const int* in_sizes, int n_in,
                              void* d_out, int out_size)
{
    const int*   idx     = (const int*)  d_in[0];
    const int*   targets = (const int*)  d_in[1];
    const float* wte     = (const float*)d_in[2];
    const float* wpe     = (const float*)d_in[3];
    const float* ln1_w   = (const float*)d_in[4];
    const float* ln1_b   = (const float*)d_in[5];
    const float* attn_w  = (const float*)d_in[6];
    const float* attn_b  = (const float*)d_in[7];
    const float* proj_w  = (const float*)d_in[8];
    const float* proj_b  = (const float*)d_in[9];
    const float* ln2_w   = (const float*)d_in[10];
    const float* ln2_b   = (const float*)d_in[11];
    const float* fc_w    = (const float*)d_in[12];
    const float* fc_b    = (const float*)d_in[13];
    const float* fcp_w   = (const float*)d_in[14];
    const float* fcp_b   = (const float*)d_in[15];
    const float* lnf_w   = (const float*)d_in[16];
    const float* lnf_b   = (const float*)d_in[17];

    float *px, *ppart, *plogfb, *prl, *ppm, *pps;
    __half *ph, *pqkv, *patt, *pffn, *pwq, *pwp, *pwf, *pwf2, *pwv;
    cudaGetSymbolAddress((void**)&px,    g_x);
    cudaGetSymbolAddress((void**)&ph,    g_h);
    cudaGetSymbolAddress((void**)&pqkv,  g_qkv);
    cudaGetSymbolAddress((void**)&patt,  g_att);
    cudaGetSymbolAddress((void**)&pffn,  g_ffn);
    cudaGetSymbolAddress((void**)&ppart, g_part);
    cudaGetSymbolAddress((void**)&plogfb,g_logits_fallback);
    cudaGetSymbolAddress((void**)&prl,   g_rowloss);
    cudaGetSymbolAddress((void**)&ppm,   g_pm);
    cudaGetSymbolAddress((void**)&pps,   g_ps);
    cudaGetSymbolAddress((void**)&pwq,   g_wq);
    cudaGetSymbolAddress((void**)&pwp,   g_wp);
    cudaGetSymbolAddress((void**)&pwf,   g_wf);
    cudaGetSymbolAddress((void**)&pwf2,  g_wf2);
    cudaGetSymbolAddress((void**)&pwv,   g_wv);

    static bool attr_done = false;
    if (!attr_done) {
        cudaFuncSetAttribute((const void*)gemm_tc<EPI_HALF,0>,  cudaFuncAttributeMaxDynamicSharedMemorySize, GT_SMEM);
        cudaFuncSetAttribute((const void*)gemm_tc<EPI_GELU,0>,  cudaFuncAttributeMaxDynamicSharedMemorySize, GT_SMEM);
        cudaFuncSetAttribute((const void*)gemm_tc<EPI_PART,0>,  cudaFuncAttributeMaxDynamicSharedMemorySize, GT_SMEM);
        cudaFuncSetAttribute((const void*)gemm_tc<EPI_LOSS,1>,  cudaFuncAttributeMaxDynamicSharedMemorySize, GT_SMEM);
        cudaFuncSetAttribute((const void*)attn_k, cudaFuncAttributeMaxDynamicSharedMemorySize, AT_SMEM);
        attr_done = true;
    }

    const long long LOGN = (long long)NTOK * VOCAB;
    float* logits_ptr;
    float* loss_ptr = nullptr;
    if ((long long)out_size >= LOGN) {
        logits_ptr = (float*)d_out;
        if ((long long)out_size > LOGN) loss_ptr = (float*)d_out + LOGN;
    } else {
        logits_ptr = plogfb;
        loss_ptr = (float*)d_out;
    }

    // weight fp32->fp16 conversion (per launch)
    {
        long long nq  = (long long)LAYERS*3*DMODEL*DMODEL/4;
        long long np  = (long long)LAYERS*DMODEL*DMODEL/4;
        long long nf  = (long long)LAYERS*4*DMODEL*DMODEL/4;
        long long nv  = (long long)VOCAB*DMODEL/4;
        cvt_half_k<<<(int)((nq+255)/256), 256>>>(attn_w, pwq, (int)nq);
        cvt_half_k<<<(int)((np+255)/256), 256>>>(proj_w, pwp, (int)np);
        cvt_half_k<<<(int)((nf+255)/256), 256>>>(fc_w,  pwf,  (int)nf);
        cvt_half_k<<<(int)((nf+255)/256), 256>>>(fcp_w, pwf2, (int)nf);
        cvt_half_k<<<(int)((nv+255)/256), 256>>>(wte,   pwv,  (int)nv);
    }

    embed_ln_k<<<NTOK, 256>>>(idx, wte, wpe, ln1_w, ln1_b, px, ph);

    dim3 gq (3*DMODEL/128, NTOK/128);       // 24 x 16
    dim3 gp2(DMODEL/128,   NTOK/128, 2);    //  8 x 16 x 2 (split-K)
    dim3 gf (4*DMODEL/128, NTOK/128);       // 32 x 16
    dim3 gv (NTOK/128, NVTILE);             // SWAP: x=M-tiles, y=N-tiles
    dim3 ga (SEQ/64, BATCH*NHEAD);

    for (int l = 0; l < LAYERS; l++) {
        gemm_tc<EPI_HALF,0><<<gq, 256, GT_SMEM>>>(ph, pwq + (size_t)l*3*DMODEL*DMODEL,
                                       attn_b + (size_t)l*3*DMODEL,
                                       (float*)pqkv, NTOK, 3*DMODEL, DMODEL, nullptr, nullptr);
        attn_k<<<ga, 128, AT_SMEM>>>(pqkv, patt);
        gemm_tc<EPI_PART,0><<<gp2, 256, GT_SMEM>>>(patt, pwp + (size_t)l*DMODEL*DMODEL,
                                        nullptr,
                                        ppart, NTOK, DMODEL, DMODEL, nullptr, nullptr);
        splitk_ln_k<<<NTOK, 256>>>(ppart, proj_b + (size_t)l*DMODEL, px,
                                   ln2_w + (size_t)l*DMODEL, ln2_b + (size_t)l*DMODEL, ph);
        gemm_tc<EPI_GELU,0><<<gf, 256, GT_SMEM>>>(ph, pwf + (size_t)l*4*DMODEL*DMODEL,
                                       fc_b + (size_t)l*4*DMODEL,
                                       (float*)pffn, NTOK, 4*DMODEL, DMODEL, nullptr, nullptr);
        gemm_tc<EPI_PART,0><<<gp2, 256, GT_SMEM>>>(pffn, pwf2 + (size_t)l*DMODEL*4*DMODEL,
                                        nullptr,
                                        ppart, NTOK, DMODEL, 4*DMODEL, nullptr, nullptr);
        const float* nw = (l + 1 < LAYERS) ? ln1_w + (size_t)(l+1)*DMODEL : lnf_w;
        const float* nb = (l + 1 < LAYERS) ? ln1_b + (size_t)(l+1)*DMODEL : lnf_b;
        splitk_ln_k<<<NTOK, 256>>>(ppart, fcp_b + (size_t)l*DMODEL, px, nw, nb, ph);
    }

    gemm_tc<EPI_LOSS,1><<<gv, 256, GT_SMEM>>>(ph, pwv, nullptr,
                                   logits_ptr, NTOK, VOCAB, DMODEL, ppm, pps);

    if (loss_ptr) {
        rowloss2_k<<<NTOK, 256>>>(ppm, pps, logits_ptr, targets, prl);
        finalize_k<<<1, 256>>>(prl, loss_ptr);
    }
}